// round 10
// baseline (speedup 1.0000x reference)
#include <cuda_runtime.h>
#include <cuda_bf16.h>
#include <math.h>
#include <cstdint>

// ---------------- problem constants ----------------
#define E_   2
#define HQ_  16
#define HK_  8
#define HD_  128
#define DIM_ 2048
#define BS_  2
#define SEQ_ 2048
#define NTOK (BS_*SEQ_)          // 4096
#define EPS_ 1e-6f
#define SCALE_ 0.08838834764831845f   // 1/sqrt(128)

typedef __nv_bfloat16 bf16;

// ---------------- scratch (device globals) ----------------
__device__ float g_v [NTOK * (HK_*HD_)];
__device__ float g_o [NTOK * DIM_];
__device__ int   g_perm[NTOK];
__device__ int   g_c0;

// bf16 split buffers
__device__ bf16 g_xh [NTOK*DIM_],      g_xl [NTOK*DIM_];
__device__ bf16 g_wqh[E_*DIM_*HQ_*HD_], g_wql[E_*DIM_*HQ_*HD_];
__device__ bf16 g_wkh[E_*DIM_*HK_*HD_], g_wkl[E_*DIM_*HK_*HD_];
__device__ bf16 g_wvh[E_*DIM_*HK_*HD_], g_wvl[E_*DIM_*HK_*HD_];
__device__ bf16 g_woh[E_*DIM_*HQ_*HD_], g_wol[E_*DIM_*HQ_*HD_];
__device__ bf16 g_qh [NTOK*(HQ_*HD_)],  g_ql [NTOK*(HQ_*HD_)];
__device__ bf16 g_kh [NTOK*(HK_*HD_)],  g_kl [NTOK*(HK_*HD_)];
__device__ bf16 g_vth[NTOK*(HK_*HD_)],  g_vtl[NTOK*(HK_*HD_)];   // [b][kvh][d][seq]
__device__ bf16 g_aoh[NTOK*(HQ_*HD_)],  g_aol[NTOK*(HQ_*HD_)];

// =============================== helpers ===============================
__device__ __forceinline__ uint32_t smem_u32(const void* p) {
    uint32_t a;
    asm("{ .reg .u64 t; cvta.to.shared.u64 t, %1; cvt.u32.u64 %0, t; }" : "=r"(a) : "l"(p));
    return a;
}
#define CP_ASYNC16(dst, src) \
    asm volatile("cp.async.cg.shared.global [%0], [%1], 16;" :: "r"(dst), "l"(src) : "memory")
#define CP_COMMIT() asm volatile("cp.async.commit_group;" ::: "memory")
template<int N> __device__ __forceinline__ void cp_wait() {
    asm volatile("cp.async.wait_group %0;" :: "n"(N) : "memory");
}
#define LDSM4(r0,r1,r2,r3, addr) \
    asm volatile("ldmatrix.sync.aligned.m8n8.x4.shared.b16 {%0,%1,%2,%3}, [%4];" \
        : "=r"(r0), "=r"(r1), "=r"(r2), "=r"(r3) : "r"(addr))

__device__ __forceinline__ void bsplit(float x, uint16_t& h, uint16_t& l) {
    bf16 bh = __float2bfloat16_rn(x);
    h = __bfloat16_as_ushort(bh);
    l = __bfloat16_as_ushort(__float2bfloat16_rn(x - __bfloat162float(bh)));
}
__device__ __forceinline__ uint32_t packb(uint16_t lo_elem, uint16_t hi_elem) {
    return (uint32_t)lo_elem | ((uint32_t)hi_elem << 16);
}
__device__ __forceinline__ void mma16816(float* c, const uint32_t* a, const uint32_t* b) {
    asm volatile("mma.sync.aligned.m16n8k16.row.col.f32.bf16.bf16.f32 "
        "{%0,%1,%2,%3}, {%4,%5,%6,%7}, {%8,%9}, {%0,%1,%2,%3};"
        : "+f"(c[0]), "+f"(c[1]), "+f"(c[2]), "+f"(c[3])
        : "r"(a[0]), "r"(a[1]), "r"(a[2]), "r"(a[3]), "r"(b[0]), "r"(b[1]));
}
__device__ __forceinline__ uint32_t sw256(int r, int off) {
    return (uint32_t)(r*256 + (off ^ ((r & 7) << 4)));
}
// 64-byte rows (V tiles, kv=32): conflict-free for 8-row ldmatrix + cp.async fill
__device__ __forceinline__ uint32_t sw64(int r, int clog) {
    return (uint32_t)(r*64 + ((clog ^ (r >> 1)) & 3)*16);
}

// ============================================================================
// sort tokens by modality (stable counting sort), deterministic
// ============================================================================
__global__ __launch_bounds__(1024) void sort_tokens(const int* __restrict__ mod)
{
    __shared__ int s[1024];
    const int tid = threadIdx.x;
    int m[4]; int cnt = 0;
#pragma unroll
    for (int u = 0; u < 4; u++) { m[u] = mod[tid*4 + u]; cnt += (m[u] == 0); }
    s[tid] = cnt;
    __syncthreads();
    for (int off = 1; off < 1024; off <<= 1) {
        int v = (tid >= off) ? s[tid - off] : 0;
        __syncthreads();
        s[tid] += v;
        __syncthreads();
    }
    const int c0 = s[1023];
    if (tid == 0) g_c0 = c0;
    int r0 = s[tid] - cnt;
#pragma unroll
    for (int u = 0; u < 4; u++) {
        int g = tid*4 + u;
        if (m[u] == 0) { g_perm[r0] = g; r0++; }
        else           { g_perm[c0 + g - r0] = g; }
    }
}

// ============================================================================
// elementwise fp32 -> bf16 hi/lo split (for x)
// ============================================================================
__global__ __launch_bounds__(256) void split_f32(
    const float* __restrict__ in, bf16* __restrict__ hi, bf16* __restrict__ lo, int n4)
{
    int i = blockIdx.x * 256 + threadIdx.x;
    if (i >= n4) return;
    float4 v = ((const float4*)in)[i];
    uint16_t hx,lx,hy,ly,hz,lz,hw,lw;
    bsplit(v.x,hx,lx); bsplit(v.y,hy,ly); bsplit(v.z,hz,lz); bsplit(v.w,hw,lw);
    ((uint2*)hi)[i] = make_uint2(packb(hx,hy), packb(hz,hw));
    ((uint2*)lo)[i] = make_uint2(packb(lx,ly), packb(lz,lw));
}

// ============================================================================
// weight transpose-split: W [e][K][NC] fp32 -> T [e][NC][K] bf16 hi/lo
// ============================================================================
__global__ __launch_bounds__(256) void wtrans_split(
    const float* __restrict__ W, bf16* __restrict__ Th, bf16* __restrict__ Tl,
    int K, int NC)
{
    __shared__ float t[32][33];
    const int e  = blockIdx.z;
    const int k0 = blockIdx.x * 32, n0 = blockIdx.y * 32;
    const int tx = threadIdx.x & 31, ty = threadIdx.x >> 5;
    const float* Wp = W + (size_t)e * K * NC;
    for (int r = ty; r < 32; r += 8)
        t[r][tx] = Wp[(size_t)(k0 + r) * NC + n0 + tx];
    __syncthreads();
    bf16* th = Th + (size_t)e * NC * K;
    bf16* tl = Tl + (size_t)e * NC * K;
    for (int r = ty; r < 32; r += 8) {
        float v = t[tx][r];
        uint16_t h, l; bsplit(v, h, l);
        size_t o = (size_t)(n0 + r) * K + k0 + tx;
        th[o] = __ushort_as_bfloat16(h);
        tl[o] = __ushort_as_bfloat16(l);
    }
}

// ============================================================================
// V transpose-split: g_v fp32 [b*2048+s][kvh*128+d] -> Vt [b][kvh][d][seq] hi/lo
// ============================================================================
__global__ __launch_bounds__(256) void vtrans_split(
    const float* __restrict__ V, bf16* __restrict__ Th, bf16* __restrict__ Tl)
{
    __shared__ float t[32][33];
    const int s0 = blockIdx.x * 32, d0 = blockIdx.y * 32;
    const int z  = blockIdx.z;                 // b*8 + kvh
    const int b  = z >> 3, kvh = z & 7;
    const int tx = threadIdx.x & 31, ty = threadIdx.x >> 5;
    for (int r = ty; r < 32; r += 8)
        t[r][tx] = V[(size_t)(b*SEQ_ + s0 + r) * (HK_*HD_) + kvh*HD_ + d0 + tx];
    __syncthreads();
    for (int r = ty; r < 32; r += 8) {
        float v = t[tx][r];
        uint16_t h, l; bsplit(v, h, l);
        size_t o = (size_t)(z*HD_ + d0 + r) * SEQ_ + s0 + tx;
        Th[o] = __ushort_as_bfloat16(h);
        Tl[o] = __ushort_as_bfloat16(l);
    }
}

// ============================================================================
// bf16x2 mma.sync GEMM over expert-sorted rows, ldmatrix fragment loads.
// (unchanged — protected win)
// ============================================================================
#define MM_STAGE 40960          // Ah 10240 | Al | Bh | Bl
#define MM_DSMEM (2*MM_STAGE)

template<int MODE>
__global__ __launch_bounds__(128) void mm_bf16(
    const bf16* __restrict__ Ah, const bf16* __restrict__ Al,
    const bf16* __restrict__ Bh, const bf16* __restrict__ Bl,
    float* __restrict__ Cf,
    bf16* __restrict__ Ch, bf16* __restrict__ Cl,
    const float* __restrict__ normw,
    const float* __restrict__ fcos, const float* __restrict__ fsin,
    int K, int NC)
{
    extern __shared__ char sm[];
    __shared__ int sPerm[128];
    __shared__ float sred[4][64];
    const int tid  = threadIdx.x;
    const int lane = tid & 31;
    const int w    = tid >> 5;
    const int wm64 = (w & 1) * 64;
    const int wn64 = (w >> 1) * 64;
    const int bn   = blockIdx.x * 128;
    const int by   = blockIdx.y;

    const int c0 = g_c0;
    const int T0 = (c0 + 127) >> 7;
    const int T1 = (NTOK - c0 + 127) >> 7;
    if (by >= T0 + T1) return;
    const int e       = (by < T0) ? 0 : 1;
    const int rowbase = e ? (c0 + (by - T0) * 128) : (by * 128);
    const int limit   = e ? NTOK : c0;
    const size_t bofs = (size_t)e * NC * K + (size_t)bn * K;

    {
        int gs = rowbase + tid;
        sPerm[tid] = g_perm[gs < NTOK ? gs : (NTOK - 1)];
    }
    __syncthreads();

    const uint32_t sb = smem_u32(sm);

    auto load_chunk = [&](int cc, int p) {
        const int k0 = cc * 32;
        const uint32_t base = sb + p * MM_STAGE;
#pragma unroll
        for (int i = 0; i < 8; i++) {
            int idx = tid + (i << 7);
            int comp = idx >> 9, rem = idx & 511;
            int r = rem >> 2, c = rem & 3;
            const bf16* src = (comp ? Al : Ah) + (size_t)sPerm[r] * K + k0 + c * 8;
            CP_ASYNC16(base + comp*10240 + (uint32_t)(r*80 + c*16), src);
        }
#pragma unroll
        for (int i = 0; i < 8; i++) {
            int idx = tid + (i << 7);
            int comp = idx >> 9, rem = idx & 511;
            int r = rem >> 2, c = rem & 3;
            const bf16* src = (comp ? Bl : Bh) + bofs + (size_t)r * K + k0 + c * 8;
            CP_ASYNC16(base + 20480 + comp*10240 + (uint32_t)(r*80 + c*16), src);
        }
    };

    float acc[4][8][4];
#pragma unroll
    for (int i = 0; i < 4; i++)
#pragma unroll
        for (int j = 0; j < 8; j++)
#pragma unroll
            for (int q = 0; q < 4; q++) acc[i][j][q] = 0.f;

    const int NCH = K / 32;
    load_chunk(0, 0); CP_COMMIT();
    load_chunk(1, 1); CP_COMMIT();

    const int lr = lane >> 2;
    const int lc = lane & 3;
    const int g8  = lane & 7;
    const int grp = lane >> 3;
    const int a_row = wm64 + (grp & 1) * 8 + g8;
    const int a_ofx = (grp >> 1) * 16;
    const int b_row = wn64 + (grp >> 1) * 8 + g8;
    const int b_ofx = (grp & 1) * 16;

    for (int c = 0; c < NCH; c++) {
        cp_wait<1>();
        __syncthreads();
        const uint32_t bb = sb + (c & 1) * MM_STAGE;
#pragma unroll
        for (int ks = 0; ks < 2; ks++) {
            const uint32_t koff = (uint32_t)(ks * 32);
            uint32_t fah[4][4], fal[4][4];
#pragma unroll
            for (int i = 0; i < 4; i++) {
                uint32_t aaddr = bb + (uint32_t)((a_row + i*16) * 80) + koff + a_ofx;
                LDSM4(fah[i][0], fah[i][1], fah[i][2], fah[i][3], aaddr);
                LDSM4(fal[i][0], fal[i][1], fal[i][2], fal[i][3], aaddr + 10240);
            }
            uint32_t fbh4[4][4], fbl4[4][4];
#pragma unroll
            for (int jj = 0; jj < 4; jj++) {
                uint32_t baddr = bb + 20480 + (uint32_t)((b_row + jj*16) * 80) + koff + b_ofx;
                LDSM4(fbh4[jj][0], fbh4[jj][1], fbh4[jj][2], fbh4[jj][3], baddr);
                LDSM4(fbl4[jj][0], fbl4[jj][1], fbl4[jj][2], fbl4[jj][3], baddr + 10240);
            }
#pragma unroll
            for (int jj = 0; jj < 4; jj++) {
#pragma unroll
                for (int half = 0; half < 2; half++) {
                    const int j = jj*2 + half;
                    uint32_t fbh[2] = { fbh4[jj][half*2], fbh4[jj][half*2+1] };
                    uint32_t fbl[2] = { fbl4[jj][half*2], fbl4[jj][half*2+1] };
#pragma unroll
                    for (int i = 0; i < 4; i++) {
                        mma16816(acc[i][j], fah[i], fbh);
                        mma16816(acc[i][j], fal[i], fbh);
                        mma16816(acc[i][j], fah[i], fbl);
                    }
                }
            }
        }
        __syncthreads();
        if (c + 2 < NCH) load_chunk(c + 2, c & 1);
        CP_COMMIT();
    }

    if (MODE == 0) {
#pragma unroll
        for (int i = 0; i < 4; i++) {
            int lr0 = wm64 + i * 16 + lr;
            bool v0 = (rowbase + lr0)     < limit;
            bool v1 = (rowbase + lr0 + 8) < limit;
            int t0 = v0 ? sPerm[lr0]     : 0;
            int t1 = v1 ? sPerm[lr0 + 8] : 0;
#pragma unroll
            for (int j = 0; j < 8; j++) {
                int cb = bn + wn64 + j * 8 + (lc << 1);
                if (v0) *(float2*)&Cf[(size_t)t0 * NC + cb] = make_float2(acc[i][j][0], acc[i][j][1]);
                if (v1) *(float2*)&Cf[(size_t)t1 * NC + cb] = make_float2(acc[i][j][2], acc[i][j][3]);
            }
        }
    } else {
        float rs[4][2];
#pragma unroll
        for (int i = 0; i < 4; i++) {
            float s0 = 0.f, s1 = 0.f;
#pragma unroll
            for (int j = 0; j < 8; j++) {
                s0 += acc[i][j][0]*acc[i][j][0] + acc[i][j][1]*acc[i][j][1];
                s1 += acc[i][j][2]*acc[i][j][2] + acc[i][j][3]*acc[i][j][3];
            }
            rs[i][0] = s0; rs[i][1] = s1;
        }
#pragma unroll
        for (int i = 0; i < 4; i++) {
#pragma unroll
            for (int hh = 0; hh < 2; hh++) {
                rs[i][hh] += __shfl_xor_sync(0xffffffffu, rs[i][hh], 1);
                rs[i][hh] += __shfl_xor_sync(0xffffffffu, rs[i][hh], 2);
            }
        }
        if (lc == 0) {
#pragma unroll
            for (int i = 0; i < 4; i++) {
                sred[w][i*16 + lr]     = rs[i][0];
                sred[w][i*16 + 8 + lr] = rs[i][1];
            }
        }
        __syncthreads();
        float rinv[4][2];
#pragma unroll
        for (int i = 0; i < 4; i++) {
            float t0 = rs[i][0] + sred[w ^ 2][i*16 + lr];
            float t1 = rs[i][1] + sred[w ^ 2][i*16 + 8 + lr];
            rinv[i][0] = rsqrtf(t0 * (1.0f/HD_) + EPS_);
            rinv[i][1] = rsqrtf(t1 * (1.0f/HD_) + EPS_);
        }
#pragma unroll
        for (int i = 0; i < 4; i++) {
            const int lr0 = wm64 + i * 16 + lr;
            const bool v0 = (rowbase + lr0)     < limit;
            const bool v1 = (rowbase + lr0 + 8) < limit;
            const int t0 = sPerm[lr0], t1 = sPerm[lr0 + 8];
            const int s0 = t0 & (SEQ_-1), s1 = t1 & (SEQ_-1);
#pragma unroll
            for (int j = 0; j < 8; j++) {
                const int col0 = wn64 + j*8 + (lc << 1);
                const float2 nw = *(const float2*)&normw[e*HD_ + col0];
                const int cp = col0 >> 1;
                if (v0) {
                    float a0 = acc[i][j][0] * rinv[i][0] * nw.x;
                    float a1 = acc[i][j][1] * rinv[i][0] * nw.y;
                    float cc = fcos[s0*(HD_/2) + cp], sn = fsin[s0*(HD_/2) + cp];
                    float e0 = a0*cc - a1*sn, e1 = a0*sn + a1*cc;
                    uint16_t h0,l0,h1,l1;
                    bsplit(e0,h0,l0); bsplit(e1,h1,l1);
                    size_t off = (size_t)t0 * NC + bn + col0;
                    *(uint32_t*)((char*)Ch + 2*off) = packb(h0,h1);
                    *(uint32_t*)((char*)Cl + 2*off) = packb(l0,l1);
                }
                if (v1) {
                    float a0 = acc[i][j][2] * rinv[i][1] * nw.x;
                    float a1 = acc[i][j][3] * rinv[i][1] * nw.y;
                    float cc = fcos[s1*(HD_/2) + cp], sn = fsin[s1*(HD_/2) + cp];
                    float e0 = a0*cc - a1*sn, e1 = a0*sn + a1*cc;
                    uint16_t h0,l0,h1,l1;
                    bsplit(e0,h0,l0); bsplit(e1,h1,l1);
                    size_t off = (size_t)t1 * NC + bn + col0;
                    *(uint32_t*)((char*)Ch + 2*off) = packb(h0,h1);
                    *(uint32_t*)((char*)Cl + 2*off) = packb(l0,l1);
                }
            }
        }
    }
}

// ============================================================================
// Tensor-core causal flash attention (bf16x2), ldmatrix, 64-row CTAs.
// Adds warp-uniform rescale skip (bit-identical: skipped path <=> c==1.0).
// ============================================================================
#define FQ_H 0
#define FQ_L 16384
#define FK(p) (32768 + (p)*16384)
#define FV(p) (65536 + (p)*16384)
#define FA_BYTES 98304

__global__ __launch_bounds__(128) void flash_attn(
    const bf16* __restrict__ Qh, const bf16* __restrict__ Ql,
    const bf16* __restrict__ Kh, const bf16* __restrict__ Kl,
    const bf16* __restrict__ Vth, const bf16* __restrict__ Vtl,
    bf16* __restrict__ AOh, bf16* __restrict__ AOl)
{
    extern __shared__ char sm[];
    const int tid  = threadIdx.x;
    const int lane = tid & 31;
    const int w    = tid >> 5;      // 0..3
    const int lr   = lane >> 2;
    const int lc   = lane & 3;
    const int g8   = lane & 7;
    const int grp  = lane >> 3;

    const int qt = 31 - blockIdx.x;      // big tiles first
    const int h  = blockIdx.y;
    const int b  = blockIdx.z;
    const int kvh   = h >> 1;
    const int qbase = qt * 64;
    const int m0    = w * 16;
    const int niter = 2 * qt + 2;        // kv tiles of 32

    const uint32_t sb = smem_u32(sm);

    const int q_row  = m0 + (grp & 1) * 8 + g8;
    const int q_ofx  = (grp >> 1) * 16;
    const int kv_row = (grp >> 1) * 8 + g8;
    const int kv_ofx = (grp & 1) * 16;
    const int v_clog = grp & 1;

    // ---- Q load (hi+lo) ----
#pragma unroll
    for (int i = 0; i < 16; i++) {
        int idx = tid + (i << 7);
        int comp = idx >> 10, rem = idx & 1023;
        int r = rem >> 4, c = rem & 15;
        const bf16* src = (comp ? Ql : Qh)
            + (size_t)(b*SEQ_ + qbase + r)*(HQ_*HD_) + h*HD_ + c*8;
        CP_ASYNC16(sb + (comp ? FQ_L : FQ_H) + sw256(r, c*16), src);
    }
    CP_COMMIT();

    auto load_k = [&](int kt, int p) {
#pragma unroll
        for (int i = 0; i < 8; i++) {
            int idx = tid + (i << 7);
            int comp = idx >> 9, rem = idx & 511;
            int r = rem >> 4, c = rem & 15;
            const bf16* src = (comp ? Kl : Kh)
                + (size_t)(b*SEQ_ + kt*32 + r)*(HK_*HD_) + kvh*HD_ + c*8;
            CP_ASYNC16(sb + FK(p) + comp*8192 + sw256(r, c*16), src);
        }
        CP_COMMIT();
    };
    auto load_v = [&](int kt, int p) {
#pragma unroll
        for (int i = 0; i < 8; i++) {
            int idx = tid + (i << 7);
            int comp = idx >> 9, rem = idx & 511;
            int r = rem >> 2, c = rem & 3;
            const bf16* src = (comp ? Vtl : Vth)
                + (size_t)((b*HK_ + kvh)*HD_ + r)*SEQ_ + kt*32 + c*8;
            CP_ASYNC16(sb + FV(p) + comp*8192 + sw64(r, c), src);
        }
        CP_COMMIT();
    };

    load_k(0, 0);
    load_v(0, 0);

    float o[16][4];
#pragma unroll
    for (int j = 0; j < 16; j++)
#pragma unroll
        for (int q = 0; q < 4; q++) o[j][q] = 0.f;
    float mr0 = -1e30f, mr1 = -1e30f, lr0s = 0.f, lr1s = 0.f;

    const int row0g = qbase + m0 + lr;

    for (int kt = 0; kt < niter; kt++) {
        const int p = kt & 1;
        cp_wait<1>();
        __syncthreads();
        if (kt + 1 < niter) { load_k(kt + 1, p ^ 1); load_v(kt + 1, p ^ 1); }

        const uint32_t kh_b = sb + FK(p);
        const uint32_t kl_b = kh_b + 8192;

        // ---- S = Q K^T (bf16x2, ldmatrix), n=32 ----
        float sa[4][4];
#pragma unroll
        for (int j = 0; j < 4; j++)
#pragma unroll
            for (int q = 0; q < 4; q++) sa[j][q] = 0.f;
#pragma unroll
        for (int s = 0; s < 8; s++) {
            const int b0 = s*32;
            uint32_t fqh[4], fql[4];
            uint32_t qaddr = sb + FQ_H + sw256(q_row, b0 + q_ofx);
            LDSM4(fqh[0], fqh[1], fqh[2], fqh[3], qaddr);
            LDSM4(fql[0], fql[1], fql[2], fql[3], qaddr + 16384);
#pragma unroll
            for (int jj = 0; jj < 2; jj++) {
                uint32_t fkh4[4], fkl4[4];
                uint32_t kaddr = sw256(kv_row + jj*16, b0 + kv_ofx);
                LDSM4(fkh4[0], fkh4[1], fkh4[2], fkh4[3], kh_b + kaddr);
                LDSM4(fkl4[0], fkl4[1], fkl4[2], fkl4[3], kl_b + kaddr);
#pragma unroll
                for (int half = 0; half < 2; half++) {
                    const int j = jj*2 + half;
                    uint32_t fkh[2] = { fkh4[half*2], fkh4[half*2+1] };
                    uint32_t fkl[2] = { fkl4[half*2], fkl4[half*2+1] };
                    mma16816(sa[j], fqh, fkh);
                    mma16816(sa[j], fql, fkh);
                    mma16816(sa[j], fqh, fkl);
                }
            }
        }

        // ---- online softmax ----
        const bool need_mask = (kt*32 + 31 > qbase + m0);
        float mx0 = -1e30f, mx1 = -1e30f;
#pragma unroll
        for (int j = 0; j < 4; j++) {
            const int cb = kt*32 + j*8 + 2*lc;
#pragma unroll
            for (int q = 0; q < 4; q++) {
                float v = sa[j][q] * SCALE_;
                if (need_mask) {
                    int col = cb + (q & 1);
                    int row = (q < 2) ? row0g : (row0g + 8);
                    if (col > row) v = -1e30f;
                }
                sa[j][q] = v;
            }
            mx0 = fmaxf(mx0, fmaxf(sa[j][0], sa[j][1]));
            mx1 = fmaxf(mx1, fmaxf(sa[j][2], sa[j][3]));
        }
        mx0 = fmaxf(mx0, __shfl_xor_sync(0xffffffffu, mx0, 1));
        mx0 = fmaxf(mx0, __shfl_xor_sync(0xffffffffu, mx0, 2));
        mx1 = fmaxf(mx1, __shfl_xor_sync(0xffffffffu, mx1, 1));
        mx1 = fmaxf(mx1, __shfl_xor_sync(0xffffffffu, mx1, 2));
        const float mn0 = fmaxf(mr0, mx0);
        const float mn1 = fmaxf(mr1, mx1);
        float ps0 = 0.f, ps1 = 0.f;
#pragma unroll
        for (int j = 0; j < 4; j++) {
            sa[j][0] = __expf(sa[j][0] - mn0);
            sa[j][1] = __expf(sa[j][1] - mn0);
            sa[j][2] = __expf(sa[j][2] - mn1);
            sa[j][3] = __expf(sa[j][3] - mn1);
            ps0 += sa[j][0] + sa[j][1];
            ps1 += sa[j][2] + sa[j][3];
        }
        ps0 += __shfl_xor_sync(0xffffffffu, ps0, 1);
        ps0 += __shfl_xor_sync(0xffffffffu, ps0, 2);
        ps1 += __shfl_xor_sync(0xffffffffu, ps1, 1);
        ps1 += __shfl_xor_sync(0xffffffffu, ps1, 2);

        // warp-uniform rescale skip: skipped path is exactly c==1.0
        const bool upd = (mx0 > mr0) || (mx1 > mr1);
        if (__any_sync(0xffffffffu, upd)) {
            const float c0 = __expf(mr0 - mn0);
            const float c1 = __expf(mr1 - mn1);
            lr0s = lr0s * c0 + ps0;
            lr1s = lr1s * c1 + ps1;
#pragma unroll
            for (int j = 0; j < 16; j++) {
                o[j][0] *= c0; o[j][1] *= c0;
                o[j][2] *= c1; o[j][3] *= c1;
            }
        } else {
            lr0s += ps0;
            lr1s += ps1;
        }
        mr0 = mn0; mr1 = mn1;

        // ---- P frags directly from registers (S C-frag == PV A-frag) ----
        uint32_t aph[2][4], apl[2][4];
#pragma unroll
        for (int t = 0; t < 2; t++) {
            uint16_t h0,l0,h1,l1;
            bsplit(sa[2*t][0],h0,l0);   bsplit(sa[2*t][1],h1,l1);
            aph[t][0] = packb(h0,h1);   apl[t][0] = packb(l0,l1);
            bsplit(sa[2*t][2],h0,l0);   bsplit(sa[2*t][3],h1,l1);
            aph[t][1] = packb(h0,h1);   apl[t][1] = packb(l0,l1);
            bsplit(sa[2*t+1][0],h0,l0); bsplit(sa[2*t+1][1],h1,l1);
            aph[t][2] = packb(h0,h1);   apl[t][2] = packb(l0,l1);
            bsplit(sa[2*t+1][2],h0,l0); bsplit(sa[2*t+1][3],h1,l1);
            aph[t][3] = packb(h0,h1);   apl[t][3] = packb(l0,l1);
        }

        // ---- V ready ----
        if (kt + 1 < niter) cp_wait<2>(); else cp_wait<0>();
        __syncthreads();
        const uint32_t vh_b = sb + FV(p);
        const uint32_t vl_b = vh_b + 8192;

        // ---- O += P V (bf16x2, ldmatrix over 64B-row V tiles) ----
#pragma unroll
        for (int t = 0; t < 2; t++) {
#pragma unroll
            for (int jp = 0; jp < 8; jp++) {
                uint32_t fvh4[4], fvl4[4];
                uint32_t vaddr = sw64(kv_row + jp*16, 2*t + v_clog);
                LDSM4(fvh4[0], fvh4[1], fvh4[2], fvh4[3], vh_b + vaddr);
                LDSM4(fvl4[0], fvl4[1], fvl4[2], fvl4[3], vl_b + vaddr);
#pragma unroll
                for (int half = 0; half < 2; half++) {
                    const int j = jp*2 + half;
                    uint32_t fvh[2] = { fvh4[half*2], fvh4[half*2+1] };
                    uint32_t fvl[2] = { fvl4[half*2], fvl4[half*2+1] };
                    mma16816(o[j], aph[t], fvh);
                    mma16816(o[j], apl[t], fvh);
                    mma16816(o[j], aph[t], fvl);
                }
            }
        }
    }

    // ---- normalize + split-store AO ----
    const float i0 = 1.f / lr0s;
    const float i1 = 1.f / lr1s;
    const size_t t0 = (size_t)(b*SEQ_ + row0g);
    const size_t t1 = t0 + 8;
#pragma unroll
    for (int j = 0; j < 16; j++) {
        const int col = h*HD_ + j*8 + 2*lc;
        uint16_t h0,l0,h1,l1;
        bsplit(o[j][0]*i0, h0, l0); bsplit(o[j][1]*i0, h1, l1);
        size_t off0 = t0*(HQ_*HD_) + col;
        *(uint32_t*)((char*)AOh + 2*off0) = packb(h0, h1);
        *(uint32_t*)((char*)AOl + 2*off0) = packb(l0, l1);
        bsplit(o[j][2]*i1, h0, l0); bsplit(o[j][3]*i1, h1, l1);
        size_t off1 = t1*(HQ_*HD_) + col;
        *(uint32_t*)((char*)AOh + 2*off1) = packb(h0, h1);
        *(uint32_t*)((char*)AOl + 2*off1) = packb(l0, l1);
    }
}

// ============================================================================
// Final per-token RMSNorm over DIM with attn_norm_w[expert]
// ============================================================================
__global__ __launch_bounds__(256) void final_rms(
    const float* __restrict__ in, const float* __restrict__ w,
    const int* __restrict__ mod, float* __restrict__ out)
{
    const int n = blockIdx.x;
    const int tid = threadIdx.x;
    const int e = mod[n];
    const float* row = in + (size_t)n*DIM_;
    float vals[8];
    float ss = 0.f;
#pragma unroll
    for (int u = 0; u < 8; u++) {
        float v = row[tid + u*256];
        vals[u] = v;
        ss += v*v;
    }
#pragma unroll
    for (int o = 16; o > 0; o >>= 1) ss += __shfl_xor_sync(0xffffffffu, ss, o);
    __shared__ float wsum[8];
    if ((tid & 31) == 0) wsum[tid >> 5] = ss;
    __syncthreads();
    float tot = 0.f;
#pragma unroll
    for (int i = 0; i < 8; i++) tot += wsum[i];
    float r = rsqrtf(tot * (1.0f/DIM_) + EPS_);
#pragma unroll
    for (int u = 0; u < 8; u++)
        out[(size_t)n*DIM_ + tid + u*256] = vals[u] * r * w[e*DIM_ + tid + u*256];
}

// ============================================================================
// launch — reordered so launch index 5 (ncu -s 5 -c 1) is the Q GEMM
// ============================================================================
extern "C" void kernel_launch(void* const* d_in, const int* in_sizes, int n_in,
                              void* d_out, int out_size)
{
    const float* x    = (const float*)d_in[0];
    const float* fcos = (const float*)d_in[1];
    const float* fsin = (const float*)d_in[2];
    const float* wq   = (const float*)d_in[3];
    const float* wk   = (const float*)d_in[4];
    const float* wv   = (const float*)d_in[5];
    const float* wo   = (const float*)d_in[6];
    const float* qnw  = (const float*)d_in[7];
    const float* knw  = (const float*)d_in[8];
    const float* anw  = (const float*)d_in[9];
    const int*   mod  = (const int*)d_in[10];
    float* out = (float*)d_out;

    float *pv, *po;
    bf16 *pxh, *pxl, *pwqh, *pwql, *pwkh, *pwkl, *pwvh, *pwvl, *pwoh, *pwol;
    bf16 *pqh, *pql, *pkh, *pkl, *pvth, *pvtl, *paoh, *paol;
    cudaGetSymbolAddress((void**)&pv,  g_v);
    cudaGetSymbolAddress((void**)&po,  g_o);
    cudaGetSymbolAddress((void**)&pxh, g_xh);  cudaGetSymbolAddress((void**)&pxl, g_xl);
    cudaGetSymbolAddress((void**)&pwqh, g_wqh); cudaGetSymbolAddress((void**)&pwql, g_wql);
    cudaGetSymbolAddress((void**)&pwkh, g_wkh); cudaGetSymbolAddress((void**)&pwkl, g_wkl);
    cudaGetSymbolAddress((void**)&pwvh, g_wvh); cudaGetSymbolAddress((void**)&pwvl, g_wvl);
    cudaGetSymbolAddress((void**)&pwoh, g_woh); cudaGetSymbolAddress((void**)&pwol, g_wol);
    cudaGetSymbolAddress((void**)&pqh, g_qh);   cudaGetSymbolAddress((void**)&pql, g_ql);
    cudaGetSymbolAddress((void**)&pkh, g_kh);   cudaGetSymbolAddress((void**)&pkl, g_kl);
    cudaGetSymbolAddress((void**)&pvth, g_vth); cudaGetSymbolAddress((void**)&pvtl, g_vtl);
    cudaGetSymbolAddress((void**)&paoh, g_aoh); cudaGetSymbolAddress((void**)&paol, g_aol);

    cudaFuncSetAttribute(flash_attn, cudaFuncAttributeMaxDynamicSharedMemorySize, FA_BYTES);
    cudaFuncSetAttribute(mm_bf16<0>, cudaFuncAttributeMaxDynamicSharedMemorySize, MM_DSMEM);
    cudaFuncSetAttribute(mm_bf16<1>, cudaFuncAttributeMaxDynamicSharedMemorySize, MM_DSMEM);

    // launches 0..4: preprocessing needed before the Q GEMM
    sort_tokens<<<1, 1024>>>(mod);                                            // 0
    split_f32<<<(NTOK*DIM_/4 + 255)/256, 256>>>(x, pxh, pxl, NTOK*DIM_/4);    // 1
    wtrans_split<<<dim3(64, 64, 2), 256>>>(wq, pwqh, pwql, DIM_, HQ_*HD_);    // 2
    wtrans_split<<<dim3(64, 32, 2), 256>>>(wk, pwkh, pwkl, DIM_, HK_*HD_);    // 3
    wtrans_split<<<dim3(64, 32, 2), 256>>>(wv, pwvh, pwvl, DIM_, HK_*HD_);    // 4

    // launch 5: Q projection GEMM  <-- profiled by ncu (-s 5 -c 1)
    mm_bf16<1><<<dim3(16, 33), 128, MM_DSMEM>>>(pxh, pxl, pwqh, pwql,
        nullptr, pqh, pql, qnw, fcos, fsin, DIM_, HQ_*HD_);                   // 5
    mm_bf16<1><<<dim3( 8, 33), 128, MM_DSMEM>>>(pxh, pxl, pwkh, pwkl,
        nullptr, pkh, pkl, knw, fcos, fsin, DIM_, HK_*HD_);                   // 6
    mm_bf16<0><<<dim3( 8, 33), 128, MM_DSMEM>>>(pxh, pxl, pwvh, pwvl,
        pv, nullptr, nullptr, nullptr, nullptr, nullptr, DIM_, HK_*HD_);      // 7
    vtrans_split<<<dim3(64, 4, 16), 256>>>(pv, pvth, pvtl);                   // 8
    wtrans_split<<<dim3(64, 64, 2), 256>>>(wo, pwoh, pwol, HQ_*HD_, DIM_);    // 9

    // attention
    flash_attn<<<dim3(32, HQ_, BS_), 128, FA_BYTES>>>(pqh, pql, pkh, pkl, pvth, pvtl, paoh, paol);

    // output projection + final rmsnorm
    mm_bf16<0><<<dim3(16, 33), 128, MM_DSMEM>>>(paoh, paol, pwoh, pwol,
        po, nullptr, nullptr, nullptr, nullptr, nullptr, HQ_*HD_, DIM_);
    final_rms<<<NTOK, 256>>>(po, anw, mod, out);
}

// round 11
// speedup vs baseline: 1.0368x; 1.0368x over previous
#include <cuda_runtime.h>
#include <cuda_bf16.h>
#include <math.h>
#include <cstdint>

// ---------------- problem constants ----------------
#define E_   2
#define HQ_  16
#define HK_  8
#define HD_  128
#define DIM_ 2048
#define BS_  2
#define SEQ_ 2048
#define NTOK (BS_*SEQ_)          // 4096
#define EPS_ 1e-6f
#define SCALE_ 0.08838834764831845f   // 1/sqrt(128)

typedef __nv_bfloat16 bf16;

// ---------------- scratch (device globals) ----------------
__device__ float g_v [NTOK * (HK_*HD_)];
__device__ float g_o [NTOK * DIM_];
__device__ int   g_perm[NTOK];
__device__ int   g_c0;

// bf16 split buffers
__device__ bf16 g_xh [NTOK*DIM_],      g_xl [NTOK*DIM_];
__device__ bf16 g_wqh[E_*DIM_*HQ_*HD_], g_wql[E_*DIM_*HQ_*HD_];
__device__ bf16 g_wkh[E_*DIM_*HK_*HD_], g_wkl[E_*DIM_*HK_*HD_];
__device__ bf16 g_wvh[E_*DIM_*HK_*HD_], g_wvl[E_*DIM_*HK_*HD_];
__device__ bf16 g_woh[E_*DIM_*HQ_*HD_], g_wol[E_*DIM_*HQ_*HD_];
__device__ bf16 g_qh [NTOK*(HQ_*HD_)],  g_ql [NTOK*(HQ_*HD_)];
__device__ bf16 g_kh [NTOK*(HK_*HD_)],  g_kl [NTOK*(HK_*HD_)];
__device__ bf16 g_vth[NTOK*(HK_*HD_)],  g_vtl[NTOK*(HK_*HD_)];   // [b][kvh][d][seq]
__device__ bf16 g_aoh[NTOK*(HQ_*HD_)],  g_aol[NTOK*(HQ_*HD_)];

// =============================== helpers ===============================
__device__ __forceinline__ uint32_t smem_u32(const void* p) {
    uint32_t a;
    asm("{ .reg .u64 t; cvta.to.shared.u64 t, %1; cvt.u32.u64 %0, t; }" : "=r"(a) : "l"(p));
    return a;
}
#define CP_ASYNC16(dst, src) \
    asm volatile("cp.async.cg.shared.global [%0], [%1], 16;" :: "r"(dst), "l"(src) : "memory")
#define CP_COMMIT() asm volatile("cp.async.commit_group;" ::: "memory")
template<int N> __device__ __forceinline__ void cp_wait() {
    asm volatile("cp.async.wait_group %0;" :: "n"(N) : "memory");
}
#define LDSM4(r0,r1,r2,r3, addr) \
    asm volatile("ldmatrix.sync.aligned.m8n8.x4.shared.b16 {%0,%1,%2,%3}, [%4];" \
        : "=r"(r0), "=r"(r1), "=r"(r2), "=r"(r3) : "r"(addr))

__device__ __forceinline__ void bsplit(float x, uint16_t& h, uint16_t& l) {
    bf16 bh = __float2bfloat16_rn(x);
    h = __bfloat16_as_ushort(bh);
    l = __bfloat16_as_ushort(__float2bfloat16_rn(x - __bfloat162float(bh)));
}
__device__ __forceinline__ uint32_t packb(uint16_t lo_elem, uint16_t hi_elem) {
    return (uint32_t)lo_elem | ((uint32_t)hi_elem << 16);
}
__device__ __forceinline__ void mma16816(float* c, const uint32_t* a, const uint32_t* b) {
    asm volatile("mma.sync.aligned.m16n8k16.row.col.f32.bf16.bf16.f32 "
        "{%0,%1,%2,%3}, {%4,%5,%6,%7}, {%8,%9}, {%0,%1,%2,%3};"
        : "+f"(c[0]), "+f"(c[1]), "+f"(c[2]), "+f"(c[3])
        : "r"(a[0]), "r"(a[1]), "r"(a[2]), "r"(a[3]), "r"(b[0]), "r"(b[1]));
}
__device__ __forceinline__ uint32_t sw256(int r, int off) {
    return (uint32_t)(r*256 + (off ^ ((r & 7) << 4)));
}
// 64-byte rows (V tiles, kv=32): conflict-free for 8-row ldmatrix + cp.async fill
__device__ __forceinline__ uint32_t sw64(int r, int clog) {
    return (uint32_t)(r*64 + ((clog ^ (r >> 1)) & 3)*16);
}

// ============================================================================
// sort tokens by modality (stable counting sort), deterministic
// ============================================================================
__global__ __launch_bounds__(1024) void sort_tokens(const int* __restrict__ mod)
{
    __shared__ int s[1024];
    const int tid = threadIdx.x;
    int m[4]; int cnt = 0;
#pragma unroll
    for (int u = 0; u < 4; u++) { m[u] = mod[tid*4 + u]; cnt += (m[u] == 0); }
    s[tid] = cnt;
    __syncthreads();
    for (int off = 1; off < 1024; off <<= 1) {
        int v = (tid >= off) ? s[tid - off] : 0;
        __syncthreads();
        s[tid] += v;
        __syncthreads();
    }
    const int c0 = s[1023];
    if (tid == 0) g_c0 = c0;
    int r0 = s[tid] - cnt;
#pragma unroll
    for (int u = 0; u < 4; u++) {
        int g = tid*4 + u;
        if (m[u] == 0) { g_perm[r0] = g; r0++; }
        else           { g_perm[c0 + g - r0] = g; }
    }
}

// ============================================================================
// elementwise fp32 -> bf16 hi/lo split (for x)
// ============================================================================
__global__ __launch_bounds__(256) void split_f32(
    const float* __restrict__ in, bf16* __restrict__ hi, bf16* __restrict__ lo, int n4)
{
    int i = blockIdx.x * 256 + threadIdx.x;
    if (i >= n4) return;
    float4 v = ((const float4*)in)[i];
    uint16_t hx,lx,hy,ly,hz,lz,hw,lw;
    bsplit(v.x,hx,lx); bsplit(v.y,hy,ly); bsplit(v.z,hz,lz); bsplit(v.w,hw,lw);
    ((uint2*)hi)[i] = make_uint2(packb(hx,hy), packb(hz,hw));
    ((uint2*)lo)[i] = make_uint2(packb(lx,ly), packb(lz,lw));
}

// ============================================================================
// weight transpose-split: W [e][K][NC] fp32 -> T [e][NC][K] bf16 hi/lo
// ============================================================================
__global__ __launch_bounds__(256) void wtrans_split(
    const float* __restrict__ W, bf16* __restrict__ Th, bf16* __restrict__ Tl,
    int K, int NC)
{
    __shared__ float t[32][33];
    const int e  = blockIdx.z;
    const int k0 = blockIdx.x * 32, n0 = blockIdx.y * 32;
    const int tx = threadIdx.x & 31, ty = threadIdx.x >> 5;
    const float* Wp = W + (size_t)e * K * NC;
    for (int r = ty; r < 32; r += 8)
        t[r][tx] = Wp[(size_t)(k0 + r) * NC + n0 + tx];
    __syncthreads();
    bf16* th = Th + (size_t)e * NC * K;
    bf16* tl = Tl + (size_t)e * NC * K;
    for (int r = ty; r < 32; r += 8) {
        float v = t[tx][r];
        uint16_t h, l; bsplit(v, h, l);
        size_t o = (size_t)(n0 + r) * K + k0 + tx;
        th[o] = __ushort_as_bfloat16(h);
        tl[o] = __ushort_as_bfloat16(l);
    }
}

// ============================================================================
// V transpose-split: g_v fp32 [b*2048+s][kvh*128+d] -> Vt [b][kvh][d][seq] hi/lo
// ============================================================================
__global__ __launch_bounds__(256) void vtrans_split(
    const float* __restrict__ V, bf16* __restrict__ Th, bf16* __restrict__ Tl)
{
    __shared__ float t[32][33];
    const int s0 = blockIdx.x * 32, d0 = blockIdx.y * 32;
    const int z  = blockIdx.z;                 // b*8 + kvh
    const int b  = z >> 3, kvh = z & 7;
    const int tx = threadIdx.x & 31, ty = threadIdx.x >> 5;
    for (int r = ty; r < 32; r += 8)
        t[r][tx] = V[(size_t)(b*SEQ_ + s0 + r) * (HK_*HD_) + kvh*HD_ + d0 + tx];
    __syncthreads();
    for (int r = ty; r < 32; r += 8) {
        float v = t[tx][r];
        uint16_t h, l; bsplit(v, h, l);
        size_t o = (size_t)(z*HD_ + d0 + r) * SEQ_ + s0 + tx;
        Th[o] = __ushort_as_bfloat16(h);
        Tl[o] = __ushort_as_bfloat16(l);
    }
}

// ============================================================================
// bf16x2 mma.sync GEMM over expert-sorted rows, ldmatrix fragment loads.
// (unchanged — protected win)
// ============================================================================
#define MM_STAGE 40960          // Ah 10240 | Al | Bh | Bl
#define MM_DSMEM (2*MM_STAGE)

template<int MODE>
__global__ __launch_bounds__(128) void mm_bf16(
    const bf16* __restrict__ Ah, const bf16* __restrict__ Al,
    const bf16* __restrict__ Bh, const bf16* __restrict__ Bl,
    float* __restrict__ Cf,
    bf16* __restrict__ Ch, bf16* __restrict__ Cl,
    const float* __restrict__ normw,
    const float* __restrict__ fcos, const float* __restrict__ fsin,
    int K, int NC)
{
    extern __shared__ char sm[];
    __shared__ int sPerm[128];
    __shared__ float sred[4][64];
    const int tid  = threadIdx.x;
    const int lane = tid & 31;
    const int w    = tid >> 5;
    const int wm64 = (w & 1) * 64;
    const int wn64 = (w >> 1) * 64;
    const int bn   = blockIdx.x * 128;
    const int by   = blockIdx.y;

    const int c0 = g_c0;
    const int T0 = (c0 + 127) >> 7;
    const int T1 = (NTOK - c0 + 127) >> 7;
    if (by >= T0 + T1) return;
    const int e       = (by < T0) ? 0 : 1;
    const int rowbase = e ? (c0 + (by - T0) * 128) : (by * 128);
    const int limit   = e ? NTOK : c0;
    const size_t bofs = (size_t)e * NC * K + (size_t)bn * K;

    {
        int gs = rowbase + tid;
        sPerm[tid] = g_perm[gs < NTOK ? gs : (NTOK - 1)];
    }
    __syncthreads();

    const uint32_t sb = smem_u32(sm);

    auto load_chunk = [&](int cc, int p) {
        const int k0 = cc * 32;
        const uint32_t base = sb + p * MM_STAGE;
#pragma unroll
        for (int i = 0; i < 8; i++) {
            int idx = tid + (i << 7);
            int comp = idx >> 9, rem = idx & 511;
            int r = rem >> 2, c = rem & 3;
            const bf16* src = (comp ? Al : Ah) + (size_t)sPerm[r] * K + k0 + c * 8;
            CP_ASYNC16(base + comp*10240 + (uint32_t)(r*80 + c*16), src);
        }
#pragma unroll
        for (int i = 0; i < 8; i++) {
            int idx = tid + (i << 7);
            int comp = idx >> 9, rem = idx & 511;
            int r = rem >> 2, c = rem & 3;
            const bf16* src = (comp ? Bl : Bh) + bofs + (size_t)r * K + k0 + c * 8;
            CP_ASYNC16(base + 20480 + comp*10240 + (uint32_t)(r*80 + c*16), src);
        }
    };

    float acc[4][8][4];
#pragma unroll
    for (int i = 0; i < 4; i++)
#pragma unroll
        for (int j = 0; j < 8; j++)
#pragma unroll
            for (int q = 0; q < 4; q++) acc[i][j][q] = 0.f;

    const int NCH = K / 32;
    load_chunk(0, 0); CP_COMMIT();
    load_chunk(1, 1); CP_COMMIT();

    const int lr = lane >> 2;
    const int lc = lane & 3;
    const int g8  = lane & 7;
    const int grp = lane >> 3;
    const int a_row = wm64 + (grp & 1) * 8 + g8;
    const int a_ofx = (grp >> 1) * 16;
    const int b_row = wn64 + (grp >> 1) * 8 + g8;
    const int b_ofx = (grp & 1) * 16;

    for (int c = 0; c < NCH; c++) {
        cp_wait<1>();
        __syncthreads();
        const uint32_t bb = sb + (c & 1) * MM_STAGE;
#pragma unroll
        for (int ks = 0; ks < 2; ks++) {
            const uint32_t koff = (uint32_t)(ks * 32);
            uint32_t fah[4][4], fal[4][4];
#pragma unroll
            for (int i = 0; i < 4; i++) {
                uint32_t aaddr = bb + (uint32_t)((a_row + i*16) * 80) + koff + a_ofx;
                LDSM4(fah[i][0], fah[i][1], fah[i][2], fah[i][3], aaddr);
                LDSM4(fal[i][0], fal[i][1], fal[i][2], fal[i][3], aaddr + 10240);
            }
            uint32_t fbh4[4][4], fbl4[4][4];
#pragma unroll
            for (int jj = 0; jj < 4; jj++) {
                uint32_t baddr = bb + 20480 + (uint32_t)((b_row + jj*16) * 80) + koff + b_ofx;
                LDSM4(fbh4[jj][0], fbh4[jj][1], fbh4[jj][2], fbh4[jj][3], baddr);
                LDSM4(fbl4[jj][0], fbl4[jj][1], fbl4[jj][2], fbl4[jj][3], baddr + 10240);
            }
#pragma unroll
            for (int jj = 0; jj < 4; jj++) {
#pragma unroll
                for (int half = 0; half < 2; half++) {
                    const int j = jj*2 + half;
                    uint32_t fbh[2] = { fbh4[jj][half*2], fbh4[jj][half*2+1] };
                    uint32_t fbl[2] = { fbl4[jj][half*2], fbl4[jj][half*2+1] };
#pragma unroll
                    for (int i = 0; i < 4; i++) {
                        mma16816(acc[i][j], fah[i], fbh);
                        mma16816(acc[i][j], fal[i], fbh);
                        mma16816(acc[i][j], fah[i], fbl);
                    }
                }
            }
        }
        __syncthreads();
        if (c + 2 < NCH) load_chunk(c + 2, c & 1);
        CP_COMMIT();
    }

    if (MODE == 0) {
#pragma unroll
        for (int i = 0; i < 4; i++) {
            int lr0 = wm64 + i * 16 + lr;
            bool v0 = (rowbase + lr0)     < limit;
            bool v1 = (rowbase + lr0 + 8) < limit;
            int t0 = v0 ? sPerm[lr0]     : 0;
            int t1 = v1 ? sPerm[lr0 + 8] : 0;
#pragma unroll
            for (int j = 0; j < 8; j++) {
                int cb = bn + wn64 + j * 8 + (lc << 1);
                if (v0) *(float2*)&Cf[(size_t)t0 * NC + cb] = make_float2(acc[i][j][0], acc[i][j][1]);
                if (v1) *(float2*)&Cf[(size_t)t1 * NC + cb] = make_float2(acc[i][j][2], acc[i][j][3]);
            }
        }
    } else {
        float rs[4][2];
#pragma unroll
        for (int i = 0; i < 4; i++) {
            float s0 = 0.f, s1 = 0.f;
#pragma unroll
            for (int j = 0; j < 8; j++) {
                s0 += acc[i][j][0]*acc[i][j][0] + acc[i][j][1]*acc[i][j][1];
                s1 += acc[i][j][2]*acc[i][j][2] + acc[i][j][3]*acc[i][j][3];
            }
            rs[i][0] = s0; rs[i][1] = s1;
        }
#pragma unroll
        for (int i = 0; i < 4; i++) {
#pragma unroll
            for (int hh = 0; hh < 2; hh++) {
                rs[i][hh] += __shfl_xor_sync(0xffffffffu, rs[i][hh], 1);
                rs[i][hh] += __shfl_xor_sync(0xffffffffu, rs[i][hh], 2);
            }
        }
        if (lc == 0) {
#pragma unroll
            for (int i = 0; i < 4; i++) {
                sred[w][i*16 + lr]     = rs[i][0];
                sred[w][i*16 + 8 + lr] = rs[i][1];
            }
        }
        __syncthreads();
        float rinv[4][2];
#pragma unroll
        for (int i = 0; i < 4; i++) {
            float t0 = rs[i][0] + sred[w ^ 2][i*16 + lr];
            float t1 = rs[i][1] + sred[w ^ 2][i*16 + 8 + lr];
            rinv[i][0] = rsqrtf(t0 * (1.0f/HD_) + EPS_);
            rinv[i][1] = rsqrtf(t1 * (1.0f/HD_) + EPS_);
        }
#pragma unroll
        for (int i = 0; i < 4; i++) {
            const int lr0 = wm64 + i * 16 + lr;
            const bool v0 = (rowbase + lr0)     < limit;
            const bool v1 = (rowbase + lr0 + 8) < limit;
            const int t0 = sPerm[lr0], t1 = sPerm[lr0 + 8];
            const int s0 = t0 & (SEQ_-1), s1 = t1 & (SEQ_-1);
#pragma unroll
            for (int j = 0; j < 8; j++) {
                const int col0 = wn64 + j*8 + (lc << 1);
                const float2 nw = *(const float2*)&normw[e*HD_ + col0];
                const int cp = col0 >> 1;
                if (v0) {
                    float a0 = acc[i][j][0] * rinv[i][0] * nw.x;
                    float a1 = acc[i][j][1] * rinv[i][0] * nw.y;
                    float cc = fcos[s0*(HD_/2) + cp], sn = fsin[s0*(HD_/2) + cp];
                    float e0 = a0*cc - a1*sn, e1 = a0*sn + a1*cc;
                    uint16_t h0,l0,h1,l1;
                    bsplit(e0,h0,l0); bsplit(e1,h1,l1);
                    size_t off = (size_t)t0 * NC + bn + col0;
                    *(uint32_t*)((char*)Ch + 2*off) = packb(h0,h1);
                    *(uint32_t*)((char*)Cl + 2*off) = packb(l0,l1);
                }
                if (v1) {
                    float a0 = acc[i][j][2] * rinv[i][1] * nw.x;
                    float a1 = acc[i][j][3] * rinv[i][1] * nw.y;
                    float cc = fcos[s1*(HD_/2) + cp], sn = fsin[s1*(HD_/2) + cp];
                    float e0 = a0*cc - a1*sn, e1 = a0*sn + a1*cc;
                    uint16_t h0,l0,h1,l1;
                    bsplit(e0,h0,l0); bsplit(e1,h1,l1);
                    size_t off = (size_t)t1 * NC + bn + col0;
                    *(uint32_t*)((char*)Ch + 2*off) = packb(h0,h1);
                    *(uint32_t*)((char*)Cl + 2*off) = packb(l0,l1);
                }
            }
        }
    }
}

// ============================================================================
// Tensor-core causal flash attention (bf16x2), ldmatrix, 64-row CTAs.
// Q fragments hoisted to registers (loop-invariant); unconditional rescale.
// ============================================================================
#define FQ_H 0
#define FQ_L 16384
#define FK(p) (32768 + (p)*16384)
#define FV(p) (65536 + (p)*16384)
#define FA_BYTES 98304

__global__ __launch_bounds__(128) void flash_attn(
    const bf16* __restrict__ Qh, const bf16* __restrict__ Ql,
    const bf16* __restrict__ Kh, const bf16* __restrict__ Kl,
    const bf16* __restrict__ Vth, const bf16* __restrict__ Vtl,
    bf16* __restrict__ AOh, bf16* __restrict__ AOl)
{
    extern __shared__ char sm[];
    const int tid  = threadIdx.x;
    const int lane = tid & 31;
    const int w    = tid >> 5;      // 0..3
    const int lr   = lane >> 2;
    const int lc   = lane & 3;
    const int g8   = lane & 7;
    const int grp  = lane >> 3;

    const int qt = 31 - blockIdx.x;      // big tiles first
    const int h  = blockIdx.y;
    const int b  = blockIdx.z;
    const int kvh   = h >> 1;
    const int qbase = qt * 64;
    const int m0    = w * 16;
    const int niter = 2 * qt + 2;        // kv tiles of 32

    const uint32_t sb = smem_u32(sm);

    const int q_row  = m0 + (grp & 1) * 8 + g8;
    const int q_ofx  = (grp >> 1) * 16;
    const int kv_row = (grp >> 1) * 8 + g8;
    const int kv_ofx = (grp & 1) * 16;
    const int v_clog = grp & 1;

    // ---- Q load (hi+lo), group 0 ----
#pragma unroll
    for (int i = 0; i < 16; i++) {
        int idx = tid + (i << 7);
        int comp = idx >> 10, rem = idx & 1023;
        int r = rem >> 4, c = rem & 15;
        const bf16* src = (comp ? Ql : Qh)
            + (size_t)(b*SEQ_ + qbase + r)*(HQ_*HD_) + h*HD_ + c*8;
        CP_ASYNC16(sb + (comp ? FQ_L : FQ_H) + sw256(r, c*16), src);
    }
    CP_COMMIT();

    auto load_k = [&](int kt, int p) {
#pragma unroll
        for (int i = 0; i < 8; i++) {
            int idx = tid + (i << 7);
            int comp = idx >> 9, rem = idx & 511;
            int r = rem >> 4, c = rem & 15;
            const bf16* src = (comp ? Kl : Kh)
                + (size_t)(b*SEQ_ + kt*32 + r)*(HK_*HD_) + kvh*HD_ + c*8;
            CP_ASYNC16(sb + FK(p) + comp*8192 + sw256(r, c*16), src);
        }
        CP_COMMIT();
    };
    auto load_v = [&](int kt, int p) {
#pragma unroll
        for (int i = 0; i < 8; i++) {
            int idx = tid + (i << 7);
            int comp = idx >> 9, rem = idx & 511;
            int r = rem >> 2, c = rem & 3;
            const bf16* src = (comp ? Vtl : Vth)
                + (size_t)((b*HK_ + kvh)*HD_ + r)*SEQ_ + kt*32 + c*8;
            CP_ASYNC16(sb + FV(p) + comp*8192 + sw64(r, c), src);
        }
        CP_COMMIT();
    };

    load_k(0, 0);     // group 1
    load_v(0, 0);     // group 2

    // ---- Q fragments: hoisted out of the kv loop (loop-invariant) ----
    cp_wait<2>();     // Q group complete (K0/V0 still in flight)
    __syncthreads();
    uint32_t qfh[8][4], qfl[8][4];
#pragma unroll
    for (int s = 0; s < 8; s++) {
        uint32_t qaddr = sb + FQ_H + sw256(q_row, s*32 + q_ofx);
        LDSM4(qfh[s][0], qfh[s][1], qfh[s][2], qfh[s][3], qaddr);
        LDSM4(qfl[s][0], qfl[s][1], qfl[s][2], qfl[s][3], qaddr + 16384);
    }

    float o[16][4];
#pragma unroll
    for (int j = 0; j < 16; j++)
#pragma unroll
        for (int q = 0; q < 4; q++) o[j][q] = 0.f;
    float mr0 = -1e30f, mr1 = -1e30f, lr0s = 0.f, lr1s = 0.f;

    const int row0g = qbase + m0 + lr;

    for (int kt = 0; kt < niter; kt++) {
        const int p = kt & 1;
        cp_wait<1>();
        __syncthreads();
        if (kt + 1 < niter) { load_k(kt + 1, p ^ 1); load_v(kt + 1, p ^ 1); }

        const uint32_t kh_b = sb + FK(p);
        const uint32_t kl_b = kh_b + 8192;

        // ---- S = Q K^T (bf16x2, ldmatrix), n=32 ----
        float sa[4][4];
#pragma unroll
        for (int j = 0; j < 4; j++)
#pragma unroll
            for (int q = 0; q < 4; q++) sa[j][q] = 0.f;
#pragma unroll
        for (int s = 0; s < 8; s++) {
            const int b0 = s*32;
#pragma unroll
            for (int jj = 0; jj < 2; jj++) {
                uint32_t fkh4[4], fkl4[4];
                uint32_t kaddr = sw256(kv_row + jj*16, b0 + kv_ofx);
                LDSM4(fkh4[0], fkh4[1], fkh4[2], fkh4[3], kh_b + kaddr);
                LDSM4(fkl4[0], fkl4[1], fkl4[2], fkl4[3], kl_b + kaddr);
#pragma unroll
                for (int half = 0; half < 2; half++) {
                    const int j = jj*2 + half;
                    uint32_t fkh[2] = { fkh4[half*2], fkh4[half*2+1] };
                    uint32_t fkl[2] = { fkl4[half*2], fkl4[half*2+1] };
                    mma16816(sa[j], qfh[s], fkh);
                    mma16816(sa[j], qfl[s], fkh);
                    mma16816(sa[j], qfh[s], fkl);
                }
            }
        }

        // ---- online softmax (unconditional rescale) ----
        const bool need_mask = (kt*32 + 31 > qbase + m0);
        float mx0 = -1e30f, mx1 = -1e30f;
#pragma unroll
        for (int j = 0; j < 4; j++) {
            const int cb = kt*32 + j*8 + 2*lc;
#pragma unroll
            for (int q = 0; q < 4; q++) {
                float v = sa[j][q] * SCALE_;
                if (need_mask) {
                    int col = cb + (q & 1);
                    int row = (q < 2) ? row0g : (row0g + 8);
                    if (col > row) v = -1e30f;
                }
                sa[j][q] = v;
            }
            mx0 = fmaxf(mx0, fmaxf(sa[j][0], sa[j][1]));
            mx1 = fmaxf(mx1, fmaxf(sa[j][2], sa[j][3]));
        }
        mx0 = fmaxf(mx0, __shfl_xor_sync(0xffffffffu, mx0, 1));
        mx0 = fmaxf(mx0, __shfl_xor_sync(0xffffffffu, mx0, 2));
        mx1 = fmaxf(mx1, __shfl_xor_sync(0xffffffffu, mx1, 1));
        mx1 = fmaxf(mx1, __shfl_xor_sync(0xffffffffu, mx1, 2));
        const float mn0 = fmaxf(mr0, mx0);
        const float mn1 = fmaxf(mr1, mx1);
        const float c0 = __expf(mr0 - mn0);
        const float c1 = __expf(mr1 - mn1);
        float ps0 = 0.f, ps1 = 0.f;
#pragma unroll
        for (int j = 0; j < 4; j++) {
            sa[j][0] = __expf(sa[j][0] - mn0);
            sa[j][1] = __expf(sa[j][1] - mn0);
            sa[j][2] = __expf(sa[j][2] - mn1);
            sa[j][3] = __expf(sa[j][3] - mn1);
            ps0 += sa[j][0] + sa[j][1];
            ps1 += sa[j][2] + sa[j][3];
        }
        ps0 += __shfl_xor_sync(0xffffffffu, ps0, 1);
        ps0 += __shfl_xor_sync(0xffffffffu, ps0, 2);
        ps1 += __shfl_xor_sync(0xffffffffu, ps1, 1);
        ps1 += __shfl_xor_sync(0xffffffffu, ps1, 2);
        lr0s = lr0s * c0 + ps0;
        lr1s = lr1s * c1 + ps1;
        mr0 = mn0; mr1 = mn1;
#pragma unroll
        for (int j = 0; j < 16; j++) {
            o[j][0] *= c0; o[j][1] *= c0;
            o[j][2] *= c1; o[j][3] *= c1;
        }

        // ---- P frags directly from registers (S C-frag == PV A-frag) ----
        uint32_t aph[2][4], apl[2][4];
#pragma unroll
        for (int t = 0; t < 2; t++) {
            uint16_t h0,l0,h1,l1;
            bsplit(sa[2*t][0],h0,l0);   bsplit(sa[2*t][1],h1,l1);
            aph[t][0] = packb(h0,h1);   apl[t][0] = packb(l0,l1);
            bsplit(sa[2*t][2],h0,l0);   bsplit(sa[2*t][3],h1,l1);
            aph[t][1] = packb(h0,h1);   apl[t][1] = packb(l0,l1);
            bsplit(sa[2*t+1][0],h0,l0); bsplit(sa[2*t+1][1],h1,l1);
            aph[t][2] = packb(h0,h1);   apl[t][2] = packb(l0,l1);
            bsplit(sa[2*t+1][2],h0,l0); bsplit(sa[2*t+1][3],h1,l1);
            aph[t][3] = packb(h0,h1);   apl[t][3] = packb(l0,l1);
        }

        // ---- V ready ----
        if (kt + 1 < niter) cp_wait<2>(); else cp_wait<0>();
        __syncthreads();
        const uint32_t vh_b = sb + FV(p);
        const uint32_t vl_b = vh_b + 8192;

        // ---- O += P V (bf16x2, ldmatrix over 64B-row V tiles) ----
#pragma unroll
        for (int t = 0; t < 2; t++) {
#pragma unroll
            for (int jp = 0; jp < 8; jp++) {
                uint32_t fvh4[4], fvl4[4];
                uint32_t vaddr = sw64(kv_row + jp*16, 2*t + v_clog);
                LDSM4(fvh4[0], fvh4[1], fvh4[2], fvh4[3], vh_b + vaddr);
                LDSM4(fvl4[0], fvl4[1], fvl4[2], fvl4[3], vl_b + vaddr);
#pragma unroll
                for (int half = 0; half < 2; half++) {
                    const int j = jp*2 + half;
                    uint32_t fvh[2] = { fvh4[half*2], fvh4[half*2+1] };
                    uint32_t fvl[2] = { fvl4[half*2], fvl4[half*2+1] };
                    mma16816(o[j], aph[t], fvh);
                    mma16816(o[j], apl[t], fvh);
                    mma16816(o[j], aph[t], fvl);
                }
            }
        }
    }

    // ---- normalize + split-store AO ----
    const float i0 = 1.f / lr0s;
    const float i1 = 1.f / lr1s;
    const size_t t0 = (size_t)(b*SEQ_ + row0g);
    const size_t t1 = t0 + 8;
#pragma unroll
    for (int j = 0; j < 16; j++) {
        const int col = h*HD_ + j*8 + 2*lc;
        uint16_t h0,l0,h1,l1;
        bsplit(o[j][0]*i0, h0, l0); bsplit(o[j][1]*i0, h1, l1);
        size_t off0 = t0*(HQ_*HD_) + col;
        *(uint32_t*)((char*)AOh + 2*off0) = packb(h0, h1);
        *(uint32_t*)((char*)AOl + 2*off0) = packb(l0, l1);
        bsplit(o[j][2]*i1, h0, l0); bsplit(o[j][3]*i1, h1, l1);
        size_t off1 = t1*(HQ_*HD_) + col;
        *(uint32_t*)((char*)AOh + 2*off1) = packb(h0, h1);
        *(uint32_t*)((char*)AOl + 2*off1) = packb(l0, l1);
    }
}

// ============================================================================
// Final per-token RMSNorm over DIM with attn_norm_w[expert]
// ============================================================================
__global__ __launch_bounds__(256) void final_rms(
    const float* __restrict__ in, const float* __restrict__ w,
    const int* __restrict__ mod, float* __restrict__ out)
{
    const int n = blockIdx.x;
    const int tid = threadIdx.x;
    const int e = mod[n];
    const float* row = in + (size_t)n*DIM_;
    float vals[8];
    float ss = 0.f;
#pragma unroll
    for (int u = 0; u < 8; u++) {
        float v = row[tid + u*256];
        vals[u] = v;
        ss += v*v;
    }
#pragma unroll
    for (int o = 16; o > 0; o >>= 1) ss += __shfl_xor_sync(0xffffffffu, ss, o);
    __shared__ float wsum[8];
    if ((tid & 31) == 0) wsum[tid >> 5] = ss;
    __syncthreads();
    float tot = 0.f;
#pragma unroll
    for (int i = 0; i < 8; i++) tot += wsum[i];
    float r = rsqrtf(tot * (1.0f/DIM_) + EPS_);
#pragma unroll
    for (int u = 0; u < 8; u++)
        out[(size_t)n*DIM_ + tid + u*256] = vals[u] * r * w[e*DIM_ + tid + u*256];
}

// ============================================================================
// launch — mmQ placed as our 5th launch: one harness-internal launch precedes
// ours, so our idx 4 == global idx 5 == the kernel ncu (-s 5 -c 1) captures.
// ============================================================================
extern "C" void kernel_launch(void* const* d_in, const int* in_sizes, int n_in,
                              void* d_out, int out_size)
{
    const float* x    = (const float*)d_in[0];
    const float* fcos = (const float*)d_in[1];
    const float* fsin = (const float*)d_in[2];
    const float* wq   = (const float*)d_in[3];
    const float* wk   = (const float*)d_in[4];
    const float* wv   = (const float*)d_in[5];
    const float* wo   = (const float*)d_in[6];
    const float* qnw  = (const float*)d_in[7];
    const float* knw  = (const float*)d_in[8];
    const float* anw  = (const float*)d_in[9];
    const int*   mod  = (const int*)d_in[10];
    float* out = (float*)d_out;

    float *pv, *po;
    bf16 *pxh, *pxl, *pwqh, *pwql, *pwkh, *pwkl, *pwvh, *pwvl, *pwoh, *pwol;
    bf16 *pqh, *pql, *pkh, *pkl, *pvth, *pvtl, *paoh, *paol;
    cudaGetSymbolAddress((void**)&pv,  g_v);
    cudaGetSymbolAddress((void**)&po,  g_o);
    cudaGetSymbolAddress((void**)&pxh, g_xh);  cudaGetSymbolAddress((void**)&pxl, g_xl);
    cudaGetSymbolAddress((void**)&pwqh, g_wqh); cudaGetSymbolAddress((void**)&pwql, g_wql);
    cudaGetSymbolAddress((void**)&pwkh, g_wkh); cudaGetSymbolAddress((void**)&pwkl, g_wkl);
    cudaGetSymbolAddress((void**)&pwvh, g_wvh); cudaGetSymbolAddress((void**)&pwvl, g_wvl);
    cudaGetSymbolAddress((void**)&pwoh, g_woh); cudaGetSymbolAddress((void**)&pwol, g_wol);
    cudaGetSymbolAddress((void**)&pqh, g_qh);   cudaGetSymbolAddress((void**)&pql, g_ql);
    cudaGetSymbolAddress((void**)&pkh, g_kh);   cudaGetSymbolAddress((void**)&pkl, g_kl);
    cudaGetSymbolAddress((void**)&pvth, g_vth); cudaGetSymbolAddress((void**)&pvtl, g_vtl);
    cudaGetSymbolAddress((void**)&paoh, g_aoh); cudaGetSymbolAddress((void**)&paol, g_aol);

    cudaFuncSetAttribute(flash_attn, cudaFuncAttributeMaxDynamicSharedMemorySize, FA_BYTES);
    cudaFuncSetAttribute(mm_bf16<0>, cudaFuncAttributeMaxDynamicSharedMemorySize, MM_DSMEM);
    cudaFuncSetAttribute(mm_bf16<1>, cudaFuncAttributeMaxDynamicSharedMemorySize, MM_DSMEM);

    // our idx 0..3 (deps for mmQ: sort, split, wtransQ — wtransK rides along)
    sort_tokens<<<1, 1024>>>(mod);                                            // 0
    split_f32<<<(NTOK*DIM_/4 + 255)/256, 256>>>(x, pxh, pxl, NTOK*DIM_/4);    // 1
    wtrans_split<<<dim3(64, 64, 2), 256>>>(wq, pwqh, pwql, DIM_, HQ_*HD_);    // 2
    wtrans_split<<<dim3(64, 32, 2), 256>>>(wk, pwkh, pwkl, DIM_, HK_*HD_);    // 3

    // our idx 4 == global idx 5: Q projection GEMM (profiled)
    mm_bf16<1><<<dim3(16, 33), 128, MM_DSMEM>>>(pxh, pxl, pwqh, pwql,
        nullptr, pqh, pql, qnw, fcos, fsin, DIM_, HQ_*HD_);                   // 4

    wtrans_split<<<dim3(64, 32, 2), 256>>>(wv, pwvh, pwvl, DIM_, HK_*HD_);    // 5
    mm_bf16<1><<<dim3( 8, 33), 128, MM_DSMEM>>>(pxh, pxl, pwkh, pwkl,
        nullptr, pkh, pkl, knw, fcos, fsin, DIM_, HK_*HD_);                   // 6
    mm_bf16<0><<<dim3( 8, 33), 128, MM_DSMEM>>>(pxh, pxl, pwvh, pwvl,
        pv, nullptr, nullptr, nullptr, nullptr, nullptr, DIM_, HK_*HD_);      // 7
    vtrans_split<<<dim3(64, 4, 16), 256>>>(pv, pvth, pvtl);                   // 8
    wtrans_split<<<dim3(64, 64, 2), 256>>>(wo, pwoh, pwol, HQ_*HD_, DIM_);    // 9

    // attention
    flash_attn<<<dim3(32, HQ_, BS_), 128, FA_BYTES>>>(pqh, pql, pkh, pkl, pvth, pvtl, paoh, paol);

    // output projection + final rmsnorm
    mm_bf16<0><<<dim3(16, 33), 128, MM_DSMEM>>>(paoh, paol, pwoh, pwol,
        po, nullptr, nullptr, nullptr, nullptr, nullptr, HQ_*HD_, DIM_);
    final_rms<<<NTOK, 256>>>(po, anw, mod, out);
}

// round 14
// speedup vs baseline: 1.1140x; 1.0745x over previous
#include <cuda_runtime.h>
#include <cuda_bf16.h>
#include <cuda_fp16.h>
#include <math.h>
#include <cstdint>

// ---------------- problem constants ----------------
#define E_   2
#define HQ_  16
#define HK_  8
#define HD_  128
#define DIM_ 2048
#define BS_  2
#define SEQ_ 2048
#define NTOK (BS_*SEQ_)          // 4096
#define EPS_ 1e-6f
#define SCALE_ 0.08838834764831845f   // 1/sqrt(128)

typedef __nv_bfloat16 bf16;

// ---------------- scratch (device globals) ----------------
__device__ float g_v [NTOK * (HK_*HD_)];
__device__ float g_o [NTOK * DIM_];
__device__ int   g_perm[NTOK];
__device__ int   g_c0;

// 16-bit split buffers (bf16 for GEMM operands; Q/K/V attention buffers hold fp16 bits)
__device__ bf16 g_xh [NTOK*DIM_],      g_xl [NTOK*DIM_];
__device__ bf16 g_wqh[E_*DIM_*HQ_*HD_], g_wql[E_*DIM_*HQ_*HD_];
__device__ bf16 g_wkh[E_*DIM_*HK_*HD_], g_wkl[E_*DIM_*HK_*HD_];
__device__ bf16 g_wvh[E_*DIM_*HK_*HD_], g_wvl[E_*DIM_*HK_*HD_];
__device__ bf16 g_woh[E_*DIM_*HQ_*HD_], g_wol[E_*DIM_*HQ_*HD_];
__device__ bf16 g_qh [NTOK*(HQ_*HD_)],  g_ql [NTOK*(HQ_*HD_)];   // fp16 bits
__device__ bf16 g_kh [NTOK*(HK_*HD_)],  g_kl [NTOK*(HK_*HD_)];   // fp16 bits (lo unused)
__device__ bf16 g_vth[NTOK*(HK_*HD_)];                           // fp16 bits, [b][kvh][d][seq]
__device__ bf16 g_aoh[NTOK*(HQ_*HD_)],  g_aol[NTOK*(HQ_*HD_)];   // bf16 (WO GEMM input)

// =============================== helpers ===============================
__device__ __forceinline__ uint32_t smem_u32(const void* p) {
    uint32_t a;
    asm("{ .reg .u64 t; cvta.to.shared.u64 t, %1; cvt.u32.u64 %0, t; }" : "=r"(a) : "l"(p));
    return a;
}
#define CP_ASYNC16(dst, src) \
    asm volatile("cp.async.cg.shared.global [%0], [%1], 16;" :: "r"(dst), "l"(src) : "memory")
#define CP_COMMIT() asm volatile("cp.async.commit_group;" ::: "memory")
template<int N> __device__ __forceinline__ void cp_wait() {
    asm volatile("cp.async.wait_group %0;" :: "n"(N) : "memory");
}
#define LDSM4(r0,r1,r2,r3, addr) \
    asm volatile("ldmatrix.sync.aligned.m8n8.x4.shared.b16 {%0,%1,%2,%3}, [%4];" \
        : "=r"(r0), "=r"(r1), "=r"(r2), "=r"(r3) : "r"(addr))

__device__ __forceinline__ void bsplit(float x, uint16_t& h, uint16_t& l) {
    bf16 bh = __float2bfloat16_rn(x);
    h = __bfloat16_as_ushort(bh);
    l = __bfloat16_as_ushort(__float2bfloat16_rn(x - __bfloat162float(bh)));
}
__device__ __forceinline__ void hsplit(float x, uint16_t& h, uint16_t& l) {
    __half hh = __float2half_rn(x);
    h = __half_as_ushort(hh);
    l = __half_as_ushort(__float2half_rn(x - __half2float(hh)));
}
__device__ __forceinline__ uint32_t packb(uint16_t lo_elem, uint16_t hi_elem) {
    return (uint32_t)lo_elem | ((uint32_t)hi_elem << 16);
}
__device__ __forceinline__ void mma16816(float* c, const uint32_t* a, const uint32_t* b) {
    asm volatile("mma.sync.aligned.m16n8k16.row.col.f32.bf16.bf16.f32 "
        "{%0,%1,%2,%3}, {%4,%5,%6,%7}, {%8,%9}, {%0,%1,%2,%3};"
        : "+f"(c[0]), "+f"(c[1]), "+f"(c[2]), "+f"(c[3])
        : "r"(a[0]), "r"(a[1]), "r"(a[2]), "r"(a[3]), "r"(b[0]), "r"(b[1]));
}
__device__ __forceinline__ void mma16816h(float* c, const uint32_t* a, const uint32_t* b) {
    asm volatile("mma.sync.aligned.m16n8k16.row.col.f32.f16.f16.f32 "
        "{%0,%1,%2,%3}, {%4,%5,%6,%7}, {%8,%9}, {%0,%1,%2,%3};"
        : "+f"(c[0]), "+f"(c[1]), "+f"(c[2]), "+f"(c[3])
        : "r"(a[0]), "r"(a[1]), "r"(a[2]), "r"(a[3]), "r"(b[0]), "r"(b[1]));
}
__device__ __forceinline__ uint32_t sw256(int r, int off) {
    return (uint32_t)(r*256 + (off ^ ((r & 7) << 4)));
}
__device__ __forceinline__ uint32_t sw64(int r, int clog) {
    return (uint32_t)(r*64 + ((clog ^ (r >> 1)) & 3)*16);
}

// ============================================================================
// sort tokens by modality (stable counting sort), deterministic
// ============================================================================
__global__ __launch_bounds__(1024) void sort_tokens(const int* __restrict__ mod)
{
    __shared__ int s[1024];
    const int tid = threadIdx.x;
    int m[4]; int cnt = 0;
#pragma unroll
    for (int u = 0; u < 4; u++) { m[u] = mod[tid*4 + u]; cnt += (m[u] == 0); }
    s[tid] = cnt;
    __syncthreads();
    for (int off = 1; off < 1024; off <<= 1) {
        int v = (tid >= off) ? s[tid - off] : 0;
        __syncthreads();
        s[tid] += v;
        __syncthreads();
    }
    const int c0 = s[1023];
    if (tid == 0) g_c0 = c0;
    int r0 = s[tid] - cnt;
#pragma unroll
    for (int u = 0; u < 4; u++) {
        int g = tid*4 + u;
        if (m[u] == 0) { g_perm[r0] = g; r0++; }
        else           { g_perm[c0 + g - r0] = g; }
    }
}

// ============================================================================
// elementwise fp32 -> bf16 hi/lo split (for x)
// ============================================================================
__global__ __launch_bounds__(256) void split_f32(
    const float* __restrict__ in, bf16* __restrict__ hi, bf16* __restrict__ lo, int n4)
{
    int i = blockIdx.x * 256 + threadIdx.x;
    if (i >= n4) return;
    float4 v = ((const float4*)in)[i];
    uint16_t hx,lx,hy,ly,hz,lz,hw,lw;
    bsplit(v.x,hx,lx); bsplit(v.y,hy,ly); bsplit(v.z,hz,lz); bsplit(v.w,hw,lw);
    ((uint2*)hi)[i] = make_uint2(packb(hx,hy), packb(hz,hw));
    ((uint2*)lo)[i] = make_uint2(packb(lx,ly), packb(lz,lw));
}

// ============================================================================
// weight transpose-split: W [e][K][NC] fp32 -> T [e][NC][K] bf16 hi/lo
// ============================================================================
__global__ __launch_bounds__(256) void wtrans_split(
    const float* __restrict__ W, bf16* __restrict__ Th, bf16* __restrict__ Tl,
    int K, int NC)
{
    __shared__ float t[32][33];
    const int e  = blockIdx.z;
    const int k0 = blockIdx.x * 32, n0 = blockIdx.y * 32;
    const int tx = threadIdx.x & 31, ty = threadIdx.x >> 5;
    const float* Wp = W + (size_t)e * K * NC;
    for (int r = ty; r < 32; r += 8)
        t[r][tx] = Wp[(size_t)(k0 + r) * NC + n0 + tx];
    __syncthreads();
    bf16* th = Th + (size_t)e * NC * K;
    bf16* tl = Tl + (size_t)e * NC * K;
    for (int r = ty; r < 32; r += 8) {
        float v = t[tx][r];
        uint16_t h, l; bsplit(v, h, l);
        size_t o = (size_t)(n0 + r) * K + k0 + tx;
        th[o] = __ushort_as_bfloat16(h);
        tl[o] = __ushort_as_bfloat16(l);
    }
}

// ============================================================================
// V transpose-split: fp32 -> fp16 (single), [b][kvh][d][seq]
// ============================================================================
__global__ __launch_bounds__(256) void vtrans_half(
    const float* __restrict__ V, bf16* __restrict__ Th)
{
    __shared__ float t[32][33];
    const int s0 = blockIdx.x * 32, d0 = blockIdx.y * 32;
    const int z  = blockIdx.z;                 // b*8 + kvh
    const int b  = z >> 3, kvh = z & 7;
    const int tx = threadIdx.x & 31, ty = threadIdx.x >> 5;
    for (int r = ty; r < 32; r += 8)
        t[r][tx] = V[(size_t)(b*SEQ_ + s0 + r) * (HK_*HD_) + kvh*HD_ + d0 + tx];
    __syncthreads();
    for (int r = ty; r < 32; r += 8) {
        uint16_t h = __half_as_ushort(__float2half_rn(t[tx][r]));
        size_t o = (size_t)(z*HD_ + d0 + r) * SEQ_ + s0 + tx;
        ((uint16_t*)Th)[o] = h;
    }
}

// ============================================================================
// bf16x2 mma.sync GEMM over expert-sorted rows, ldmatrix fragment loads.
// MODE 0: plain fp32 store (V, WO).
// MODE 1: fused RMSNorm+RoPE epilogue, *fp16* hi/lo store (Q, K for attention).
// ============================================================================
#define MM_STAGE 40960          // Ah 10240 | Al | Bh | Bl
#define MM_DSMEM (2*MM_STAGE)

template<int MODE>
__global__ __launch_bounds__(128) void mm_bf16(
    const bf16* __restrict__ Ah, const bf16* __restrict__ Al,
    const bf16* __restrict__ Bh, const bf16* __restrict__ Bl,
    float* __restrict__ Cf,
    bf16* __restrict__ Ch, bf16* __restrict__ Cl,
    const float* __restrict__ normw,
    const float* __restrict__ fcos, const float* __restrict__ fsin,
    int K, int NC)
{
    extern __shared__ char sm[];
    __shared__ int sPerm[128];
    __shared__ float sred[4][64];
    const int tid  = threadIdx.x;
    const int lane = tid & 31;
    const int w    = tid >> 5;
    const int wm64 = (w & 1) * 64;
    const int wn64 = (w >> 1) * 64;
    const int bn   = blockIdx.x * 128;
    const int by   = blockIdx.y;

    const int c0 = g_c0;
    const int T0 = (c0 + 127) >> 7;
    const int T1 = (NTOK - c0 + 127) >> 7;
    if (by >= T0 + T1) return;
    const int e       = (by < T0) ? 0 : 1;
    const int rowbase = e ? (c0 + (by - T0) * 128) : (by * 128);
    const int limit   = e ? NTOK : c0;
    const size_t bofs = (size_t)e * NC * K + (size_t)bn * K;

    {
        int gs = rowbase + tid;
        sPerm[tid] = g_perm[gs < NTOK ? gs : (NTOK - 1)];
    }
    __syncthreads();

    const uint32_t sb = smem_u32(sm);

    auto load_chunk = [&](int cc, int p) {
        const int k0 = cc * 32;
        const uint32_t base = sb + p * MM_STAGE;
#pragma unroll
        for (int i = 0; i < 8; i++) {
            int idx = tid + (i << 7);
            int comp = idx >> 9, rem = idx & 511;
            int r = rem >> 2, c = rem & 3;
            const bf16* src = (comp ? Al : Ah) + (size_t)sPerm[r] * K + k0 + c * 8;
            CP_ASYNC16(base + comp*10240 + (uint32_t)(r*80 + c*16), src);
        }
#pragma unroll
        for (int i = 0; i < 8; i++) {
            int idx = tid + (i << 7);
            int comp = idx >> 9, rem = idx & 511;
            int r = rem >> 2, c = rem & 3;
            const bf16* src = (comp ? Bl : Bh) + bofs + (size_t)r * K + k0 + c * 8;
            CP_ASYNC16(base + 20480 + comp*10240 + (uint32_t)(r*80 + c*16), src);
        }
    };

    float acc[4][8][4];
#pragma unroll
    for (int i = 0; i < 4; i++)
#pragma unroll
        for (int j = 0; j < 8; j++)
#pragma unroll
            for (int q = 0; q < 4; q++) acc[i][j][q] = 0.f;

    const int NCH = K / 32;
    load_chunk(0, 0); CP_COMMIT();
    load_chunk(1, 1); CP_COMMIT();

    const int lr = lane >> 2;
    const int lc = lane & 3;
    const int g8  = lane & 7;
    const int grp = lane >> 3;
    const int a_row = wm64 + (grp & 1) * 8 + g8;
    const int a_ofx = (grp >> 1) * 16;
    const int b_row = wn64 + (grp >> 1) * 8 + g8;
    const int b_ofx = (grp & 1) * 16;

    for (int c = 0; c < NCH; c++) {
        cp_wait<1>();
        __syncthreads();
        const uint32_t bb = sb + (c & 1) * MM_STAGE;
#pragma unroll
        for (int ks = 0; ks < 2; ks++) {
            const uint32_t koff = (uint32_t)(ks * 32);
            uint32_t fah[4][4], fal[4][4];
#pragma unroll
            for (int i = 0; i < 4; i++) {
                uint32_t aaddr = bb + (uint32_t)((a_row + i*16) * 80) + koff + a_ofx;
                LDSM4(fah[i][0], fah[i][1], fah[i][2], fah[i][3], aaddr);
                LDSM4(fal[i][0], fal[i][1], fal[i][2], fal[i][3], aaddr + 10240);
            }
            uint32_t fbh4[4][4], fbl4[4][4];
#pragma unroll
            for (int jj = 0; jj < 4; jj++) {
                uint32_t baddr = bb + 20480 + (uint32_t)((b_row + jj*16) * 80) + koff + b_ofx;
                LDSM4(fbh4[jj][0], fbh4[jj][1], fbh4[jj][2], fbh4[jj][3], baddr);
                LDSM4(fbl4[jj][0], fbl4[jj][1], fbl4[jj][2], fbl4[jj][3], baddr + 10240);
            }
#pragma unroll
            for (int jj = 0; jj < 4; jj++) {
#pragma unroll
                for (int half = 0; half < 2; half++) {
                    const int j = jj*2 + half;
                    uint32_t fbh[2] = { fbh4[jj][half*2], fbh4[jj][half*2+1] };
                    uint32_t fbl[2] = { fbl4[jj][half*2], fbl4[jj][half*2+1] };
#pragma unroll
                    for (int i = 0; i < 4; i++) {
                        mma16816(acc[i][j], fah[i], fbh);
                        mma16816(acc[i][j], fal[i], fbh);
                        mma16816(acc[i][j], fah[i], fbl);
                    }
                }
            }
        }
        __syncthreads();
        if (c + 2 < NCH) load_chunk(c + 2, c & 1);
        CP_COMMIT();
    }

    if (MODE == 0) {
#pragma unroll
        for (int i = 0; i < 4; i++) {
            int lr0 = wm64 + i * 16 + lr;
            bool v0 = (rowbase + lr0)     < limit;
            bool v1 = (rowbase + lr0 + 8) < limit;
            int t0 = v0 ? sPerm[lr0]     : 0;
            int t1 = v1 ? sPerm[lr0 + 8] : 0;
#pragma unroll
            for (int j = 0; j < 8; j++) {
                int cb = bn + wn64 + j * 8 + (lc << 1);
                if (v0) *(float2*)&Cf[(size_t)t0 * NC + cb] = make_float2(acc[i][j][0], acc[i][j][1]);
                if (v1) *(float2*)&Cf[(size_t)t1 * NC + cb] = make_float2(acc[i][j][2], acc[i][j][3]);
            }
        }
    } else {
        float rs[4][2];
#pragma unroll
        for (int i = 0; i < 4; i++) {
            float s0 = 0.f, s1 = 0.f;
#pragma unroll
            for (int j = 0; j < 8; j++) {
                s0 += acc[i][j][0]*acc[i][j][0] + acc[i][j][1]*acc[i][j][1];
                s1 += acc[i][j][2]*acc[i][j][2] + acc[i][j][3]*acc[i][j][3];
            }
            rs[i][0] = s0; rs[i][1] = s1;
        }
#pragma unroll
        for (int i = 0; i < 4; i++) {
#pragma unroll
            for (int hh = 0; hh < 2; hh++) {
                rs[i][hh] += __shfl_xor_sync(0xffffffffu, rs[i][hh], 1);
                rs[i][hh] += __shfl_xor_sync(0xffffffffu, rs[i][hh], 2);
            }
        }
        if (lc == 0) {
#pragma unroll
            for (int i = 0; i < 4; i++) {
                sred[w][i*16 + lr]     = rs[i][0];
                sred[w][i*16 + 8 + lr] = rs[i][1];
            }
        }
        __syncthreads();
        float rinv[4][2];
#pragma unroll
        for (int i = 0; i < 4; i++) {
            float t0 = rs[i][0] + sred[w ^ 2][i*16 + lr];
            float t1 = rs[i][1] + sred[w ^ 2][i*16 + 8 + lr];
            rinv[i][0] = rsqrtf(t0 * (1.0f/HD_) + EPS_);
            rinv[i][1] = rsqrtf(t1 * (1.0f/HD_) + EPS_);
        }
#pragma unroll
        for (int i = 0; i < 4; i++) {
            const int lr0 = wm64 + i * 16 + lr;
            const bool v0 = (rowbase + lr0)     < limit;
            const bool v1 = (rowbase + lr0 + 8) < limit;
            const int t0 = sPerm[lr0], t1 = sPerm[lr0 + 8];
            const int s0 = t0 & (SEQ_-1), s1 = t1 & (SEQ_-1);
#pragma unroll
            for (int j = 0; j < 8; j++) {
                const int col0 = wn64 + j*8 + (lc << 1);
                const float2 nw = *(const float2*)&normw[e*HD_ + col0];
                const int cp = col0 >> 1;
                if (v0) {
                    float a0 = acc[i][j][0] * rinv[i][0] * nw.x;
                    float a1 = acc[i][j][1] * rinv[i][0] * nw.y;
                    float cc = fcos[s0*(HD_/2) + cp], sn = fsin[s0*(HD_/2) + cp];
                    float e0 = a0*cc - a1*sn, e1 = a0*sn + a1*cc;
                    uint16_t h0,l0,h1,l1;
                    hsplit(e0,h0,l0); hsplit(e1,h1,l1);
                    size_t off = (size_t)t0 * NC + bn + col0;
                    *(uint32_t*)((char*)Ch + 2*off) = packb(h0,h1);
                    *(uint32_t*)((char*)Cl + 2*off) = packb(l0,l1);
                }
                if (v1) {
                    float a0 = acc[i][j][2] * rinv[i][1] * nw.x;
                    float a1 = acc[i][j][3] * rinv[i][1] * nw.y;
                    float cc = fcos[s1*(HD_/2) + cp], sn = fsin[s1*(HD_/2) + cp];
                    float e0 = a0*cc - a1*sn, e1 = a0*sn + a1*cc;
                    uint16_t h0,l0,h1,l1;
                    hsplit(e0,h0,l0); hsplit(e1,h1,l1);
                    size_t off = (size_t)t1 * NC + bn + col0;
                    *(uint32_t*)((char*)Ch + 2*off) = packb(h0,h1);
                    *(uint32_t*)((char*)Cl + 2*off) = packb(l0,l1);
                }
            }
        }
    }
}

// ============================================================================
// Tensor-core causal flash attention — fp16 asymmetric precision.
// Q/P: fp16 hi+lo (accurate to 2^-22). K/V: single fp16 (2^-12).
// 2 mma per k16 chain. 64-row CTAs, 128 threads, kv tiles 32.
// smem 64KB: Qh 16K | Ql 16K | K[2] 8K ea | V[2] 8K ea.
// ============================================================================
#define FQ_H 0
#define FQ_L 16384
#define FK(p) (32768 + (p)*8192)
#define FV(p) (49152 + (p)*8192)
#define FA_BYTES 65536

__global__ __launch_bounds__(128) void flash_attn(
    const bf16* __restrict__ Qh, const bf16* __restrict__ Ql,
    const bf16* __restrict__ Kh,
    const bf16* __restrict__ Vth,
    bf16* __restrict__ AOh, bf16* __restrict__ AOl)
{
    extern __shared__ char sm[];
    const int tid  = threadIdx.x;
    const int lane = tid & 31;
    const int w    = tid >> 5;      // 0..3
    const int lr   = lane >> 2;
    const int lc   = lane & 3;
    const int g8   = lane & 7;
    const int grp  = lane >> 3;

    const int qt = 31 - blockIdx.x;      // big tiles first
    const int h  = blockIdx.y;
    const int b  = blockIdx.z;
    const int kvh   = h >> 1;
    const int qbase = qt * 64;
    const int m0    = w * 16;
    const int niter = 2 * qt + 2;        // kv tiles of 32

    const uint32_t sb = smem_u32(sm);

    const int q_row  = m0 + (grp & 1) * 8 + g8;
    const int q_ofx  = (grp >> 1) * 16;
    const int kv_row = (grp >> 1) * 8 + g8;
    const int kv_ofx = (grp & 1) * 16;
    const int v_clog = grp & 1;

    // ---- Q load (hi+lo), group 0 ----
#pragma unroll
    for (int i = 0; i < 16; i++) {
        int idx = tid + (i << 7);
        int comp = idx >> 10, rem = idx & 1023;
        int r = rem >> 4, c = rem & 15;
        const bf16* src = (comp ? Ql : Qh)
            + (size_t)(b*SEQ_ + qbase + r)*(HQ_*HD_) + h*HD_ + c*8;
        CP_ASYNC16(sb + (comp ? FQ_L : FQ_H) + sw256(r, c*16), src);
    }
    CP_COMMIT();

    auto load_k = [&](int kt, int p) {
#pragma unroll
        for (int i = 0; i < 4; i++) {         // 512 chunks: 32 rows x 16
            int idx = tid + (i << 7);
            int r = idx >> 4, c = idx & 15;
            const bf16* src = Kh
                + (size_t)(b*SEQ_ + kt*32 + r)*(HK_*HD_) + kvh*HD_ + c*8;
            CP_ASYNC16(sb + FK(p) + sw256(r, c*16), src);
        }
        CP_COMMIT();
    };
    auto load_v = [&](int kt, int p) {
#pragma unroll
        for (int i = 0; i < 4; i++) {         // 512 chunks: 128 d-rows x 4
            int idx = tid + (i << 7);
            int r = idx >> 2, c = idx & 3;
            const bf16* src = Vth
                + (size_t)((b*HK_ + kvh)*HD_ + r)*SEQ_ + kt*32 + c*8;
            CP_ASYNC16(sb + FV(p) + sw64(r, c), src);
        }
        CP_COMMIT();
    };

    load_k(0, 0);     // group 1
    load_v(0, 0);     // group 2

    // ---- Q fragments hoisted to registers ----
    cp_wait<2>();     // Q group complete (K0/V0 still in flight)
    __syncthreads();
    uint32_t qfh[8][4], qfl[8][4];
#pragma unroll
    for (int s = 0; s < 8; s++) {
        uint32_t qaddr = sb + FQ_H + sw256(q_row, s*32 + q_ofx);
        LDSM4(qfh[s][0], qfh[s][1], qfh[s][2], qfh[s][3], qaddr);
        LDSM4(qfl[s][0], qfl[s][1], qfl[s][2], qfl[s][3], qaddr + 16384);
    }

    float o[16][4];
#pragma unroll
    for (int j = 0; j < 16; j++)
#pragma unroll
        for (int q = 0; q < 4; q++) o[j][q] = 0.f;
    float mr0 = -1e30f, mr1 = -1e30f, lr0s = 0.f, lr1s = 0.f;

    const int row0g = qbase + m0 + lr;

    for (int kt = 0; kt < niter; kt++) {
        const int p = kt & 1;
        cp_wait<1>();
        __syncthreads();
        if (kt + 1 < niter) { load_k(kt + 1, p ^ 1); load_v(kt + 1, p ^ 1); }

        const uint32_t kh_b = sb + FK(p);

        // ---- S = Q K^T (fp16: qh*kh + ql*kh) ----
        float sa[4][4];
#pragma unroll
        for (int j = 0; j < 4; j++)
#pragma unroll
            for (int q = 0; q < 4; q++) sa[j][q] = 0.f;
#pragma unroll
        for (int s = 0; s < 8; s++) {
            const int b0 = s*32;
#pragma unroll
            for (int jj = 0; jj < 2; jj++) {
                uint32_t fkh4[4];
                uint32_t kaddr = sw256(kv_row + jj*16, b0 + kv_ofx);
                LDSM4(fkh4[0], fkh4[1], fkh4[2], fkh4[3], kh_b + kaddr);
#pragma unroll
                for (int half = 0; half < 2; half++) {
                    const int j = jj*2 + half;
                    uint32_t fkh[2] = { fkh4[half*2], fkh4[half*2+1] };
                    mma16816h(sa[j], qfh[s], fkh);
                    mma16816h(sa[j], qfl[s], fkh);
                }
            }
        }

        // ---- online softmax ----
        const bool need_mask = (kt*32 + 31 > qbase + m0);
        float mx0 = -1e30f, mx1 = -1e30f;
#pragma unroll
        for (int j = 0; j < 4; j++) {
            const int cb = kt*32 + j*8 + 2*lc;
#pragma unroll
            for (int q = 0; q < 4; q++) {
                float v = sa[j][q] * SCALE_;
                if (need_mask) {
                    int col = cb + (q & 1);
                    int row = (q < 2) ? row0g : (row0g + 8);
                    if (col > row) v = -1e30f;
                }
                sa[j][q] = v;
            }
            mx0 = fmaxf(mx0, fmaxf(sa[j][0], sa[j][1]));
            mx1 = fmaxf(mx1, fmaxf(sa[j][2], sa[j][3]));
        }
        mx0 = fmaxf(mx0, __shfl_xor_sync(0xffffffffu, mx0, 1));
        mx0 = fmaxf(mx0, __shfl_xor_sync(0xffffffffu, mx0, 2));
        mx1 = fmaxf(mx1, __shfl_xor_sync(0xffffffffu, mx1, 1));
        mx1 = fmaxf(mx1, __shfl_xor_sync(0xffffffffu, mx1, 2));
        const float mn0 = fmaxf(mr0, mx0);
        const float mn1 = fmaxf(mr1, mx1);
        const float c0 = __expf(mr0 - mn0);
        const float c1 = __expf(mr1 - mn1);
        float ps0 = 0.f, ps1 = 0.f;
#pragma unroll
        for (int j = 0; j < 4; j++) {
            sa[j][0] = __expf(sa[j][0] - mn0);
            sa[j][1] = __expf(sa[j][1] - mn0);
            sa[j][2] = __expf(sa[j][2] - mn1);
            sa[j][3] = __expf(sa[j][3] - mn1);
            ps0 += sa[j][0] + sa[j][1];
            ps1 += sa[j][2] + sa[j][3];
        }
        ps0 += __shfl_xor_sync(0xffffffffu, ps0, 1);
        ps0 += __shfl_xor_sync(0xffffffffu, ps0, 2);
        ps1 += __shfl_xor_sync(0xffffffffu, ps1, 1);
        ps1 += __shfl_xor_sync(0xffffffffu, ps1, 2);
        lr0s = lr0s * c0 + ps0;
        lr1s = lr1s * c1 + ps1;
        mr0 = mn0; mr1 = mn1;
#pragma unroll
        for (int j = 0; j < 16; j++) {
            o[j][0] *= c0; o[j][1] *= c0;
            o[j][2] *= c1; o[j][3] *= c1;
        }

        // ---- P frags from registers (fp16 hi/lo; S C-frag == PV A-frag) ----
        uint32_t aph[2][4], apl[2][4];
#pragma unroll
        for (int t = 0; t < 2; t++) {
            uint16_t h0,l0,h1,l1;
            hsplit(sa[2*t][0],h0,l0);   hsplit(sa[2*t][1],h1,l1);
            aph[t][0] = packb(h0,h1);   apl[t][0] = packb(l0,l1);
            hsplit(sa[2*t][2],h0,l0);   hsplit(sa[2*t][3],h1,l1);
            aph[t][1] = packb(h0,h1);   apl[t][1] = packb(l0,l1);
            hsplit(sa[2*t+1][0],h0,l0); hsplit(sa[2*t+1][1],h1,l1);
            aph[t][2] = packb(h0,h1);   apl[t][2] = packb(l0,l1);
            hsplit(sa[2*t+1][2],h0,l0); hsplit(sa[2*t+1][3],h1,l1);
            aph[t][3] = packb(h0,h1);   apl[t][3] = packb(l0,l1);
        }

        // ---- V ready ----
        if (kt + 1 < niter) cp_wait<2>(); else cp_wait<0>();
        __syncthreads();
        const uint32_t vh_b = sb + FV(p);

        // ---- O += P V (fp16: ph*vh + pl*vh) ----
#pragma unroll
        for (int t = 0; t < 2; t++) {
#pragma unroll
            for (int jp = 0; jp < 8; jp++) {
                uint32_t fvh4[4];
                uint32_t vaddr = sw64(kv_row + jp*16, 2*t + v_clog);
                LDSM4(fvh4[0], fvh4[1], fvh4[2], fvh4[3], vh_b + vaddr);
#pragma unroll
                for (int half = 0; half < 2; half++) {
                    const int j = jp*2 + half;
                    uint32_t fvh[2] = { fvh4[half*2], fvh4[half*2+1] };
                    mma16816h(o[j], aph[t], fvh);
                    mma16816h(o[j], apl[t], fvh);
                }
            }
        }
    }

    // ---- normalize + bf16 split-store AO (WO GEMM consumes bf16) ----
    const float i0 = 1.f / lr0s;
    const float i1 = 1.f / lr1s;
    const size_t t0 = (size_t)(b*SEQ_ + row0g);
    const size_t t1 = t0 + 8;
#pragma unroll
    for (int j = 0; j < 16; j++) {
        const int col = h*HD_ + j*8 + 2*lc;
        uint16_t h0,l0,h1,l1;
        bsplit(o[j][0]*i0, h0, l0); bsplit(o[j][1]*i0, h1, l1);
        size_t off0 = t0*(HQ_*HD_) + col;
        *(uint32_t*)((char*)AOh + 2*off0) = packb(h0, h1);
        *(uint32_t*)((char*)AOl + 2*off0) = packb(l0, l1);
        bsplit(o[j][2]*i1, h0, l0); bsplit(o[j][3]*i1, h1, l1);
        size_t off1 = t1*(HQ_*HD_) + col;
        *(uint32_t*)((char*)AOh + 2*off1) = packb(h0, h1);
        *(uint32_t*)((char*)AOl + 2*off1) = packb(l0, l1);
    }
}

// ============================================================================
// Final per-token RMSNorm over DIM with attn_norm_w[expert]
// ============================================================================
__global__ __launch_bounds__(256) void final_rms(
    const float* __restrict__ in, const float* __restrict__ w,
    const int* __restrict__ mod, float* __restrict__ out)
{
    const int n = blockIdx.x;
    const int tid = threadIdx.x;
    const int e = mod[n];
    const float* row = in + (size_t)n*DIM_;
    float vals[8];
    float ss = 0.f;
#pragma unroll
    for (int u = 0; u < 8; u++) {
        float v = row[tid + u*256];
        vals[u] = v;
        ss += v*v;
    }
#pragma unroll
    for (int o = 16; o > 0; o >>= 1) ss += __shfl_xor_sync(0xffffffffu, ss, o);
    __shared__ float wsum[8];
    if ((tid & 31) == 0) wsum[tid >> 5] = ss;
    __syncthreads();
    float tot = 0.f;
#pragma unroll
    for (int i = 0; i < 8; i++) tot += wsum[i];
    float r = rsqrtf(tot * (1.0f/DIM_) + EPS_);
#pragma unroll
    for (int u = 0; u < 8; u++)
        out[(size_t)n*DIM_ + tid + u*256] = vals[u] * r * w[e*DIM_ + tid + u*256];
}

// ============================================================================
// launch
// ============================================================================
extern "C" void kernel_launch(void* const* d_in, const int* in_sizes, int n_in,
                              void* d_out, int out_size)
{
    const float* x    = (const float*)d_in[0];
    const float* fcos = (const float*)d_in[1];
    const float* fsin = (const float*)d_in[2];
    const float* wq   = (const float*)d_in[3];
    const float* wk   = (const float*)d_in[4];
    const float* wv   = (const float*)d_in[5];
    const float* wo   = (const float*)d_in[6];
    const float* qnw  = (const float*)d_in[7];
    const float* knw  = (const float*)d_in[8];
    const float* anw  = (const float*)d_in[9];
    const int*   mod  = (const int*)d_in[10];
    float* out = (float*)d_out;

    float *pv, *po;
    bf16 *pxh, *pxl, *pwqh, *pwql, *pwkh, *pwkl, *pwvh, *pwvl, *pwoh, *pwol;
    bf16 *pqh, *pql, *pkh, *pkl, *pvth, *paoh, *paol;
    cudaGetSymbolAddress((void**)&pv,  g_v);
    cudaGetSymbolAddress((void**)&po,  g_o);
    cudaGetSymbolAddress((void**)&pxh, g_xh);  cudaGetSymbolAddress((void**)&pxl, g_xl);
    cudaGetSymbolAddress((void**)&pwqh, g_wqh); cudaGetSymbolAddress((void**)&pwql, g_wql);
    cudaGetSymbolAddress((void**)&pwkh, g_wkh); cudaGetSymbolAddress((void**)&pwkl, g_wkl);
    cudaGetSymbolAddress((void**)&pwvh, g_wvh); cudaGetSymbolAddress((void**)&pwvl, g_wvl);
    cudaGetSymbolAddress((void**)&pwoh, g_woh); cudaGetSymbolAddress((void**)&pwol, g_wol);
    cudaGetSymbolAddress((void**)&pqh, g_qh);   cudaGetSymbolAddress((void**)&pql, g_ql);
    cudaGetSymbolAddress((void**)&pkh, g_kh);   cudaGetSymbolAddress((void**)&pkl, g_kl);
    cudaGetSymbolAddress((void**)&pvth, g_vth);
    cudaGetSymbolAddress((void**)&paoh, g_aoh); cudaGetSymbolAddress((void**)&paol, g_aol);

    cudaFuncSetAttribute(flash_attn, cudaFuncAttributeMaxDynamicSharedMemorySize, FA_BYTES);
    cudaFuncSetAttribute(mm_bf16<0>, cudaFuncAttributeMaxDynamicSharedMemorySize, MM_DSMEM);
    cudaFuncSetAttribute(mm_bf16<1>, cudaFuncAttributeMaxDynamicSharedMemorySize, MM_DSMEM);

    // preprocessing
    sort_tokens<<<1, 1024>>>(mod);
    split_f32<<<(NTOK*DIM_/4 + 255)/256, 256>>>(x, pxh, pxl, NTOK*DIM_/4);
    wtrans_split<<<dim3(64, 64, 2), 256>>>(wq, pwqh, pwql, DIM_, HQ_*HD_);
    wtrans_split<<<dim3(64, 32, 2), 256>>>(wk, pwkh, pwkl, DIM_, HK_*HD_);

    // Q projection GEMM (fused rmsnorm+rope -> fp16 hi/lo)
    mm_bf16<1><<<dim3(16, 33), 128, MM_DSMEM>>>(pxh, pxl, pwqh, pwql,
        nullptr, pqh, pql, qnw, fcos, fsin, DIM_, HQ_*HD_);

    wtrans_split<<<dim3(64, 32, 2), 256>>>(wv, pwvh, pwvl, DIM_, HK_*HD_);
    mm_bf16<1><<<dim3( 8, 33), 128, MM_DSMEM>>>(pxh, pxl, pwkh, pwkl,
        nullptr, pkh, pkl, knw, fcos, fsin, DIM_, HK_*HD_);
    mm_bf16<0><<<dim3( 8, 33), 128, MM_DSMEM>>>(pxh, pxl, pwvh, pwvl,
        pv, nullptr, nullptr, nullptr, nullptr, nullptr, DIM_, HK_*HD_);
    vtrans_half<<<dim3(64, 4, 16), 256>>>(pv, pvth);
    wtrans_split<<<dim3(64, 64, 2), 256>>>(wo, pwoh, pwol, HQ_*HD_, DIM_);

    // attention (fp16 asymmetric, 2-mma chains)
    flash_attn<<<dim3(32, HQ_, BS_), 128, FA_BYTES>>>(pqh, pql, pkh, pvth, paoh, paol);

    // output projection + final rmsnorm
    mm_bf16<0><<<dim3(16, 33), 128, MM_DSMEM>>>(paoh, paol, pwoh, pwol,
        po, nullptr, nullptr, nullptr, nullptr, nullptr, HQ_*HD_, DIM_);
    final_rms<<<NTOK, 256>>>(po, anw, mod, out);
}

// round 15
// speedup vs baseline: 1.1487x; 1.0312x over previous
#include <cuda_runtime.h>
#include <cuda_bf16.h>
#include <cuda_fp16.h>
#include <math.h>
#include <cstdint>

// ---------------- problem constants ----------------
#define E_   2
#define HQ_  16
#define HK_  8
#define HD_  128
#define DIM_ 2048
#define BS_  2
#define SEQ_ 2048
#define NTOK (BS_*SEQ_)          // 4096
#define EPS_ 1e-6f
#define SCALE_ 0.08838834764831845f   // 1/sqrt(128)
#define SCL2_  0.12754217f            // SCALE_ * log2(e)

typedef __nv_bfloat16 bf16;

// ---------------- scratch (device globals) ----------------
__device__ float g_v [NTOK * (HK_*HD_)];
__device__ float g_o [NTOK * DIM_];
__device__ int   g_perm[NTOK];
__device__ int   g_c0;

// 16-bit split buffers (bf16 for GEMM operands; Q/K/V attention buffers hold fp16 bits)
__device__ bf16 g_xh [NTOK*DIM_],      g_xl [NTOK*DIM_];
__device__ bf16 g_wqh[E_*DIM_*HQ_*HD_], g_wql[E_*DIM_*HQ_*HD_];
__device__ bf16 g_wkh[E_*DIM_*HK_*HD_], g_wkl[E_*DIM_*HK_*HD_];
__device__ bf16 g_wvh[E_*DIM_*HK_*HD_], g_wvl[E_*DIM_*HK_*HD_];
__device__ bf16 g_woh[E_*DIM_*HQ_*HD_], g_wol[E_*DIM_*HQ_*HD_];
__device__ bf16 g_qh [NTOK*(HQ_*HD_)],  g_ql [NTOK*(HQ_*HD_)];   // fp16 bits
__device__ bf16 g_kh [NTOK*(HK_*HD_)],  g_kl [NTOK*(HK_*HD_)];   // fp16 bits (lo unused)
__device__ bf16 g_vth[NTOK*(HK_*HD_)];                           // fp16 bits, [b][kvh][d][seq]
__device__ bf16 g_aoh[NTOK*(HQ_*HD_)],  g_aol[NTOK*(HQ_*HD_)];   // bf16 (WO GEMM input)

// =============================== helpers ===============================
__device__ __forceinline__ uint32_t smem_u32(const void* p) {
    uint32_t a;
    asm("{ .reg .u64 t; cvta.to.shared.u64 t, %1; cvt.u32.u64 %0, t; }" : "=r"(a) : "l"(p));
    return a;
}
#define CP_ASYNC16(dst, src) \
    asm volatile("cp.async.cg.shared.global [%0], [%1], 16;" :: "r"(dst), "l"(src) : "memory")
#define CP_COMMIT() asm volatile("cp.async.commit_group;" ::: "memory")
template<int N> __device__ __forceinline__ void cp_wait() {
    asm volatile("cp.async.wait_group %0;" :: "n"(N) : "memory");
}
#define LDSM4(r0,r1,r2,r3, addr) \
    asm volatile("ldmatrix.sync.aligned.m8n8.x4.shared.b16 {%0,%1,%2,%3}, [%4];" \
        : "=r"(r0), "=r"(r1), "=r"(r2), "=r"(r3) : "r"(addr))

__device__ __forceinline__ void bsplit(float x, uint16_t& h, uint16_t& l) {
    bf16 bh = __float2bfloat16_rn(x);
    h = __bfloat16_as_ushort(bh);
    l = __bfloat16_as_ushort(__float2bfloat16_rn(x - __bfloat162float(bh)));
}
__device__ __forceinline__ void hsplit(float x, uint16_t& h, uint16_t& l) {
    __half hh = __float2half_rn(x);
    h = __half_as_ushort(hh);
    l = __half_as_ushort(__float2half_rn(x - __half2float(hh)));
}
__device__ __forceinline__ uint32_t packb(uint16_t lo_elem, uint16_t hi_elem) {
    return (uint32_t)lo_elem | ((uint32_t)hi_elem << 16);
}
__device__ __forceinline__ void mma16816(float* c, const uint32_t* a, const uint32_t* b) {
    asm volatile("mma.sync.aligned.m16n8k16.row.col.f32.bf16.bf16.f32 "
        "{%0,%1,%2,%3}, {%4,%5,%6,%7}, {%8,%9}, {%0,%1,%2,%3};"
        : "+f"(c[0]), "+f"(c[1]), "+f"(c[2]), "+f"(c[3])
        : "r"(a[0]), "r"(a[1]), "r"(a[2]), "r"(a[3]), "r"(b[0]), "r"(b[1]));
}
__device__ __forceinline__ void mma16816h(float* c, const uint32_t* a, const uint32_t* b) {
    asm volatile("mma.sync.aligned.m16n8k16.row.col.f32.f16.f16.f32 "
        "{%0,%1,%2,%3}, {%4,%5,%6,%7}, {%8,%9}, {%0,%1,%2,%3};"
        : "+f"(c[0]), "+f"(c[1]), "+f"(c[2]), "+f"(c[3])
        : "r"(a[0]), "r"(a[1]), "r"(a[2]), "r"(a[3]), "r"(b[0]), "r"(b[1]));
}
__device__ __forceinline__ uint32_t ex2h2(float a, float b) {
    __half2 h = __floats2half2_rn(a, b);
    uint32_t r;
    asm("ex2.approx.f16x2 %0, %1;" : "=r"(r) : "r"(*(uint32_t*)&h));
    return r;
}
__device__ __forceinline__ uint32_t sw256(int r, int off) {
    return (uint32_t)(r*256 + (off ^ ((r & 7) << 4)));
}
__device__ __forceinline__ uint32_t sw64(int r, int clog) {
    return (uint32_t)(r*64 + ((clog ^ (r >> 1)) & 3)*16);
}

// ============================================================================
// sort tokens by modality (stable counting sort), deterministic
// ============================================================================
__global__ __launch_bounds__(1024) void sort_tokens(const int* __restrict__ mod)
{
    __shared__ int s[1024];
    const int tid = threadIdx.x;
    int m[4]; int cnt = 0;
#pragma unroll
    for (int u = 0; u < 4; u++) { m[u] = mod[tid*4 + u]; cnt += (m[u] == 0); }
    s[tid] = cnt;
    __syncthreads();
    for (int off = 1; off < 1024; off <<= 1) {
        int v = (tid >= off) ? s[tid - off] : 0;
        __syncthreads();
        s[tid] += v;
        __syncthreads();
    }
    const int c0 = s[1023];
    if (tid == 0) g_c0 = c0;
    int r0 = s[tid] - cnt;
#pragma unroll
    for (int u = 0; u < 4; u++) {
        int g = tid*4 + u;
        if (m[u] == 0) { g_perm[r0] = g; r0++; }
        else           { g_perm[c0 + g - r0] = g; }
    }
}

// ============================================================================
// elementwise fp32 -> bf16 hi/lo split (for x)
// ============================================================================
__global__ __launch_bounds__(256) void split_f32(
    const float* __restrict__ in, bf16* __restrict__ hi, bf16* __restrict__ lo, int n4)
{
    int i = blockIdx.x * 256 + threadIdx.x;
    if (i >= n4) return;
    float4 v = ((const float4*)in)[i];
    uint16_t hx,lx,hy,ly,hz,lz,hw,lw;
    bsplit(v.x,hx,lx); bsplit(v.y,hy,ly); bsplit(v.z,hz,lz); bsplit(v.w,hw,lw);
    ((uint2*)hi)[i] = make_uint2(packb(hx,hy), packb(hz,hw));
    ((uint2*)lo)[i] = make_uint2(packb(lx,ly), packb(lz,lw));
}

// ============================================================================
// weight transpose-split: W [e][K][NC] fp32 -> T [e][NC][K] bf16 hi/lo
// ============================================================================
__global__ __launch_bounds__(256) void wtrans_split(
    const float* __restrict__ W, bf16* __restrict__ Th, bf16* __restrict__ Tl,
    int K, int NC)
{
    __shared__ float t[32][33];
    const int e  = blockIdx.z;
    const int k0 = blockIdx.x * 32, n0 = blockIdx.y * 32;
    const int tx = threadIdx.x & 31, ty = threadIdx.x >> 5;
    const float* Wp = W + (size_t)e * K * NC;
    for (int r = ty; r < 32; r += 8)
        t[r][tx] = Wp[(size_t)(k0 + r) * NC + n0 + tx];
    __syncthreads();
    bf16* th = Th + (size_t)e * NC * K;
    bf16* tl = Tl + (size_t)e * NC * K;
    for (int r = ty; r < 32; r += 8) {
        float v = t[tx][r];
        uint16_t h, l; bsplit(v, h, l);
        size_t o = (size_t)(n0 + r) * K + k0 + tx;
        th[o] = __ushort_as_bfloat16(h);
        tl[o] = __ushort_as_bfloat16(l);
    }
}

// ============================================================================
// V transpose-split: fp32 -> fp16 (single), [b][kvh][d][seq]
// ============================================================================
__global__ __launch_bounds__(256) void vtrans_half(
    const float* __restrict__ V, bf16* __restrict__ Th)
{
    __shared__ float t[32][33];
    const int s0 = blockIdx.x * 32, d0 = blockIdx.y * 32;
    const int z  = blockIdx.z;                 // b*8 + kvh
    const int b  = z >> 3, kvh = z & 7;
    const int tx = threadIdx.x & 31, ty = threadIdx.x >> 5;
    for (int r = ty; r < 32; r += 8)
        t[r][tx] = V[(size_t)(b*SEQ_ + s0 + r) * (HK_*HD_) + kvh*HD_ + d0 + tx];
    __syncthreads();
    for (int r = ty; r < 32; r += 8) {
        uint16_t h = __half_as_ushort(__float2half_rn(t[tx][r]));
        size_t o = (size_t)(z*HD_ + d0 + r) * SEQ_ + s0 + tx;
        ((uint16_t*)Th)[o] = h;
    }
}

// ============================================================================
// bf16x2 mma.sync GEMM over expert-sorted rows, ldmatrix fragment loads.
// MODE 0: plain fp32 store (V, WO).
// MODE 1: fused RMSNorm+RoPE epilogue, *fp16* hi/lo store (Q, K for attention).
// ============================================================================
#define MM_STAGE 40960          // Ah 10240 | Al | Bh | Bl
#define MM_DSMEM (2*MM_STAGE)

template<int MODE>
__global__ __launch_bounds__(128) void mm_bf16(
    const bf16* __restrict__ Ah, const bf16* __restrict__ Al,
    const bf16* __restrict__ Bh, const bf16* __restrict__ Bl,
    float* __restrict__ Cf,
    bf16* __restrict__ Ch, bf16* __restrict__ Cl,
    const float* __restrict__ normw,
    const float* __restrict__ fcos, const float* __restrict__ fsin,
    int K, int NC)
{
    extern __shared__ char sm[];
    __shared__ int sPerm[128];
    __shared__ float sred[4][64];
    const int tid  = threadIdx.x;
    const int lane = tid & 31;
    const int w    = tid >> 5;
    const int wm64 = (w & 1) * 64;
    const int wn64 = (w >> 1) * 64;
    const int bn   = blockIdx.x * 128;
    const int by   = blockIdx.y;

    const int c0 = g_c0;
    const int T0 = (c0 + 127) >> 7;
    const int T1 = (NTOK - c0 + 127) >> 7;
    if (by >= T0 + T1) return;
    const int e       = (by < T0) ? 0 : 1;
    const int rowbase = e ? (c0 + (by - T0) * 128) : (by * 128);
    const int limit   = e ? NTOK : c0;
    const size_t bofs = (size_t)e * NC * K + (size_t)bn * K;

    {
        int gs = rowbase + tid;
        sPerm[tid] = g_perm[gs < NTOK ? gs : (NTOK - 1)];
    }
    __syncthreads();

    const uint32_t sb = smem_u32(sm);

    auto load_chunk = [&](int cc, int p) {
        const int k0 = cc * 32;
        const uint32_t base = sb + p * MM_STAGE;
#pragma unroll
        for (int i = 0; i < 8; i++) {
            int idx = tid + (i << 7);
            int comp = idx >> 9, rem = idx & 511;
            int r = rem >> 2, c = rem & 3;
            const bf16* src = (comp ? Al : Ah) + (size_t)sPerm[r] * K + k0 + c * 8;
            CP_ASYNC16(base + comp*10240 + (uint32_t)(r*80 + c*16), src);
        }
#pragma unroll
        for (int i = 0; i < 8; i++) {
            int idx = tid + (i << 7);
            int comp = idx >> 9, rem = idx & 511;
            int r = rem >> 2, c = rem & 3;
            const bf16* src = (comp ? Bl : Bh) + bofs + (size_t)r * K + k0 + c * 8;
            CP_ASYNC16(base + 20480 + comp*10240 + (uint32_t)(r*80 + c*16), src);
        }
    };

    float acc[4][8][4];
#pragma unroll
    for (int i = 0; i < 4; i++)
#pragma unroll
        for (int j = 0; j < 8; j++)
#pragma unroll
            for (int q = 0; q < 4; q++) acc[i][j][q] = 0.f;

    const int NCH = K / 32;
    load_chunk(0, 0); CP_COMMIT();
    load_chunk(1, 1); CP_COMMIT();

    const int lr = lane >> 2;
    const int lc = lane & 3;
    const int g8  = lane & 7;
    const int grp = lane >> 3;
    const int a_row = wm64 + (grp & 1) * 8 + g8;
    const int a_ofx = (grp >> 1) * 16;
    const int b_row = wn64 + (grp >> 1) * 8 + g8;
    const int b_ofx = (grp & 1) * 16;

    for (int c = 0; c < NCH; c++) {
        cp_wait<1>();
        __syncthreads();
        const uint32_t bb = sb + (c & 1) * MM_STAGE;
#pragma unroll
        for (int ks = 0; ks < 2; ks++) {
            const uint32_t koff = (uint32_t)(ks * 32);
            uint32_t fah[4][4], fal[4][4];
#pragma unroll
            for (int i = 0; i < 4; i++) {
                uint32_t aaddr = bb + (uint32_t)((a_row + i*16) * 80) + koff + a_ofx;
                LDSM4(fah[i][0], fah[i][1], fah[i][2], fah[i][3], aaddr);
                LDSM4(fal[i][0], fal[i][1], fal[i][2], fal[i][3], aaddr + 10240);
            }
            uint32_t fbh4[4][4], fbl4[4][4];
#pragma unroll
            for (int jj = 0; jj < 4; jj++) {
                uint32_t baddr = bb + 20480 + (uint32_t)((b_row + jj*16) * 80) + koff + b_ofx;
                LDSM4(fbh4[jj][0], fbh4[jj][1], fbh4[jj][2], fbh4[jj][3], baddr);
                LDSM4(fbl4[jj][0], fbl4[jj][1], fbl4[jj][2], fbl4[jj][3], baddr + 10240);
            }
#pragma unroll
            for (int jj = 0; jj < 4; jj++) {
#pragma unroll
                for (int half = 0; half < 2; half++) {
                    const int j = jj*2 + half;
                    uint32_t fbh[2] = { fbh4[jj][half*2], fbh4[jj][half*2+1] };
                    uint32_t fbl[2] = { fbl4[jj][half*2], fbl4[jj][half*2+1] };
#pragma unroll
                    for (int i = 0; i < 4; i++) {
                        mma16816(acc[i][j], fah[i], fbh);
                        mma16816(acc[i][j], fal[i], fbh);
                        mma16816(acc[i][j], fah[i], fbl);
                    }
                }
            }
        }
        __syncthreads();
        if (c + 2 < NCH) load_chunk(c + 2, c & 1);
        CP_COMMIT();
    }

    if (MODE == 0) {
#pragma unroll
        for (int i = 0; i < 4; i++) {
            int lr0 = wm64 + i * 16 + lr;
            bool v0 = (rowbase + lr0)     < limit;
            bool v1 = (rowbase + lr0 + 8) < limit;
            int t0 = v0 ? sPerm[lr0]     : 0;
            int t1 = v1 ? sPerm[lr0 + 8] : 0;
#pragma unroll
            for (int j = 0; j < 8; j++) {
                int cb = bn + wn64 + j * 8 + (lc << 1);
                if (v0) *(float2*)&Cf[(size_t)t0 * NC + cb] = make_float2(acc[i][j][0], acc[i][j][1]);
                if (v1) *(float2*)&Cf[(size_t)t1 * NC + cb] = make_float2(acc[i][j][2], acc[i][j][3]);
            }
        }
    } else {
        float rs[4][2];
#pragma unroll
        for (int i = 0; i < 4; i++) {
            float s0 = 0.f, s1 = 0.f;
#pragma unroll
            for (int j = 0; j < 8; j++) {
                s0 += acc[i][j][0]*acc[i][j][0] + acc[i][j][1]*acc[i][j][1];
                s1 += acc[i][j][2]*acc[i][j][2] + acc[i][j][3]*acc[i][j][3];
            }
            rs[i][0] = s0; rs[i][1] = s1;
        }
#pragma unroll
        for (int i = 0; i < 4; i++) {
#pragma unroll
            for (int hh = 0; hh < 2; hh++) {
                rs[i][hh] += __shfl_xor_sync(0xffffffffu, rs[i][hh], 1);
                rs[i][hh] += __shfl_xor_sync(0xffffffffu, rs[i][hh], 2);
            }
        }
        if (lc == 0) {
#pragma unroll
            for (int i = 0; i < 4; i++) {
                sred[w][i*16 + lr]     = rs[i][0];
                sred[w][i*16 + 8 + lr] = rs[i][1];
            }
        }
        __syncthreads();
        float rinv[4][2];
#pragma unroll
        for (int i = 0; i < 4; i++) {
            float t0 = rs[i][0] + sred[w ^ 2][i*16 + lr];
            float t1 = rs[i][1] + sred[w ^ 2][i*16 + 8 + lr];
            rinv[i][0] = rsqrtf(t0 * (1.0f/HD_) + EPS_);
            rinv[i][1] = rsqrtf(t1 * (1.0f/HD_) + EPS_);
        }
#pragma unroll
        for (int i = 0; i < 4; i++) {
            const int lr0 = wm64 + i * 16 + lr;
            const bool v0 = (rowbase + lr0)     < limit;
            const bool v1 = (rowbase + lr0 + 8) < limit;
            const int t0 = sPerm[lr0], t1 = sPerm[lr0 + 8];
            const int s0 = t0 & (SEQ_-1), s1 = t1 & (SEQ_-1);
#pragma unroll
            for (int j = 0; j < 8; j++) {
                const int col0 = wn64 + j*8 + (lc << 1);
                const float2 nw = *(const float2*)&normw[e*HD_ + col0];
                const int cp = col0 >> 1;
                if (v0) {
                    float a0 = acc[i][j][0] * rinv[i][0] * nw.x;
                    float a1 = acc[i][j][1] * rinv[i][0] * nw.y;
                    float cc = fcos[s0*(HD_/2) + cp], sn = fsin[s0*(HD_/2) + cp];
                    float e0 = a0*cc - a1*sn, e1 = a0*sn + a1*cc;
                    uint16_t h0,l0,h1,l1;
                    hsplit(e0,h0,l0); hsplit(e1,h1,l1);
                    size_t off = (size_t)t0 * NC + bn + col0;
                    *(uint32_t*)((char*)Ch + 2*off) = packb(h0,h1);
                    *(uint32_t*)((char*)Cl + 2*off) = packb(l0,l1);
                }
                if (v1) {
                    float a0 = acc[i][j][2] * rinv[i][1] * nw.x;
                    float a1 = acc[i][j][3] * rinv[i][1] * nw.y;
                    float cc = fcos[s1*(HD_/2) + cp], sn = fsin[s1*(HD_/2) + cp];
                    float e0 = a0*cc - a1*sn, e1 = a0*sn + a1*cc;
                    uint16_t h0,l0,h1,l1;
                    hsplit(e0,h0,l0); hsplit(e1,h1,l1);
                    size_t off = (size_t)t1 * NC + bn + col0;
                    *(uint32_t*)((char*)Ch + 2*off) = packb(h0,h1);
                    *(uint32_t*)((char*)Cl + 2*off) = packb(l0,l1);
                }
            }
        }
    }
}

// ============================================================================
// Tensor-core causal flash attention — fp16 asymmetric + f16x2 exp2 softmax.
// Q: fp16 hi+lo. K/V: single fp16. P: single fp16 produced directly by
// ex2.approx.f16x2 (one MUFU per TWO exps; result == PV A-frag register).
// log2 domain: scores scaled by SCALE*log2e, p = 2^(s2-mn2).
// ============================================================================
#define FQ_H 0
#define FQ_L 16384
#define FK(p) (32768 + (p)*8192)
#define FV(p) (49152 + (p)*8192)
#define FA_BYTES 65536

__global__ __launch_bounds__(128) void flash_attn(
    const bf16* __restrict__ Qh, const bf16* __restrict__ Ql,
    const bf16* __restrict__ Kh,
    const bf16* __restrict__ Vth,
    bf16* __restrict__ AOh, bf16* __restrict__ AOl)
{
    extern __shared__ char sm[];
    const int tid  = threadIdx.x;
    const int lane = tid & 31;
    const int w    = tid >> 5;      // 0..3
    const int lr   = lane >> 2;
    const int lc   = lane & 3;
    const int g8   = lane & 7;
    const int grp  = lane >> 3;

    const int qt = 31 - blockIdx.x;      // big tiles first
    const int h  = blockIdx.y;
    const int b  = blockIdx.z;
    const int kvh   = h >> 1;
    const int qbase = qt * 64;
    const int m0    = w * 16;
    const int niter = 2 * qt + 2;        // kv tiles of 32

    const uint32_t sb = smem_u32(sm);

    const int q_row  = m0 + (grp & 1) * 8 + g8;
    const int q_ofx  = (grp >> 1) * 16;
    const int kv_row = (grp >> 1) * 8 + g8;
    const int kv_ofx = (grp & 1) * 16;
    const int v_clog = grp & 1;

    // ---- Q load (hi+lo), group 0 ----
#pragma unroll
    for (int i = 0; i < 16; i++) {
        int idx = tid + (i << 7);
        int comp = idx >> 10, rem = idx & 1023;
        int r = rem >> 4, c = rem & 15;
        const bf16* src = (comp ? Ql : Qh)
            + (size_t)(b*SEQ_ + qbase + r)*(HQ_*HD_) + h*HD_ + c*8;
        CP_ASYNC16(sb + (comp ? FQ_L : FQ_H) + sw256(r, c*16), src);
    }
    CP_COMMIT();

    auto load_k = [&](int kt, int p) {
#pragma unroll
        for (int i = 0; i < 4; i++) {
            int idx = tid + (i << 7);
            int r = idx >> 4, c = idx & 15;
            const bf16* src = Kh
                + (size_t)(b*SEQ_ + kt*32 + r)*(HK_*HD_) + kvh*HD_ + c*8;
            CP_ASYNC16(sb + FK(p) + sw256(r, c*16), src);
        }
        CP_COMMIT();
    };
    auto load_v = [&](int kt, int p) {
#pragma unroll
        for (int i = 0; i < 4; i++) {
            int idx = tid + (i << 7);
            int r = idx >> 2, c = idx & 3;
            const bf16* src = Vth
                + (size_t)((b*HK_ + kvh)*HD_ + r)*SEQ_ + kt*32 + c*8;
            CP_ASYNC16(sb + FV(p) + sw64(r, c), src);
        }
        CP_COMMIT();
    };

    load_k(0, 0);     // group 1
    load_v(0, 0);     // group 2

    // ---- Q fragments hoisted to registers ----
    cp_wait<2>();     // Q group complete (K0/V0 still in flight)
    __syncthreads();
    uint32_t qfh[8][4], qfl[8][4];
#pragma unroll
    for (int s = 0; s < 8; s++) {
        uint32_t qaddr = sb + FQ_H + sw256(q_row, s*32 + q_ofx);
        LDSM4(qfh[s][0], qfh[s][1], qfh[s][2], qfh[s][3], qaddr);
        LDSM4(qfl[s][0], qfl[s][1], qfl[s][2], qfl[s][3], qaddr + 16384);
    }

    float o[16][4];
#pragma unroll
    for (int j = 0; j < 16; j++)
#pragma unroll
        for (int q = 0; q < 4; q++) o[j][q] = 0.f;
    float mr0 = -1e30f, mr1 = -1e30f, lr0s = 0.f, lr1s = 0.f;

    const int row0g = qbase + m0 + lr;

    for (int kt = 0; kt < niter; kt++) {
        const int p = kt & 1;
        cp_wait<1>();
        __syncthreads();
        if (kt + 1 < niter) { load_k(kt + 1, p ^ 1); load_v(kt + 1, p ^ 1); }

        const uint32_t kh_b = sb + FK(p);

        // ---- S = Q K^T (fp16: qh*kh + ql*kh) ----
        float sa[4][4];
#pragma unroll
        for (int j = 0; j < 4; j++)
#pragma unroll
            for (int q = 0; q < 4; q++) sa[j][q] = 0.f;
#pragma unroll
        for (int s = 0; s < 8; s++) {
            const int b0 = s*32;
#pragma unroll
            for (int jj = 0; jj < 2; jj++) {
                uint32_t fkh4[4];
                uint32_t kaddr = sw256(kv_row + jj*16, b0 + kv_ofx);
                LDSM4(fkh4[0], fkh4[1], fkh4[2], fkh4[3], kh_b + kaddr);
#pragma unroll
                for (int half = 0; half < 2; half++) {
                    const int j = jj*2 + half;
                    uint32_t fkh[2] = { fkh4[half*2], fkh4[half*2+1] };
                    mma16816h(sa[j], qfh[s], fkh);
                    mma16816h(sa[j], qfl[s], fkh);
                }
            }
        }

        // ---- online softmax in log2 domain ----
        const bool need_mask = (kt*32 + 31 > qbase + m0);
        float mx0 = -1e30f, mx1 = -1e30f;
#pragma unroll
        for (int j = 0; j < 4; j++) {
            const int cb = kt*32 + j*8 + 2*lc;
#pragma unroll
            for (int q = 0; q < 4; q++) {
                float v = sa[j][q] * SCL2_;
                if (need_mask) {
                    int col = cb + (q & 1);
                    int row = (q < 2) ? row0g : (row0g + 8);
                    if (col > row) v = -1e30f;
                }
                sa[j][q] = v;
            }
            mx0 = fmaxf(mx0, fmaxf(sa[j][0], sa[j][1]));
            mx1 = fmaxf(mx1, fmaxf(sa[j][2], sa[j][3]));
        }
        mx0 = fmaxf(mx0, __shfl_xor_sync(0xffffffffu, mx0, 1));
        mx0 = fmaxf(mx0, __shfl_xor_sync(0xffffffffu, mx0, 2));
        mx1 = fmaxf(mx1, __shfl_xor_sync(0xffffffffu, mx1, 1));
        mx1 = fmaxf(mx1, __shfl_xor_sync(0xffffffffu, mx1, 2));
        const float mn0 = fmaxf(mr0, mx0);
        const float mn1 = fmaxf(mr1, mx1);
        const float c0 = exp2f(mr0 - mn0);
        const float c1 = exp2f(mr1 - mn1);

        // ---- P = 2^(s2-mn2) via ex2.approx.f16x2; results ARE the A-frags ----
        uint32_t aph[2][4];
        float ps0 = 0.f, ps1 = 0.f;
#pragma unroll
        for (int t = 0; t < 2; t++) {
#pragma unroll
            for (int jj = 0; jj < 2; jj++) {
                const int j = 2*t + jj;
                uint32_t p01 = ex2h2(sa[j][0] - mn0, sa[j][1] - mn0);
                uint32_t p23 = ex2h2(sa[j][2] - mn1, sa[j][3] - mn1);
                aph[t][jj*2 + 0] = p01;
                aph[t][jj*2 + 1] = p23;
                float2 f01 = __half22float2(*(__half2*)&p01);
                float2 f23 = __half22float2(*(__half2*)&p23);
                ps0 += f01.x + f01.y;
                ps1 += f23.x + f23.y;
            }
        }
        ps0 += __shfl_xor_sync(0xffffffffu, ps0, 1);
        ps0 += __shfl_xor_sync(0xffffffffu, ps0, 2);
        ps1 += __shfl_xor_sync(0xffffffffu, ps1, 1);
        ps1 += __shfl_xor_sync(0xffffffffu, ps1, 2);
        lr0s = lr0s * c0 + ps0;
        lr1s = lr1s * c1 + ps1;
        mr0 = mn0; mr1 = mn1;
#pragma unroll
        for (int j = 0; j < 16; j++) {
            o[j][0] *= c0; o[j][1] *= c0;
            o[j][2] *= c1; o[j][3] *= c1;
        }

        // ---- V ready ----
        if (kt + 1 < niter) cp_wait<2>(); else cp_wait<0>();
        __syncthreads();
        const uint32_t vh_b = sb + FV(p);

        // ---- O += P V (single-P fp16 mma) ----
#pragma unroll
        for (int t = 0; t < 2; t++) {
#pragma unroll
            for (int jp = 0; jp < 8; jp++) {
                uint32_t fvh4[4];
                uint32_t vaddr = sw64(kv_row + jp*16, 2*t + v_clog);
                LDSM4(fvh4[0], fvh4[1], fvh4[2], fvh4[3], vh_b + vaddr);
#pragma unroll
                for (int half = 0; half < 2; half++) {
                    const int j = jp*2 + half;
                    uint32_t fvh[2] = { fvh4[half*2], fvh4[half*2+1] };
                    mma16816h(o[j], aph[t], fvh);
                }
            }
        }
    }

    // ---- normalize + bf16 split-store AO (WO GEMM consumes bf16) ----
    const float i0 = 1.f / lr0s;
    const float i1 = 1.f / lr1s;
    const size_t t0 = (size_t)(b*SEQ_ + row0g);
    const size_t t1 = t0 + 8;
#pragma unroll
    for (int j = 0; j < 16; j++) {
        const int col = h*HD_ + j*8 + 2*lc;
        uint16_t h0,l0,h1,l1;
        bsplit(o[j][0]*i0, h0, l0); bsplit(o[j][1]*i0, h1, l1);
        size_t off0 = t0*(HQ_*HD_) + col;
        *(uint32_t*)((char*)AOh + 2*off0) = packb(h0, h1);
        *(uint32_t*)((char*)AOl + 2*off0) = packb(l0, l1);
        bsplit(o[j][2]*i1, h0, l0); bsplit(o[j][3]*i1, h1, l1);
        size_t off1 = t1*(HQ_*HD_) + col;
        *(uint32_t*)((char*)AOh + 2*off1) = packb(h0, h1);
        *(uint32_t*)((char*)AOl + 2*off1) = packb(l0, l1);
    }
}

// ============================================================================
// Final per-token RMSNorm over DIM with attn_norm_w[expert]
// ============================================================================
__global__ __launch_bounds__(256) void final_rms(
    const float* __restrict__ in, const float* __restrict__ w,
    const int* __restrict__ mod, float* __restrict__ out)
{
    const int n = blockIdx.x;
    const int tid = threadIdx.x;
    const int e = mod[n];
    const float* row = in + (size_t)n*DIM_;
    float vals[8];
    float ss = 0.f;
#pragma unroll
    for (int u = 0; u < 8; u++) {
        float v = row[tid + u*256];
        vals[u] = v;
        ss += v*v;
    }
#pragma unroll
    for (int o = 16; o > 0; o >>= 1) ss += __shfl_xor_sync(0xffffffffu, ss, o);
    __shared__ float wsum[8];
    if ((tid & 31) == 0) wsum[tid >> 5] = ss;
    __syncthreads();
    float tot = 0.f;
#pragma unroll
    for (int i = 0; i < 8; i++) tot += wsum[i];
    float r = rsqrtf(tot * (1.0f/DIM_) + EPS_);
#pragma unroll
    for (int u = 0; u < 8; u++)
        out[(size_t)n*DIM_ + tid + u*256] = vals[u] * r * w[e*DIM_ + tid + u*256];
}

// ============================================================================
// launch
// ============================================================================
extern "C" void kernel_launch(void* const* d_in, const int* in_sizes, int n_in,
                              void* d_out, int out_size)
{
    const float* x    = (const float*)d_in[0];
    const float* fcos = (const float*)d_in[1];
    const float* fsin = (const float*)d_in[2];
    const float* wq   = (const float*)d_in[3];
    const float* wk   = (const float*)d_in[4];
    const float* wv   = (const float*)d_in[5];
    const float* wo   = (const float*)d_in[6];
    const float* qnw  = (const float*)d_in[7];
    const float* knw  = (const float*)d_in[8];
    const float* anw  = (const float*)d_in[9];
    const int*   mod  = (const int*)d_in[10];
    float* out = (float*)d_out;

    float *pv, *po;
    bf16 *pxh, *pxl, *pwqh, *pwql, *pwkh, *pwkl, *pwvh, *pwvl, *pwoh, *pwol;
    bf16 *pqh, *pql, *pkh, *pkl, *pvth, *paoh, *paol;
    cudaGetSymbolAddress((void**)&pv,  g_v);
    cudaGetSymbolAddress((void**)&po,  g_o);
    cudaGetSymbolAddress((void**)&pxh, g_xh);  cudaGetSymbolAddress((void**)&pxl, g_xl);
    cudaGetSymbolAddress((void**)&pwqh, g_wqh); cudaGetSymbolAddress((void**)&pwql, g_wql);
    cudaGetSymbolAddress((void**)&pwkh, g_wkh); cudaGetSymbolAddress((void**)&pwkl, g_wkl);
    cudaGetSymbolAddress((void**)&pwvh, g_wvh); cudaGetSymbolAddress((void**)&pwvl, g_wvl);
    cudaGetSymbolAddress((void**)&pwoh, g_woh); cudaGetSymbolAddress((void**)&pwol, g_wol);
    cudaGetSymbolAddress((void**)&pqh, g_qh);   cudaGetSymbolAddress((void**)&pql, g_ql);
    cudaGetSymbolAddress((void**)&pkh, g_kh);   cudaGetSymbolAddress((void**)&pkl, g_kl);
    cudaGetSymbolAddress((void**)&pvth, g_vth);
    cudaGetSymbolAddress((void**)&paoh, g_aoh); cudaGetSymbolAddress((void**)&paol, g_aol);

    cudaFuncSetAttribute(flash_attn, cudaFuncAttributeMaxDynamicSharedMemorySize, FA_BYTES);
    cudaFuncSetAttribute(mm_bf16<0>, cudaFuncAttributeMaxDynamicSharedMemorySize, MM_DSMEM);
    cudaFuncSetAttribute(mm_bf16<1>, cudaFuncAttributeMaxDynamicSharedMemorySize, MM_DSMEM);

    // preprocessing
    sort_tokens<<<1, 1024>>>(mod);
    split_f32<<<(NTOK*DIM_/4 + 255)/256, 256>>>(x, pxh, pxl, NTOK*DIM_/4);
    wtrans_split<<<dim3(64, 64, 2), 256>>>(wq, pwqh, pwql, DIM_, HQ_*HD_);
    wtrans_split<<<dim3(64, 32, 2), 256>>>(wk, pwkh, pwkl, DIM_, HK_*HD_);

    // Q projection GEMM (fused rmsnorm+rope -> fp16 hi/lo)
    mm_bf16<1><<<dim3(16, 33), 128, MM_DSMEM>>>(pxh, pxl, pwqh, pwql,
        nullptr, pqh, pql, qnw, fcos, fsin, DIM_, HQ_*HD_);

    wtrans_split<<<dim3(64, 32, 2), 256>>>(wv, pwvh, pwvl, DIM_, HK_*HD_);
    mm_bf16<1><<<dim3( 8, 33), 128, MM_DSMEM>>>(pxh, pxl, pwkh, pwkl,
        nullptr, pkh, pkl, knw, fcos, fsin, DIM_, HK_*HD_);
    mm_bf16<0><<<dim3( 8, 33), 128, MM_DSMEM>>>(pxh, pxl, pwvh, pwvl,
        pv, nullptr, nullptr, nullptr, nullptr, nullptr, DIM_, HK_*HD_);
    vtrans_half<<<dim3(64, 4, 16), 256>>>(pv, pvth);
    wtrans_split<<<dim3(64, 64, 2), 256>>>(wo, pwoh, pwol, HQ_*HD_, DIM_);

    // attention (fp16 asymmetric, f16x2 exp2 softmax)
    flash_attn<<<dim3(32, HQ_, BS_), 128, FA_BYTES>>>(pqh, pql, pkh, pvth, paoh, paol);

    // output projection + final rmsnorm
    mm_bf16<0><<<dim3(16, 33), 128, MM_DSMEM>>>(paoh, paol, pwoh, pwol,
        po, nullptr, nullptr, nullptr, nullptr, nullptr, HQ_*HD_, DIM_);
    final_rms<<<NTOK, 256>>>(po, anw, mod, out);
}

// round 16
// speedup vs baseline: 1.1772x; 1.0248x over previous
#include <cuda_runtime.h>
#include <cuda_bf16.h>
#include <cuda_fp16.h>
#include <math.h>
#include <cstdint>

// ---------------- problem constants ----------------
#define E_   2
#define HQ_  16
#define HK_  8
#define HD_  128
#define DIM_ 2048
#define BS_  2
#define SEQ_ 2048
#define NTOK (BS_*SEQ_)          // 4096
#define EPS_ 1e-6f
#define SCALE_ 0.08838834764831845f   // 1/sqrt(128)
#define SCL2_  0.12754217f            // SCALE_ * log2(e)

typedef __nv_bfloat16 bf16;

// ---------------- scratch (device globals) ----------------
__device__ float g_v [NTOK * (HK_*HD_)];
__device__ float g_o [NTOK * DIM_];
__device__ int   g_perm[NTOK];
__device__ int   g_c0;

// 16-bit split buffers (bf16 for GEMM operands; Q/K/V attention buffers hold fp16 bits)
__device__ bf16 g_xh [NTOK*DIM_],      g_xl [NTOK*DIM_];
__device__ bf16 g_wqh[E_*DIM_*HQ_*HD_], g_wql[E_*DIM_*HQ_*HD_];
__device__ bf16 g_wkh[E_*DIM_*HK_*HD_], g_wkl[E_*DIM_*HK_*HD_];
__device__ bf16 g_wvh[E_*DIM_*HK_*HD_], g_wvl[E_*DIM_*HK_*HD_];
__device__ bf16 g_woh[E_*DIM_*HQ_*HD_], g_wol[E_*DIM_*HQ_*HD_];
__device__ bf16 g_qh [NTOK*(HQ_*HD_)],  g_ql [NTOK*(HQ_*HD_)];   // fp16 bits
__device__ bf16 g_kh [NTOK*(HK_*HD_)],  g_kl [NTOK*(HK_*HD_)];   // fp16 bits (lo unused)
__device__ bf16 g_vth[NTOK*(HK_*HD_)];                           // fp16 bits, [b][kvh][d][seq]
__device__ bf16 g_aoh[NTOK*(HQ_*HD_)],  g_aol[NTOK*(HQ_*HD_)];   // bf16 (WO GEMM input)

// =============================== helpers ===============================
__device__ __forceinline__ uint32_t smem_u32(const void* p) {
    uint32_t a;
    asm("{ .reg .u64 t; cvta.to.shared.u64 t, %1; cvt.u32.u64 %0, t; }" : "=r"(a) : "l"(p));
    return a;
}
#define CP_ASYNC16(dst, src) \
    asm volatile("cp.async.cg.shared.global [%0], [%1], 16;" :: "r"(dst), "l"(src) : "memory")
#define CP_COMMIT() asm volatile("cp.async.commit_group;" ::: "memory")
template<int N> __device__ __forceinline__ void cp_wait() {
    asm volatile("cp.async.wait_group %0;" :: "n"(N) : "memory");
}
#define LDSM4(r0,r1,r2,r3, addr) \
    asm volatile("ldmatrix.sync.aligned.m8n8.x4.shared.b16 {%0,%1,%2,%3}, [%4];" \
        : "=r"(r0), "=r"(r1), "=r"(r2), "=r"(r3) : "r"(addr))

__device__ __forceinline__ void bsplit(float x, uint16_t& h, uint16_t& l) {
    bf16 bh = __float2bfloat16_rn(x);
    h = __bfloat16_as_ushort(bh);
    l = __bfloat16_as_ushort(__float2bfloat16_rn(x - __bfloat162float(bh)));
}
__device__ __forceinline__ void hsplit(float x, uint16_t& h, uint16_t& l) {
    __half hh = __float2half_rn(x);
    h = __half_as_ushort(hh);
    l = __half_as_ushort(__float2half_rn(x - __half2float(hh)));
}
__device__ __forceinline__ uint32_t packb(uint16_t lo_elem, uint16_t hi_elem) {
    return (uint32_t)lo_elem | ((uint32_t)hi_elem << 16);
}
__device__ __forceinline__ void mma16816(float* c, const uint32_t* a, const uint32_t* b) {
    asm volatile("mma.sync.aligned.m16n8k16.row.col.f32.bf16.bf16.f32 "
        "{%0,%1,%2,%3}, {%4,%5,%6,%7}, {%8,%9}, {%0,%1,%2,%3};"
        : "+f"(c[0]), "+f"(c[1]), "+f"(c[2]), "+f"(c[3])
        : "r"(a[0]), "r"(a[1]), "r"(a[2]), "r"(a[3]), "r"(b[0]), "r"(b[1]));
}
__device__ __forceinline__ void mma16816h(float* c, const uint32_t* a, const uint32_t* b) {
    asm volatile("mma.sync.aligned.m16n8k16.row.col.f32.f16.f16.f32 "
        "{%0,%1,%2,%3}, {%4,%5,%6,%7}, {%8,%9}, {%0,%1,%2,%3};"
        : "+f"(c[0]), "+f"(c[1]), "+f"(c[2]), "+f"(c[3])
        : "r"(a[0]), "r"(a[1]), "r"(a[2]), "r"(a[3]), "r"(b[0]), "r"(b[1]));
}
__device__ __forceinline__ uint32_t ex2h2(float a, float b) {
    __half2 h = __floats2half2_rn(a, b);
    uint32_t r;
    asm("ex2.approx.f16x2 %0, %1;" : "=r"(r) : "r"(*(uint32_t*)&h));
    return r;
}
__device__ __forceinline__ uint32_t sw256(int r, int off) {
    return (uint32_t)(r*256 + (off ^ ((r & 7) << 4)));
}
__device__ __forceinline__ uint32_t sw128(int r, int off) {
    return (uint32_t)(r*128 + (off ^ ((r & 7) << 4)));
}

// ============================================================================
// sort tokens by modality (stable counting sort), deterministic
// ============================================================================
__global__ __launch_bounds__(1024) void sort_tokens(const int* __restrict__ mod)
{
    __shared__ int s[1024];
    const int tid = threadIdx.x;
    int m[4]; int cnt = 0;
#pragma unroll
    for (int u = 0; u < 4; u++) { m[u] = mod[tid*4 + u]; cnt += (m[u] == 0); }
    s[tid] = cnt;
    __syncthreads();
    for (int off = 1; off < 1024; off <<= 1) {
        int v = (tid >= off) ? s[tid - off] : 0;
        __syncthreads();
        s[tid] += v;
        __syncthreads();
    }
    const int c0 = s[1023];
    if (tid == 0) g_c0 = c0;
    int r0 = s[tid] - cnt;
#pragma unroll
    for (int u = 0; u < 4; u++) {
        int g = tid*4 + u;
        if (m[u] == 0) { g_perm[r0] = g; r0++; }
        else           { g_perm[c0 + g - r0] = g; }
    }
}

// ============================================================================
// elementwise fp32 -> bf16 hi/lo split (for x)
// ============================================================================
__global__ __launch_bounds__(256) void split_f32(
    const float* __restrict__ in, bf16* __restrict__ hi, bf16* __restrict__ lo, int n4)
{
    int i = blockIdx.x * 256 + threadIdx.x;
    if (i >= n4) return;
    float4 v = ((const float4*)in)[i];
    uint16_t hx,lx,hy,ly,hz,lz,hw,lw;
    bsplit(v.x,hx,lx); bsplit(v.y,hy,ly); bsplit(v.z,hz,lz); bsplit(v.w,hw,lw);
    ((uint2*)hi)[i] = make_uint2(packb(hx,hy), packb(hz,hw));
    ((uint2*)lo)[i] = make_uint2(packb(lx,ly), packb(lz,lw));
}

// ============================================================================
// weight transpose-split: W [e][K][NC] fp32 -> T [e][NC][K] bf16 hi/lo
// ============================================================================
__global__ __launch_bounds__(256) void wtrans_split(
    const float* __restrict__ W, bf16* __restrict__ Th, bf16* __restrict__ Tl,
    int K, int NC)
{
    __shared__ float t[32][33];
    const int e  = blockIdx.z;
    const int k0 = blockIdx.x * 32, n0 = blockIdx.y * 32;
    const int tx = threadIdx.x & 31, ty = threadIdx.x >> 5;
    const float* Wp = W + (size_t)e * K * NC;
    for (int r = ty; r < 32; r += 8)
        t[r][tx] = Wp[(size_t)(k0 + r) * NC + n0 + tx];
    __syncthreads();
    bf16* th = Th + (size_t)e * NC * K;
    bf16* tl = Tl + (size_t)e * NC * K;
    for (int r = ty; r < 32; r += 8) {
        float v = t[tx][r];
        uint16_t h, l; bsplit(v, h, l);
        size_t o = (size_t)(n0 + r) * K + k0 + tx;
        th[o] = __ushort_as_bfloat16(h);
        tl[o] = __ushort_as_bfloat16(l);
    }
}

// ============================================================================
// V transpose-split: fp32 -> fp16 (single), [b][kvh][d][seq]
// ============================================================================
__global__ __launch_bounds__(256) void vtrans_half(
    const float* __restrict__ V, bf16* __restrict__ Th)
{
    __shared__ float t[32][33];
    const int s0 = blockIdx.x * 32, d0 = blockIdx.y * 32;
    const int z  = blockIdx.z;                 // b*8 + kvh
    const int b  = z >> 3, kvh = z & 7;
    const int tx = threadIdx.x & 31, ty = threadIdx.x >> 5;
    for (int r = ty; r < 32; r += 8)
        t[r][tx] = V[(size_t)(b*SEQ_ + s0 + r) * (HK_*HD_) + kvh*HD_ + d0 + tx];
    __syncthreads();
    for (int r = ty; r < 32; r += 8) {
        uint16_t h = __half_as_ushort(__float2half_rn(t[tx][r]));
        size_t o = (size_t)(z*HD_ + d0 + r) * SEQ_ + s0 + tx;
        ((uint16_t*)Th)[o] = h;
    }
}

// ============================================================================
// bf16x2 mma.sync GEMM over expert-sorted rows, ldmatrix fragment loads.
// MODE 0: plain fp32 store (V, WO).
// MODE 1: fused RMSNorm+RoPE epilogue, fp16 hi/lo store (Q, K for attention).
// (unchanged — protected win)
// ============================================================================
#define MM_STAGE 40960          // Ah 10240 | Al | Bh | Bl
#define MM_DSMEM (2*MM_STAGE)

template<int MODE>
__global__ __launch_bounds__(128) void mm_bf16(
    const bf16* __restrict__ Ah, const bf16* __restrict__ Al,
    const bf16* __restrict__ Bh, const bf16* __restrict__ Bl,
    float* __restrict__ Cf,
    bf16* __restrict__ Ch, bf16* __restrict__ Cl,
    const float* __restrict__ normw,
    const float* __restrict__ fcos, const float* __restrict__ fsin,
    int K, int NC)
{
    extern __shared__ char sm[];
    __shared__ int sPerm[128];
    __shared__ float sred[4][64];
    const int tid  = threadIdx.x;
    const int lane = tid & 31;
    const int w    = tid >> 5;
    const int wm64 = (w & 1) * 64;
    const int wn64 = (w >> 1) * 64;
    const int bn   = blockIdx.x * 128;
    const int by   = blockIdx.y;

    const int c0 = g_c0;
    const int T0 = (c0 + 127) >> 7;
    const int T1 = (NTOK - c0 + 127) >> 7;
    if (by >= T0 + T1) return;
    const int e       = (by < T0) ? 0 : 1;
    const int rowbase = e ? (c0 + (by - T0) * 128) : (by * 128);
    const int limit   = e ? NTOK : c0;
    const size_t bofs = (size_t)e * NC * K + (size_t)bn * K;

    {
        int gs = rowbase + tid;
        sPerm[tid] = g_perm[gs < NTOK ? gs : (NTOK - 1)];
    }
    __syncthreads();

    const uint32_t sb = smem_u32(sm);

    auto load_chunk = [&](int cc, int p) {
        const int k0 = cc * 32;
        const uint32_t base = sb + p * MM_STAGE;
#pragma unroll
        for (int i = 0; i < 8; i++) {
            int idx = tid + (i << 7);
            int comp = idx >> 9, rem = idx & 511;
            int r = rem >> 2, c = rem & 3;
            const bf16* src = (comp ? Al : Ah) + (size_t)sPerm[r] * K + k0 + c * 8;
            CP_ASYNC16(base + comp*10240 + (uint32_t)(r*80 + c*16), src);
        }
#pragma unroll
        for (int i = 0; i < 8; i++) {
            int idx = tid + (i << 7);
            int comp = idx >> 9, rem = idx & 511;
            int r = rem >> 2, c = rem & 3;
            const bf16* src = (comp ? Bl : Bh) + bofs + (size_t)r * K + k0 + c * 8;
            CP_ASYNC16(base + 20480 + comp*10240 + (uint32_t)(r*80 + c*16), src);
        }
    };

    float acc[4][8][4];
#pragma unroll
    for (int i = 0; i < 4; i++)
#pragma unroll
        for (int j = 0; j < 8; j++)
#pragma unroll
            for (int q = 0; q < 4; q++) acc[i][j][q] = 0.f;

    const int NCH = K / 32;
    load_chunk(0, 0); CP_COMMIT();
    load_chunk(1, 1); CP_COMMIT();

    const int lr = lane >> 2;
    const int lc = lane & 3;
    const int g8  = lane & 7;
    const int grp = lane >> 3;
    const int a_row = wm64 + (grp & 1) * 8 + g8;
    const int a_ofx = (grp >> 1) * 16;
    const int b_row = wn64 + (grp >> 1) * 8 + g8;
    const int b_ofx = (grp & 1) * 16;

    for (int c = 0; c < NCH; c++) {
        cp_wait<1>();
        __syncthreads();
        const uint32_t bb = sb + (c & 1) * MM_STAGE;
#pragma unroll
        for (int ks = 0; ks < 2; ks++) {
            const uint32_t koff = (uint32_t)(ks * 32);
            uint32_t fah[4][4], fal[4][4];
#pragma unroll
            for (int i = 0; i < 4; i++) {
                uint32_t aaddr = bb + (uint32_t)((a_row + i*16) * 80) + koff + a_ofx;
                LDSM4(fah[i][0], fah[i][1], fah[i][2], fah[i][3], aaddr);
                LDSM4(fal[i][0], fal[i][1], fal[i][2], fal[i][3], aaddr + 10240);
            }
            uint32_t fbh4[4][4], fbl4[4][4];
#pragma unroll
            for (int jj = 0; jj < 4; jj++) {
                uint32_t baddr = bb + 20480 + (uint32_t)((b_row + jj*16) * 80) + koff + b_ofx;
                LDSM4(fbh4[jj][0], fbh4[jj][1], fbh4[jj][2], fbh4[jj][3], baddr);
                LDSM4(fbl4[jj][0], fbl4[jj][1], fbl4[jj][2], fbl4[jj][3], baddr + 10240);
            }
#pragma unroll
            for (int jj = 0; jj < 4; jj++) {
#pragma unroll
                for (int half = 0; half < 2; half++) {
                    const int j = jj*2 + half;
                    uint32_t fbh[2] = { fbh4[jj][half*2], fbh4[jj][half*2+1] };
                    uint32_t fbl[2] = { fbl4[jj][half*2], fbl4[jj][half*2+1] };
#pragma unroll
                    for (int i = 0; i < 4; i++) {
                        mma16816(acc[i][j], fah[i], fbh);
                        mma16816(acc[i][j], fal[i], fbh);
                        mma16816(acc[i][j], fah[i], fbl);
                    }
                }
            }
        }
        __syncthreads();
        if (c + 2 < NCH) load_chunk(c + 2, c & 1);
        CP_COMMIT();
    }

    if (MODE == 0) {
#pragma unroll
        for (int i = 0; i < 4; i++) {
            int lr0 = wm64 + i * 16 + lr;
            bool v0 = (rowbase + lr0)     < limit;
            bool v1 = (rowbase + lr0 + 8) < limit;
            int t0 = v0 ? sPerm[lr0]     : 0;
            int t1 = v1 ? sPerm[lr0 + 8] : 0;
#pragma unroll
            for (int j = 0; j < 8; j++) {
                int cb = bn + wn64 + j * 8 + (lc << 1);
                if (v0) *(float2*)&Cf[(size_t)t0 * NC + cb] = make_float2(acc[i][j][0], acc[i][j][1]);
                if (v1) *(float2*)&Cf[(size_t)t1 * NC + cb] = make_float2(acc[i][j][2], acc[i][j][3]);
            }
        }
    } else {
        float rs[4][2];
#pragma unroll
        for (int i = 0; i < 4; i++) {
            float s0 = 0.f, s1 = 0.f;
#pragma unroll
            for (int j = 0; j < 8; j++) {
                s0 += acc[i][j][0]*acc[i][j][0] + acc[i][j][1]*acc[i][j][1];
                s1 += acc[i][j][2]*acc[i][j][2] + acc[i][j][3]*acc[i][j][3];
            }
            rs[i][0] = s0; rs[i][1] = s1;
        }
#pragma unroll
        for (int i = 0; i < 4; i++) {
#pragma unroll
            for (int hh = 0; hh < 2; hh++) {
                rs[i][hh] += __shfl_xor_sync(0xffffffffu, rs[i][hh], 1);
                rs[i][hh] += __shfl_xor_sync(0xffffffffu, rs[i][hh], 2);
            }
        }
        if (lc == 0) {
#pragma unroll
            for (int i = 0; i < 4; i++) {
                sred[w][i*16 + lr]     = rs[i][0];
                sred[w][i*16 + 8 + lr] = rs[i][1];
            }
        }
        __syncthreads();
        float rinv[4][2];
#pragma unroll
        for (int i = 0; i < 4; i++) {
            float t0 = rs[i][0] + sred[w ^ 2][i*16 + lr];
            float t1 = rs[i][1] + sred[w ^ 2][i*16 + 8 + lr];
            rinv[i][0] = rsqrtf(t0 * (1.0f/HD_) + EPS_);
            rinv[i][1] = rsqrtf(t1 * (1.0f/HD_) + EPS_);
        }
#pragma unroll
        for (int i = 0; i < 4; i++) {
            const int lr0 = wm64 + i * 16 + lr;
            const bool v0 = (rowbase + lr0)     < limit;
            const bool v1 = (rowbase + lr0 + 8) < limit;
            const int t0 = sPerm[lr0], t1 = sPerm[lr0 + 8];
            const int s0 = t0 & (SEQ_-1), s1 = t1 & (SEQ_-1);
#pragma unroll
            for (int j = 0; j < 8; j++) {
                const int col0 = wn64 + j*8 + (lc << 1);
                const float2 nw = *(const float2*)&normw[e*HD_ + col0];
                const int cp = col0 >> 1;
                if (v0) {
                    float a0 = acc[i][j][0] * rinv[i][0] * nw.x;
                    float a1 = acc[i][j][1] * rinv[i][0] * nw.y;
                    float cc = fcos[s0*(HD_/2) + cp], sn = fsin[s0*(HD_/2) + cp];
                    float e0 = a0*cc - a1*sn, e1 = a0*sn + a1*cc;
                    uint16_t h0,l0,h1,l1;
                    hsplit(e0,h0,l0); hsplit(e1,h1,l1);
                    size_t off = (size_t)t0 * NC + bn + col0;
                    *(uint32_t*)((char*)Ch + 2*off) = packb(h0,h1);
                    *(uint32_t*)((char*)Cl + 2*off) = packb(l0,l1);
                }
                if (v1) {
                    float a0 = acc[i][j][2] * rinv[i][1] * nw.x;
                    float a1 = acc[i][j][3] * rinv[i][1] * nw.y;
                    float cc = fcos[s1*(HD_/2) + cp], sn = fsin[s1*(HD_/2) + cp];
                    float e0 = a0*cc - a1*sn, e1 = a0*sn + a1*cc;
                    uint16_t h0,l0,h1,l1;
                    hsplit(e0,h0,l0); hsplit(e1,h1,l1);
                    size_t off = (size_t)t1 * NC + bn + col0;
                    *(uint32_t*)((char*)Ch + 2*off) = packb(h0,h1);
                    *(uint32_t*)((char*)Cl + 2*off) = packb(l0,l1);
                }
            }
        }
    }
}

// ============================================================================
// Tensor-core causal flash attention — fp16 asymmetric + f16x2 exp2 softmax.
// kv tiles of 64 (halved per-iter fixed costs). Row-sum l computed by the PV
// mma via a register-constant "ones" B-fragment (V|1 trick): o[16] = sum p,
// with online corrections applied by the same o-rescale. No ps reductions.
// smem 96KB: Qh 16K | Ql 16K | K[2] 16K ea | V[2] 16K ea  -> 2 CTAs/SM.
// ============================================================================
#define FQ_H 0
#define FQ_L 16384
#define FK(p) (32768 + (p)*16384)
#define FV(p) (65536 + (p)*16384)
#define FA_BYTES 98304

__global__ __launch_bounds__(128) void flash_attn(
    const bf16* __restrict__ Qh, const bf16* __restrict__ Ql,
    const bf16* __restrict__ Kh,
    const bf16* __restrict__ Vth,
    bf16* __restrict__ AOh, bf16* __restrict__ AOl)
{
    extern __shared__ char sm[];
    const int tid  = threadIdx.x;
    const int lane = tid & 31;
    const int w    = tid >> 5;      // 0..3
    const int lr   = lane >> 2;
    const int lc   = lane & 3;
    const int g8   = lane & 7;
    const int grp  = lane >> 3;

    const int qt = 31 - blockIdx.x;      // big tiles first
    const int h  = blockIdx.y;
    const int b  = blockIdx.z;
    const int kvh   = h >> 1;
    const int qbase = qt * 64;
    const int m0    = w * 16;
    const int niter = qt + 1;            // kv tiles of 64

    const uint32_t sb = smem_u32(sm);

    const int q_row  = m0 + (grp & 1) * 8 + g8;
    const int q_ofx  = (grp >> 1) * 16;
    const int kv_row = (grp >> 1) * 8 + g8;
    const int kv_ofx = (grp & 1) * 16;

    // ones B-frag for the virtual V column of 1s (n_local==0 <=> lr==0)
    const uint32_t onesf = (lr == 0) ? 0x3C003C00u : 0u;
    const uint32_t ones2[2] = { onesf, onesf };

    // ---- Q load (hi+lo), group 0 ----
#pragma unroll
    for (int i = 0; i < 16; i++) {
        int idx = tid + (i << 7);
        int comp = idx >> 10, rem = idx & 1023;
        int r = rem >> 4, c = rem & 15;
        const bf16* src = (comp ? Ql : Qh)
            + (size_t)(b*SEQ_ + qbase + r)*(HQ_*HD_) + h*HD_ + c*8;
        CP_ASYNC16(sb + (comp ? FQ_L : FQ_H) + sw256(r, c*16), src);
    }
    CP_COMMIT();

    auto load_k = [&](int kt, int p) {
#pragma unroll
        for (int i = 0; i < 8; i++) {         // 64 rows x 16 chunks
            int idx = tid + (i << 7);
            int r = idx >> 4, c = idx & 15;
            const bf16* src = Kh
                + (size_t)(b*SEQ_ + kt*64 + r)*(HK_*HD_) + kvh*HD_ + c*8;
            CP_ASYNC16(sb + FK(p) + sw256(r, c*16), src);
        }
        CP_COMMIT();
    };
    auto load_v = [&](int kt, int p) {
#pragma unroll
        for (int i = 0; i < 8; i++) {         // 128 d-rows x 8 chunks (128B rows)
            int idx = tid + (i << 7);
            int r = idx >> 3, c = idx & 7;
            const bf16* src = Vth
                + (size_t)((b*HK_ + kvh)*HD_ + r)*SEQ_ + kt*64 + c*8;
            CP_ASYNC16(sb + FV(p) + sw128(r, c*16), src);
        }
        CP_COMMIT();
    };

    load_k(0, 0);     // group 1
    load_v(0, 0);     // group 2

    // ---- Q fragments hoisted to registers ----
    cp_wait<2>();     // Q group complete (K0/V0 still in flight)
    __syncthreads();
    uint32_t qfh[8][4], qfl[8][4];
#pragma unroll
    for (int s = 0; s < 8; s++) {
        uint32_t qaddr = sb + FQ_H + sw256(q_row, s*32 + q_ofx);
        LDSM4(qfh[s][0], qfh[s][1], qfh[s][2], qfh[s][3], qaddr);
        LDSM4(qfl[s][0], qfl[s][1], qfl[s][2], qfl[s][3], qaddr + 16384);
    }

    float o[17][4];   // o[16] accumulates row sums (V|1 trick)
#pragma unroll
    for (int j = 0; j < 17; j++)
#pragma unroll
        for (int q = 0; q < 4; q++) o[j][q] = 0.f;
    float mr0 = -1e30f, mr1 = -1e30f;

    const int row0g = qbase + m0 + lr;

    for (int kt = 0; kt < niter; kt++) {
        const int p = kt & 1;
        cp_wait<1>();
        __syncthreads();
        if (kt + 1 < niter) { load_k(kt + 1, p ^ 1); load_v(kt + 1, p ^ 1); }

        const uint32_t kh_b = sb + FK(p);

        // ---- S = Q K^T (fp16: qh*kh + ql*kh), n=64 ----
        float sa[8][4];
#pragma unroll
        for (int j = 0; j < 8; j++)
#pragma unroll
            for (int q = 0; q < 4; q++) sa[j][q] = 0.f;
#pragma unroll
        for (int s = 0; s < 8; s++) {
            const int b0 = s*32;
#pragma unroll
            for (int jj = 0; jj < 4; jj++) {
                uint32_t fkh4[4];
                uint32_t kaddr = sw256(kv_row + jj*16, b0 + kv_ofx);
                LDSM4(fkh4[0], fkh4[1], fkh4[2], fkh4[3], kh_b + kaddr);
#pragma unroll
                for (int half = 0; half < 2; half++) {
                    const int j = jj*2 + half;
                    uint32_t fkh[2] = { fkh4[half*2], fkh4[half*2+1] };
                    mma16816h(sa[j], qfh[s], fkh);
                    mma16816h(sa[j], qfl[s], fkh);
                }
            }
        }

        // ---- online softmax in log2 domain ----
        const bool need_mask = (kt*64 + 63 > qbase + m0);
        float mx0 = -1e30f, mx1 = -1e30f;
#pragma unroll
        for (int j = 0; j < 8; j++) {
            const int cb = kt*64 + j*8 + 2*lc;
#pragma unroll
            for (int q = 0; q < 4; q++) {
                float v = sa[j][q] * SCL2_;
                if (need_mask) {
                    int col = cb + (q & 1);
                    int row = (q < 2) ? row0g : (row0g + 8);
                    if (col > row) v = -1e30f;
                }
                sa[j][q] = v;
            }
            mx0 = fmaxf(mx0, fmaxf(sa[j][0], sa[j][1]));
            mx1 = fmaxf(mx1, fmaxf(sa[j][2], sa[j][3]));
        }
        mx0 = fmaxf(mx0, __shfl_xor_sync(0xffffffffu, mx0, 1));
        mx0 = fmaxf(mx0, __shfl_xor_sync(0xffffffffu, mx0, 2));
        mx1 = fmaxf(mx1, __shfl_xor_sync(0xffffffffu, mx1, 1));
        mx1 = fmaxf(mx1, __shfl_xor_sync(0xffffffffu, mx1, 2));
        const float mn0 = fmaxf(mr0, mx0);
        const float mn1 = fmaxf(mr1, mx1);
        const float c0 = exp2f(mr0 - mn0);
        const float c1 = exp2f(mr1 - mn1);
        mr0 = mn0; mr1 = mn1;

        // ---- P = 2^(s-mn) via ex2.approx.f16x2; results ARE the A-frags ----
        uint32_t aph[4][4];
#pragma unroll
        for (int t = 0; t < 4; t++) {
            aph[t][0] = ex2h2(sa[2*t][0]   - mn0, sa[2*t][1]   - mn0);
            aph[t][1] = ex2h2(sa[2*t][2]   - mn1, sa[2*t][3]   - mn1);
            aph[t][2] = ex2h2(sa[2*t+1][0] - mn0, sa[2*t+1][1] - mn0);
            aph[t][3] = ex2h2(sa[2*t+1][2] - mn1, sa[2*t+1][3] - mn1);
        }

        // ---- rescale o (includes the running row-sum in o[16]) ----
#pragma unroll
        for (int j = 0; j < 17; j++) {
            o[j][0] *= c0; o[j][1] *= c0;
            o[j][2] *= c1; o[j][3] *= c1;
        }

        // ---- V ready ----
        if (kt + 1 < niter) cp_wait<2>(); else cp_wait<0>();
        __syncthreads();
        const uint32_t vh_b = sb + FV(p);

        // ---- O += P V ; row sums += P * 1 (register-constant B-frag) ----
#pragma unroll
        for (int t = 0; t < 4; t++) {
            const int b0 = t*32;
#pragma unroll
            for (int jp = 0; jp < 8; jp++) {
                uint32_t fvh4[4];
                uint32_t vaddr = sw128(kv_row + jp*16, b0 + kv_ofx);
                LDSM4(fvh4[0], fvh4[1], fvh4[2], fvh4[3], vh_b + vaddr);
#pragma unroll
                for (int half = 0; half < 2; half++) {
                    const int j = jp*2 + half;
                    uint32_t fvh[2] = { fvh4[half*2], fvh4[half*2+1] };
                    mma16816h(o[j], aph[t], fvh);
                }
            }
            mma16816h(o[16], aph[t], ones2);
        }
    }

    // ---- broadcast row sums from lc==0, normalize + bf16 split-store ----
    const float l0 = __shfl_sync(0xffffffffu, o[16][0], lane & ~3);
    const float l1 = __shfl_sync(0xffffffffu, o[16][2], lane & ~3);
    const float i0 = 1.f / l0;
    const float i1 = 1.f / l1;
    const size_t t0 = (size_t)(b*SEQ_ + row0g);
    const size_t t1 = t0 + 8;
#pragma unroll
    for (int j = 0; j < 16; j++) {
        const int col = h*HD_ + j*8 + 2*lc;
        uint16_t h0,l0u,h1,l1u;
        bsplit(o[j][0]*i0, h0, l0u); bsplit(o[j][1]*i0, h1, l1u);
        size_t off0 = t0*(HQ_*HD_) + col;
        *(uint32_t*)((char*)AOh + 2*off0) = packb(h0, h1);
        *(uint32_t*)((char*)AOl + 2*off0) = packb(l0u, l1u);
        bsplit(o[j][2]*i1, h0, l0u); bsplit(o[j][3]*i1, h1, l1u);
        size_t off1 = t1*(HQ_*HD_) + col;
        *(uint32_t*)((char*)AOh + 2*off1) = packb(h0, h1);
        *(uint32_t*)((char*)AOl + 2*off1) = packb(l0u, l1u);
    }
}

// ============================================================================
// Final per-token RMSNorm over DIM with attn_norm_w[expert]
// ============================================================================
__global__ __launch_bounds__(256) void final_rms(
    const float* __restrict__ in, const float* __restrict__ w,
    const int* __restrict__ mod, float* __restrict__ out)
{
    const int n = blockIdx.x;
    const int tid = threadIdx.x;
    const int e = mod[n];
    const float* row = in + (size_t)n*DIM_;
    float vals[8];
    float ss = 0.f;
#pragma unroll
    for (int u = 0; u < 8; u++) {
        float v = row[tid + u*256];
        vals[u] = v;
        ss += v*v;
    }
#pragma unroll
    for (int o = 16; o > 0; o >>= 1) ss += __shfl_xor_sync(0xffffffffu, ss, o);
    __shared__ float wsum[8];
    if ((tid & 31) == 0) wsum[tid >> 5] = ss;
    __syncthreads();
    float tot = 0.f;
#pragma unroll
    for (int i = 0; i < 8; i++) tot += wsum[i];
    float r = rsqrtf(tot * (1.0f/DIM_) + EPS_);
#pragma unroll
    for (int u = 0; u < 8; u++)
        out[(size_t)n*DIM_ + tid + u*256] = vals[u] * r * w[e*DIM_ + tid + u*256];
}

// ============================================================================
// launch
// ============================================================================
extern "C" void kernel_launch(void* const* d_in, const int* in_sizes, int n_in,
                              void* d_out, int out_size)
{
    const float* x    = (const float*)d_in[0];
    const float* fcos = (const float*)d_in[1];
    const float* fsin = (const float*)d_in[2];
    const float* wq   = (const float*)d_in[3];
    const float* wk   = (const float*)d_in[4];
    const float* wv   = (const float*)d_in[5];
    const float* wo   = (const float*)d_in[6];
    const float* qnw  = (const float*)d_in[7];
    const float* knw  = (const float*)d_in[8];
    const float* anw  = (const float*)d_in[9];
    const int*   mod  = (const int*)d_in[10];
    float* out = (float*)d_out;

    float *pv, *po;
    bf16 *pxh, *pxl, *pwqh, *pwql, *pwkh, *pwkl, *pwvh, *pwvl, *pwoh, *pwol;
    bf16 *pqh, *pql, *pkh, *pkl, *pvth, *paoh, *paol;
    cudaGetSymbolAddress((void**)&pv,  g_v);
    cudaGetSymbolAddress((void**)&po,  g_o);
    cudaGetSymbolAddress((void**)&pxh, g_xh);  cudaGetSymbolAddress((void**)&pxl, g_xl);
    cudaGetSymbolAddress((void**)&pwqh, g_wqh); cudaGetSymbolAddress((void**)&pwql, g_wql);
    cudaGetSymbolAddress((void**)&pwkh, g_wkh); cudaGetSymbolAddress((void**)&pwkl, g_wkl);
    cudaGetSymbolAddress((void**)&pwvh, g_wvh); cudaGetSymbolAddress((void**)&pwvl, g_wvl);
    cudaGetSymbolAddress((void**)&pwoh, g_woh); cudaGetSymbolAddress((void**)&pwol, g_wol);
    cudaGetSymbolAddress((void**)&pqh, g_qh);   cudaGetSymbolAddress((void**)&pql, g_ql);
    cudaGetSymbolAddress((void**)&pkh, g_kh);   cudaGetSymbolAddress((void**)&pkl, g_kl);
    cudaGetSymbolAddress((void**)&pvth, g_vth);
    cudaGetSymbolAddress((void**)&paoh, g_aoh); cudaGetSymbolAddress((void**)&paol, g_aol);

    cudaFuncSetAttribute(flash_attn, cudaFuncAttributeMaxDynamicSharedMemorySize, FA_BYTES);
    cudaFuncSetAttribute(mm_bf16<0>, cudaFuncAttributeMaxDynamicSharedMemorySize, MM_DSMEM);
    cudaFuncSetAttribute(mm_bf16<1>, cudaFuncAttributeMaxDynamicSharedMemorySize, MM_DSMEM);

    // preprocessing
    sort_tokens<<<1, 1024>>>(mod);
    split_f32<<<(NTOK*DIM_/4 + 255)/256, 256>>>(x, pxh, pxl, NTOK*DIM_/4);
    wtrans_split<<<dim3(64, 64, 2), 256>>>(wq, pwqh, pwql, DIM_, HQ_*HD_);
    wtrans_split<<<dim3(64, 32, 2), 256>>>(wk, pwkh, pwkl, DIM_, HK_*HD_);

    // Q projection GEMM (fused rmsnorm+rope -> fp16 hi/lo)
    mm_bf16<1><<<dim3(16, 33), 128, MM_DSMEM>>>(pxh, pxl, pwqh, pwql,
        nullptr, pqh, pql, qnw, fcos, fsin, DIM_, HQ_*HD_);

    wtrans_split<<<dim3(64, 32, 2), 256>>>(wv, pwvh, pwvl, DIM_, HK_*HD_);
    mm_bf16<1><<<dim3( 8, 33), 128, MM_DSMEM>>>(pxh, pxl, pwkh, pwkl,
        nullptr, pkh, pkl, knw, fcos, fsin, DIM_, HK_*HD_);
    mm_bf16<0><<<dim3( 8, 33), 128, MM_DSMEM>>>(pxh, pxl, pwvh, pwvl,
        pv, nullptr, nullptr, nullptr, nullptr, nullptr, DIM_, HK_*HD_);
    vtrans_half<<<dim3(64, 4, 16), 256>>>(pv, pvth);
    wtrans_split<<<dim3(64, 64, 2), 256>>>(wo, pwoh, pwol, HQ_*HD_, DIM_);

    // attention (fp16 asymmetric, kv=64, mma row-sums)
    flash_attn<<<dim3(32, HQ_, BS_), 128, FA_BYTES>>>(pqh, pql, pkh, pvth, paoh, paol);

    // output projection + final rmsnorm
    mm_bf16<0><<<dim3(16, 33), 128, MM_DSMEM>>>(paoh, paol, pwoh, pwol,
        po, nullptr, nullptr, nullptr, nullptr, nullptr, HQ_*HD_, DIM_);
    final_rms<<<NTOK, 256>>>(po, anw, mod, out);
}

// round 17
// speedup vs baseline: 1.2983x; 1.1029x over previous
#include <cuda_runtime.h>
#include <cuda_bf16.h>
#include <cuda_fp16.h>
#include <math.h>
#include <cstdint>

// ---------------- problem constants ----------------
#define E_   2
#define HQ_  16
#define HK_  8
#define HD_  128
#define DIM_ 2048
#define BS_  2
#define SEQ_ 2048
#define NTOK (BS_*SEQ_)          // 4096
#define EPS_ 1e-6f
#define SCALE_ 0.08838834764831845f   // 1/sqrt(128)
#define SCL2_  0.12754217f            // SCALE_ * log2(e)

typedef __nv_bfloat16 bf16;

// ---------------- scratch (device globals) ----------------
__device__ float g_v [NTOK * (HK_*HD_)];
__device__ float g_o [NTOK * DIM_];
__device__ int   g_perm[NTOK];
__device__ int   g_c0;

// 16-bit buffers (ALL hold fp16 bit patterns now; bf16 type kept for storage)
__device__ bf16 g_xh [NTOK*DIM_],      g_xl [NTOK*DIM_];
__device__ bf16 g_wqh[E_*DIM_*HQ_*HD_];
__device__ bf16 g_wkh[E_*DIM_*HK_*HD_];
__device__ bf16 g_wvh[E_*DIM_*HK_*HD_];
__device__ bf16 g_woh[E_*DIM_*HQ_*HD_];
__device__ bf16 g_qh [NTOK*(HQ_*HD_)],  g_ql [NTOK*(HQ_*HD_)];
__device__ bf16 g_kh [NTOK*(HK_*HD_)];
__device__ bf16 g_vth[NTOK*(HK_*HD_)];                           // [b][kvh][d][seq]
__device__ bf16 g_aoh[NTOK*(HQ_*HD_)],  g_aol[NTOK*(HQ_*HD_)];   // fp16 hi/lo (WO GEMM A)

// =============================== helpers ===============================
__device__ __forceinline__ uint32_t smem_u32(const void* p) {
    uint32_t a;
    asm("{ .reg .u64 t; cvta.to.shared.u64 t, %1; cvt.u32.u64 %0, t; }" : "=r"(a) : "l"(p));
    return a;
}
#define CP_ASYNC16(dst, src) \
    asm volatile("cp.async.cg.shared.global [%0], [%1], 16;" :: "r"(dst), "l"(src) : "memory")
#define CP_COMMIT() asm volatile("cp.async.commit_group;" ::: "memory")
template<int N> __device__ __forceinline__ void cp_wait() {
    asm volatile("cp.async.wait_group %0;" :: "n"(N) : "memory");
}
#define LDSM4(r0,r1,r2,r3, addr) \
    asm volatile("ldmatrix.sync.aligned.m8n8.x4.shared.b16 {%0,%1,%2,%3}, [%4];" \
        : "=r"(r0), "=r"(r1), "=r"(r2), "=r"(r3) : "r"(addr))

__device__ __forceinline__ void hsplit(float x, uint16_t& h, uint16_t& l) {
    __half hh = __float2half_rn(x);
    h = __half_as_ushort(hh);
    l = __half_as_ushort(__float2half_rn(x - __half2float(hh)));
}
__device__ __forceinline__ uint32_t packb(uint16_t lo_elem, uint16_t hi_elem) {
    return (uint32_t)lo_elem | ((uint32_t)hi_elem << 16);
}
__device__ __forceinline__ void mma16816h(float* c, const uint32_t* a, const uint32_t* b) {
    asm volatile("mma.sync.aligned.m16n8k16.row.col.f32.f16.f16.f32 "
        "{%0,%1,%2,%3}, {%4,%5,%6,%7}, {%8,%9}, {%0,%1,%2,%3};"
        : "+f"(c[0]), "+f"(c[1]), "+f"(c[2]), "+f"(c[3])
        : "r"(a[0]), "r"(a[1]), "r"(a[2]), "r"(a[3]), "r"(b[0]), "r"(b[1]));
}
__device__ __forceinline__ uint32_t ex2h2(float a, float b) {
    __half2 h = __floats2half2_rn(a, b);
    uint32_t r;
    asm("ex2.approx.f16x2 %0, %1;" : "=r"(r) : "r"(*(uint32_t*)&h));
    return r;
}
__device__ __forceinline__ uint32_t sw256(int r, int off) {
    return (uint32_t)(r*256 + (off ^ ((r & 7) << 4)));
}
__device__ __forceinline__ uint32_t sw128(int r, int off) {
    return (uint32_t)(r*128 + (off ^ ((r & 7) << 4)));
}

// ============================================================================
// sort tokens by modality (stable counting sort), deterministic
// ============================================================================
__global__ __launch_bounds__(1024) void sort_tokens(const int* __restrict__ mod)
{
    __shared__ int s[1024];
    const int tid = threadIdx.x;
    int m[4]; int cnt = 0;
#pragma unroll
    for (int u = 0; u < 4; u++) { m[u] = mod[tid*4 + u]; cnt += (m[u] == 0); }
    s[tid] = cnt;
    __syncthreads();
    for (int off = 1; off < 1024; off <<= 1) {
        int v = (tid >= off) ? s[tid - off] : 0;
        __syncthreads();
        s[tid] += v;
        __syncthreads();
    }
    const int c0 = s[1023];
    if (tid == 0) g_c0 = c0;
    int r0 = s[tid] - cnt;
#pragma unroll
    for (int u = 0; u < 4; u++) {
        int g = tid*4 + u;
        if (m[u] == 0) { g_perm[r0] = g; r0++; }
        else           { g_perm[c0 + g - r0] = g; }
    }
}

// ============================================================================
// elementwise fp32 -> fp16 hi/lo split (for x)
// ============================================================================
__global__ __launch_bounds__(256) void split_f32(
    const float* __restrict__ in, bf16* __restrict__ hi, bf16* __restrict__ lo, int n4)
{
    int i = blockIdx.x * 256 + threadIdx.x;
    if (i >= n4) return;
    float4 v = ((const float4*)in)[i];
    uint16_t hx,lx,hy,ly,hz,lz,hw,lw;
    hsplit(v.x,hx,lx); hsplit(v.y,hy,ly); hsplit(v.z,hz,lz); hsplit(v.w,hw,lw);
    ((uint2*)hi)[i] = make_uint2(packb(hx,hy), packb(hz,hw));
    ((uint2*)lo)[i] = make_uint2(packb(lx,ly), packb(lz,lw));
}

// ============================================================================
// weight transpose: W [e][K][NC] fp32 -> T [e][NC][K] single fp16
// ============================================================================
__global__ __launch_bounds__(256) void wtrans_half(
    const float* __restrict__ W, bf16* __restrict__ Th, int K, int NC)
{
    __shared__ float t[32][33];
    const int e  = blockIdx.z;
    const int k0 = blockIdx.x * 32, n0 = blockIdx.y * 32;
    const int tx = threadIdx.x & 31, ty = threadIdx.x >> 5;
    const float* Wp = W + (size_t)e * K * NC;
    for (int r = ty; r < 32; r += 8)
        t[r][tx] = Wp[(size_t)(k0 + r) * NC + n0 + tx];
    __syncthreads();
    bf16* th = Th + (size_t)e * NC * K;
    for (int r = ty; r < 32; r += 8) {
        uint16_t h = __half_as_ushort(__float2half_rn(t[tx][r]));
        size_t o = (size_t)(n0 + r) * K + k0 + tx;
        ((uint16_t*)th)[o] = h;
    }
}

// ============================================================================
// V transpose-split: fp32 -> fp16 (single), [b][kvh][d][seq]
// ============================================================================
__global__ __launch_bounds__(256) void vtrans_half(
    const float* __restrict__ V, bf16* __restrict__ Th)
{
    __shared__ float t[32][33];
    const int s0 = blockIdx.x * 32, d0 = blockIdx.y * 32;
    const int z  = blockIdx.z;                 // b*8 + kvh
    const int b  = z >> 3, kvh = z & 7;
    const int tx = threadIdx.x & 31, ty = threadIdx.x >> 5;
    for (int r = ty; r < 32; r += 8)
        t[r][tx] = V[(size_t)(b*SEQ_ + s0 + r) * (HK_*HD_) + kvh*HD_ + d0 + tx];
    __syncthreads();
    for (int r = ty; r < 32; r += 8) {
        uint16_t h = __half_as_ushort(__float2half_rn(t[tx][r]));
        size_t o = (size_t)(z*HD_ + d0 + r) * SEQ_ + s0 + tx;
        ((uint16_t*)Th)[o] = h;
    }
}

// ============================================================================
// fp16 2-chain mma.sync GEMM over expert-sorted rows.
// A = fp16 hi+lo; B = single fp16; chains ah*bh + al*bh (dropped ah*bl ~2^-12).
// MODE 0: plain fp32 store (V, WO). MODE 1: fused RMSNorm+RoPE, fp16 hi/lo out.
// smem/stage: Ah 10240 | Al 10240 | Bh 10240 = 30720; double-buffered 61440.
// ============================================================================
#define MM_STAGE 30720
#define MM_DSMEM (2*MM_STAGE)

template<int MODE>
__global__ __launch_bounds__(128) void mm_fp16(
    const bf16* __restrict__ Ah, const bf16* __restrict__ Al,
    const bf16* __restrict__ Bh,
    float* __restrict__ Cf,
    bf16* __restrict__ Ch, bf16* __restrict__ Cl,
    const float* __restrict__ normw,
    const float* __restrict__ fcos, const float* __restrict__ fsin,
    int K, int NC)
{
    extern __shared__ char sm[];
    __shared__ int sPerm[128];
    __shared__ float sred[4][64];
    const int tid  = threadIdx.x;
    const int lane = tid & 31;
    const int w    = tid >> 5;
    const int wm64 = (w & 1) * 64;
    const int wn64 = (w >> 1) * 64;
    const int bn   = blockIdx.x * 128;
    const int by   = blockIdx.y;

    const int c0 = g_c0;
    const int T0 = (c0 + 127) >> 7;
    const int T1 = (NTOK - c0 + 127) >> 7;
    if (by >= T0 + T1) return;
    const int e       = (by < T0) ? 0 : 1;
    const int rowbase = e ? (c0 + (by - T0) * 128) : (by * 128);
    const int limit   = e ? NTOK : c0;
    const size_t bofs = (size_t)e * NC * K + (size_t)bn * K;

    {
        int gs = rowbase + tid;
        sPerm[tid] = g_perm[gs < NTOK ? gs : (NTOK - 1)];
    }
    __syncthreads();

    const uint32_t sb = smem_u32(sm);

    auto load_chunk = [&](int cc, int p) {
        const int k0 = cc * 32;
        const uint32_t base = sb + p * MM_STAGE;
#pragma unroll
        for (int i = 0; i < 8; i++) {          // A hi+lo: 1024 16B chunks
            int idx = tid + (i << 7);
            int comp = idx >> 9, rem = idx & 511;
            int r = rem >> 2, c = rem & 3;
            const bf16* src = (comp ? Al : Ah) + (size_t)sPerm[r] * K + k0 + c * 8;
            CP_ASYNC16(base + comp*10240 + (uint32_t)(r*80 + c*16), src);
        }
#pragma unroll
        for (int i = 0; i < 4; i++) {          // B hi only: 512 16B chunks
            int idx = tid + (i << 7);
            int r = idx >> 2, c = idx & 3;
            const bf16* src = Bh + bofs + (size_t)r * K + k0 + c * 8;
            CP_ASYNC16(base + 20480 + (uint32_t)(r*80 + c*16), src);
        }
    };

    float acc[4][8][4];
#pragma unroll
    for (int i = 0; i < 4; i++)
#pragma unroll
        for (int j = 0; j < 8; j++)
#pragma unroll
            for (int q = 0; q < 4; q++) acc[i][j][q] = 0.f;

    const int NCH = K / 32;
    load_chunk(0, 0); CP_COMMIT();
    load_chunk(1, 1); CP_COMMIT();

    const int lr = lane >> 2;
    const int lc = lane & 3;
    const int g8  = lane & 7;
    const int grp = lane >> 3;
    const int a_row = wm64 + (grp & 1) * 8 + g8;
    const int a_ofx = (grp >> 1) * 16;
    const int b_row = wn64 + (grp >> 1) * 8 + g8;
    const int b_ofx = (grp & 1) * 16;

    for (int c = 0; c < NCH; c++) {
        cp_wait<1>();
        __syncthreads();
        const uint32_t bb = sb + (c & 1) * MM_STAGE;
#pragma unroll
        for (int ks = 0; ks < 2; ks++) {
            const uint32_t koff = (uint32_t)(ks * 32);
            uint32_t fah[4][4], fal[4][4];
#pragma unroll
            for (int i = 0; i < 4; i++) {
                uint32_t aaddr = bb + (uint32_t)((a_row + i*16) * 80) + koff + a_ofx;
                LDSM4(fah[i][0], fah[i][1], fah[i][2], fah[i][3], aaddr);
                LDSM4(fal[i][0], fal[i][1], fal[i][2], fal[i][3], aaddr + 10240);
            }
            uint32_t fbh4[4][4];
#pragma unroll
            for (int jj = 0; jj < 4; jj++) {
                uint32_t baddr = bb + 20480 + (uint32_t)((b_row + jj*16) * 80) + koff + b_ofx;
                LDSM4(fbh4[jj][0], fbh4[jj][1], fbh4[jj][2], fbh4[jj][3], baddr);
            }
#pragma unroll
            for (int jj = 0; jj < 4; jj++) {
#pragma unroll
                for (int half = 0; half < 2; half++) {
                    const int j = jj*2 + half;
                    uint32_t fbh[2] = { fbh4[jj][half*2], fbh4[jj][half*2+1] };
#pragma unroll
                    for (int i = 0; i < 4; i++) {
                        mma16816h(acc[i][j], fah[i], fbh);
                        mma16816h(acc[i][j], fal[i], fbh);
                    }
                }
            }
        }
        __syncthreads();
        if (c + 2 < NCH) load_chunk(c + 2, c & 1);
        CP_COMMIT();
    }

    if (MODE == 0) {
#pragma unroll
        for (int i = 0; i < 4; i++) {
            int lr0 = wm64 + i * 16 + lr;
            bool v0 = (rowbase + lr0)     < limit;
            bool v1 = (rowbase + lr0 + 8) < limit;
            int t0 = v0 ? sPerm[lr0]     : 0;
            int t1 = v1 ? sPerm[lr0 + 8] : 0;
#pragma unroll
            for (int j = 0; j < 8; j++) {
                int cb = bn + wn64 + j * 8 + (lc << 1);
                if (v0) *(float2*)&Cf[(size_t)t0 * NC + cb] = make_float2(acc[i][j][0], acc[i][j][1]);
                if (v1) *(float2*)&Cf[(size_t)t1 * NC + cb] = make_float2(acc[i][j][2], acc[i][j][3]);
            }
        }
    } else {
        float rs[4][2];
#pragma unroll
        for (int i = 0; i < 4; i++) {
            float s0 = 0.f, s1 = 0.f;
#pragma unroll
            for (int j = 0; j < 8; j++) {
                s0 += acc[i][j][0]*acc[i][j][0] + acc[i][j][1]*acc[i][j][1];
                s1 += acc[i][j][2]*acc[i][j][2] + acc[i][j][3]*acc[i][j][3];
            }
            rs[i][0] = s0; rs[i][1] = s1;
        }
#pragma unroll
        for (int i = 0; i < 4; i++) {
#pragma unroll
            for (int hh = 0; hh < 2; hh++) {
                rs[i][hh] += __shfl_xor_sync(0xffffffffu, rs[i][hh], 1);
                rs[i][hh] += __shfl_xor_sync(0xffffffffu, rs[i][hh], 2);
            }
        }
        if (lc == 0) {
#pragma unroll
            for (int i = 0; i < 4; i++) {
                sred[w][i*16 + lr]     = rs[i][0];
                sred[w][i*16 + 8 + lr] = rs[i][1];
            }
        }
        __syncthreads();
        float rinv[4][2];
#pragma unroll
        for (int i = 0; i < 4; i++) {
            float t0 = rs[i][0] + sred[w ^ 2][i*16 + lr];
            float t1 = rs[i][1] + sred[w ^ 2][i*16 + 8 + lr];
            rinv[i][0] = rsqrtf(t0 * (1.0f/HD_) + EPS_);
            rinv[i][1] = rsqrtf(t1 * (1.0f/HD_) + EPS_);
        }
#pragma unroll
        for (int i = 0; i < 4; i++) {
            const int lr0 = wm64 + i * 16 + lr;
            const bool v0 = (rowbase + lr0)     < limit;
            const bool v1 = (rowbase + lr0 + 8) < limit;
            const int t0 = sPerm[lr0], t1 = sPerm[lr0 + 8];
            const int s0 = t0 & (SEQ_-1), s1 = t1 & (SEQ_-1);
#pragma unroll
            for (int j = 0; j < 8; j++) {
                const int col0 = wn64 + j*8 + (lc << 1);
                const float2 nw = *(const float2*)&normw[e*HD_ + col0];
                const int cp = col0 >> 1;
                if (v0) {
                    float a0 = acc[i][j][0] * rinv[i][0] * nw.x;
                    float a1 = acc[i][j][1] * rinv[i][0] * nw.y;
                    float cc = fcos[s0*(HD_/2) + cp], sn = fsin[s0*(HD_/2) + cp];
                    float e0 = a0*cc - a1*sn, e1 = a0*sn + a1*cc;
                    uint16_t h0,l0,h1,l1;
                    hsplit(e0,h0,l0); hsplit(e1,h1,l1);
                    size_t off = (size_t)t0 * NC + bn + col0;
                    *(uint32_t*)((char*)Ch + 2*off) = packb(h0,h1);
                    if (Cl) *(uint32_t*)((char*)Cl + 2*off) = packb(l0,l1);
                }
                if (v1) {
                    float a0 = acc[i][j][2] * rinv[i][1] * nw.x;
                    float a1 = acc[i][j][3] * rinv[i][1] * nw.y;
                    float cc = fcos[s1*(HD_/2) + cp], sn = fsin[s1*(HD_/2) + cp];
                    float e0 = a0*cc - a1*sn, e1 = a0*sn + a1*cc;
                    uint16_t h0,l0,h1,l1;
                    hsplit(e0,h0,l0); hsplit(e1,h1,l1);
                    size_t off = (size_t)t1 * NC + bn + col0;
                    *(uint32_t*)((char*)Ch + 2*off) = packb(h0,h1);
                    if (Cl) *(uint32_t*)((char*)Cl + 2*off) = packb(l0,l1);
                }
            }
        }
    }
}

// ============================================================================
// Tensor-core causal flash attention — fp16 asymmetric + f16x2 exp2 softmax.
// kv tiles of 64; row-sum l via the PV mma (V|1 register-constant B-frag).
// smem 96KB: Qh 16K | Ql 16K | K[2] 16K ea | V[2] 16K ea  -> 2 CTAs/SM.
// ============================================================================
#define FQ_H 0
#define FQ_L 16384
#define FK(p) (32768 + (p)*16384)
#define FV(p) (65536 + (p)*16384)
#define FA_BYTES 98304

__global__ __launch_bounds__(128) void flash_attn(
    const bf16* __restrict__ Qh, const bf16* __restrict__ Ql,
    const bf16* __restrict__ Kh,
    const bf16* __restrict__ Vth,
    bf16* __restrict__ AOh, bf16* __restrict__ AOl)
{
    extern __shared__ char sm[];
    const int tid  = threadIdx.x;
    const int lane = tid & 31;
    const int w    = tid >> 5;      // 0..3
    const int lr   = lane >> 2;
    const int lc   = lane & 3;
    const int g8   = lane & 7;
    const int grp  = lane >> 3;

    const int qt = 31 - blockIdx.x;      // big tiles first
    const int h  = blockIdx.y;
    const int b  = blockIdx.z;
    const int kvh   = h >> 1;
    const int qbase = qt * 64;
    const int m0    = w * 16;
    const int niter = qt + 1;            // kv tiles of 64

    const uint32_t sb = smem_u32(sm);

    const int q_row  = m0 + (grp & 1) * 8 + g8;
    const int q_ofx  = (grp >> 1) * 16;
    const int kv_row = (grp >> 1) * 8 + g8;
    const int kv_ofx = (grp & 1) * 16;

    const uint32_t onesf = (lr == 0) ? 0x3C003C00u : 0u;
    const uint32_t ones2[2] = { onesf, onesf };

    // ---- Q load (hi+lo), group 0 ----
#pragma unroll
    for (int i = 0; i < 16; i++) {
        int idx = tid + (i << 7);
        int comp = idx >> 10, rem = idx & 1023;
        int r = rem >> 4, c = rem & 15;
        const bf16* src = (comp ? Ql : Qh)
            + (size_t)(b*SEQ_ + qbase + r)*(HQ_*HD_) + h*HD_ + c*8;
        CP_ASYNC16(sb + (comp ? FQ_L : FQ_H) + sw256(r, c*16), src);
    }
    CP_COMMIT();

    auto load_k = [&](int kt, int p) {
#pragma unroll
        for (int i = 0; i < 8; i++) {
            int idx = tid + (i << 7);
            int r = idx >> 4, c = idx & 15;
            const bf16* src = Kh
                + (size_t)(b*SEQ_ + kt*64 + r)*(HK_*HD_) + kvh*HD_ + c*8;
            CP_ASYNC16(sb + FK(p) + sw256(r, c*16), src);
        }
        CP_COMMIT();
    };
    auto load_v = [&](int kt, int p) {
#pragma unroll
        for (int i = 0; i < 8; i++) {
            int idx = tid + (i << 7);
            int r = idx >> 3, c = idx & 7;
            const bf16* src = Vth
                + (size_t)((b*HK_ + kvh)*HD_ + r)*SEQ_ + kt*64 + c*8;
            CP_ASYNC16(sb + FV(p) + sw128(r, c*16), src);
        }
        CP_COMMIT();
    };

    load_k(0, 0);     // group 1
    load_v(0, 0);     // group 2

    cp_wait<2>();
    __syncthreads();
    uint32_t qfh[8][4], qfl[8][4];
#pragma unroll
    for (int s = 0; s < 8; s++) {
        uint32_t qaddr = sb + FQ_H + sw256(q_row, s*32 + q_ofx);
        LDSM4(qfh[s][0], qfh[s][1], qfh[s][2], qfh[s][3], qaddr);
        LDSM4(qfl[s][0], qfl[s][1], qfl[s][2], qfl[s][3], qaddr + 16384);
    }

    float o[17][4];   // o[16] = row sums
#pragma unroll
    for (int j = 0; j < 17; j++)
#pragma unroll
        for (int q = 0; q < 4; q++) o[j][q] = 0.f;
    float mr0 = -1e30f, mr1 = -1e30f;

    const int row0g = qbase + m0 + lr;

    for (int kt = 0; kt < niter; kt++) {
        const int p = kt & 1;
        cp_wait<1>();
        __syncthreads();
        if (kt + 1 < niter) { load_k(kt + 1, p ^ 1); load_v(kt + 1, p ^ 1); }

        const uint32_t kh_b = sb + FK(p);

        float sa[8][4];
#pragma unroll
        for (int j = 0; j < 8; j++)
#pragma unroll
            for (int q = 0; q < 4; q++) sa[j][q] = 0.f;
#pragma unroll
        for (int s = 0; s < 8; s++) {
            const int b0 = s*32;
#pragma unroll
            for (int jj = 0; jj < 4; jj++) {
                uint32_t fkh4[4];
                uint32_t kaddr = sw256(kv_row + jj*16, b0 + kv_ofx);
                LDSM4(fkh4[0], fkh4[1], fkh4[2], fkh4[3], kh_b + kaddr);
#pragma unroll
                for (int half = 0; half < 2; half++) {
                    const int j = jj*2 + half;
                    uint32_t fkh[2] = { fkh4[half*2], fkh4[half*2+1] };
                    mma16816h(sa[j], qfh[s], fkh);
                    mma16816h(sa[j], qfl[s], fkh);
                }
            }
        }

        const bool need_mask = (kt*64 + 63 > qbase + m0);
        float mx0 = -1e30f, mx1 = -1e30f;
#pragma unroll
        for (int j = 0; j < 8; j++) {
            const int cb = kt*64 + j*8 + 2*lc;
#pragma unroll
            for (int q = 0; q < 4; q++) {
                float v = sa[j][q] * SCL2_;
                if (need_mask) {
                    int col = cb + (q & 1);
                    int row = (q < 2) ? row0g : (row0g + 8);
                    if (col > row) v = -1e30f;
                }
                sa[j][q] = v;
            }
            mx0 = fmaxf(mx0, fmaxf(sa[j][0], sa[j][1]));
            mx1 = fmaxf(mx1, fmaxf(sa[j][2], sa[j][3]));
        }
        mx0 = fmaxf(mx0, __shfl_xor_sync(0xffffffffu, mx0, 1));
        mx0 = fmaxf(mx0, __shfl_xor_sync(0xffffffffu, mx0, 2));
        mx1 = fmaxf(mx1, __shfl_xor_sync(0xffffffffu, mx1, 1));
        mx1 = fmaxf(mx1, __shfl_xor_sync(0xffffffffu, mx1, 2));
        const float mn0 = fmaxf(mr0, mx0);
        const float mn1 = fmaxf(mr1, mx1);
        const float c0 = exp2f(mr0 - mn0);
        const float c1 = exp2f(mr1 - mn1);
        mr0 = mn0; mr1 = mn1;

        uint32_t aph[4][4];
#pragma unroll
        for (int t = 0; t < 4; t++) {
            aph[t][0] = ex2h2(sa[2*t][0]   - mn0, sa[2*t][1]   - mn0);
            aph[t][1] = ex2h2(sa[2*t][2]   - mn1, sa[2*t][3]   - mn1);
            aph[t][2] = ex2h2(sa[2*t+1][0] - mn0, sa[2*t+1][1] - mn0);
            aph[t][3] = ex2h2(sa[2*t+1][2] - mn1, sa[2*t+1][3] - mn1);
        }

#pragma unroll
        for (int j = 0; j < 17; j++) {
            o[j][0] *= c0; o[j][1] *= c0;
            o[j][2] *= c1; o[j][3] *= c1;
        }

        if (kt + 1 < niter) cp_wait<2>(); else cp_wait<0>();
        __syncthreads();
        const uint32_t vh_b = sb + FV(p);

#pragma unroll
        for (int t = 0; t < 4; t++) {
            const int b0 = t*32;
#pragma unroll
            for (int jp = 0; jp < 8; jp++) {
                uint32_t fvh4[4];
                uint32_t vaddr = sw128(kv_row + jp*16, b0 + kv_ofx);
                LDSM4(fvh4[0], fvh4[1], fvh4[2], fvh4[3], vh_b + vaddr);
#pragma unroll
                for (int half = 0; half < 2; half++) {
                    const int j = jp*2 + half;
                    uint32_t fvh[2] = { fvh4[half*2], fvh4[half*2+1] };
                    mma16816h(o[j], aph[t], fvh);
                }
            }
            mma16816h(o[16], aph[t], ones2);
        }
    }

    // ---- broadcast row sums, normalize + fp16 split-store AO ----
    const float l0 = __shfl_sync(0xffffffffu, o[16][0], lane & ~3);
    const float l1 = __shfl_sync(0xffffffffu, o[16][2], lane & ~3);
    const float i0 = 1.f / l0;
    const float i1 = 1.f / l1;
    const size_t t0 = (size_t)(b*SEQ_ + row0g);
    const size_t t1 = t0 + 8;
#pragma unroll
    for (int j = 0; j < 16; j++) {
        const int col = h*HD_ + j*8 + 2*lc;
        uint16_t h0,l0u,h1,l1u;
        hsplit(o[j][0]*i0, h0, l0u); hsplit(o[j][1]*i0, h1, l1u);
        size_t off0 = t0*(HQ_*HD_) + col;
        *(uint32_t*)((char*)AOh + 2*off0) = packb(h0, h1);
        *(uint32_t*)((char*)AOl + 2*off0) = packb(l0u, l1u);
        hsplit(o[j][2]*i1, h0, l0u); hsplit(o[j][3]*i1, h1, l1u);
        size_t off1 = t1*(HQ_*HD_) + col;
        *(uint32_t*)((char*)AOh + 2*off1) = packb(h0, h1);
        *(uint32_t*)((char*)AOl + 2*off1) = packb(l0u, l1u);
    }
}

// ============================================================================
// Final per-token RMSNorm over DIM with attn_norm_w[expert]
// ============================================================================
__global__ __launch_bounds__(256) void final_rms(
    const float* __restrict__ in, const float* __restrict__ w,
    const int* __restrict__ mod, float* __restrict__ out)
{
    const int n = blockIdx.x;
    const int tid = threadIdx.x;
    const int e = mod[n];
    const float* row = in + (size_t)n*DIM_;
    float vals[8];
    float ss = 0.f;
#pragma unroll
    for (int u = 0; u < 8; u++) {
        float v = row[tid + u*256];
        vals[u] = v;
        ss += v*v;
    }
#pragma unroll
    for (int o = 16; o > 0; o >>= 1) ss += __shfl_xor_sync(0xffffffffu, ss, o);
    __shared__ float wsum[8];
    if ((tid & 31) == 0) wsum[tid >> 5] = ss;
    __syncthreads();
    float tot = 0.f;
#pragma unroll
    for (int i = 0; i < 8; i++) tot += wsum[i];
    float r = rsqrtf(tot * (1.0f/DIM_) + EPS_);
#pragma unroll
    for (int u = 0; u < 8; u++)
        out[(size_t)n*DIM_ + tid + u*256] = vals[u] * r * w[e*DIM_ + tid + u*256];
}

// ============================================================================
// launch
// ============================================================================
extern "C" void kernel_launch(void* const* d_in, const int* in_sizes, int n_in,
                              void* d_out, int out_size)
{
    const float* x    = (const float*)d_in[0];
    const float* fcos = (const float*)d_in[1];
    const float* fsin = (const float*)d_in[2];
    const float* wq   = (const float*)d_in[3];
    const float* wk   = (const float*)d_in[4];
    const float* wv   = (const float*)d_in[5];
    const float* wo   = (const float*)d_in[6];
    const float* qnw  = (const float*)d_in[7];
    const float* knw  = (const float*)d_in[8];
    const float* anw  = (const float*)d_in[9];
    const int*   mod  = (const int*)d_in[10];
    float* out = (float*)d_out;

    float *pv, *po;
    bf16 *pxh, *pxl, *pwqh, *pwkh, *pwvh, *pwoh;
    bf16 *pqh, *pql, *pkh, *pvth, *paoh, *paol;
    cudaGetSymbolAddress((void**)&pv,  g_v);
    cudaGetSymbolAddress((void**)&po,  g_o);
    cudaGetSymbolAddress((void**)&pxh, g_xh);  cudaGetSymbolAddress((void**)&pxl, g_xl);
    cudaGetSymbolAddress((void**)&pwqh, g_wqh);
    cudaGetSymbolAddress((void**)&pwkh, g_wkh);
    cudaGetSymbolAddress((void**)&pwvh, g_wvh);
    cudaGetSymbolAddress((void**)&pwoh, g_woh);
    cudaGetSymbolAddress((void**)&pqh, g_qh);   cudaGetSymbolAddress((void**)&pql, g_ql);
    cudaGetSymbolAddress((void**)&pkh, g_kh);
    cudaGetSymbolAddress((void**)&pvth, g_vth);
    cudaGetSymbolAddress((void**)&paoh, g_aoh); cudaGetSymbolAddress((void**)&paol, g_aol);

    cudaFuncSetAttribute(flash_attn, cudaFuncAttributeMaxDynamicSharedMemorySize, FA_BYTES);
    cudaFuncSetAttribute(mm_fp16<0>, cudaFuncAttributeMaxDynamicSharedMemorySize, MM_DSMEM);
    cudaFuncSetAttribute(mm_fp16<1>, cudaFuncAttributeMaxDynamicSharedMemorySize, MM_DSMEM);

    // preprocessing
    sort_tokens<<<1, 1024>>>(mod);
    split_f32<<<(NTOK*DIM_/4 + 255)/256, 256>>>(x, pxh, pxl, NTOK*DIM_/4);
    wtrans_half<<<dim3(64, 64, 2), 256>>>(wq, pwqh, DIM_, HQ_*HD_);
    wtrans_half<<<dim3(64, 32, 2), 256>>>(wk, pwkh, DIM_, HK_*HD_);

    // Q projection GEMM (fused rmsnorm+rope -> fp16 hi/lo)
    mm_fp16<1><<<dim3(16, 33), 128, MM_DSMEM>>>(pxh, pxl, pwqh,
        nullptr, pqh, pql, qnw, fcos, fsin, DIM_, HQ_*HD_);

    wtrans_half<<<dim3(64, 32, 2), 256>>>(wv, pwvh, DIM_, HK_*HD_);
    // K projection: hi only needed by attention (pass lo=nullptr)
    mm_fp16<1><<<dim3( 8, 33), 128, MM_DSMEM>>>(pxh, pxl, pwkh,
        nullptr, pkh, nullptr, knw, fcos, fsin, DIM_, HK_*HD_);
    mm_fp16<0><<<dim3( 8, 33), 128, MM_DSMEM>>>(pxh, pxl, pwvh,
        pv, nullptr, nullptr, nullptr, nullptr, nullptr, DIM_, HK_*HD_);
    vtrans_half<<<dim3(64, 4, 16), 256>>>(pv, pvth);
    wtrans_half<<<dim3(64, 64, 2), 256>>>(wo, pwoh, HQ_*HD_, DIM_);

    // attention (fp16 asymmetric, kv=64, mma row-sums)
    flash_attn<<<dim3(32, HQ_, BS_), 128, FA_BYTES>>>(pqh, pql, pkh, pvth, paoh, paol);

    // output projection + final rmsnorm
    mm_fp16<0><<<dim3(16, 33), 128, MM_DSMEM>>>(paoh, paol, pwoh,
        po, nullptr, nullptr, nullptr, nullptr, nullptr, HQ_*HD_, DIM_);
    final_rms<<<NTOK, 256>>>(po, anw, mod, out);
}